// round 5
// baseline (speedup 1.0000x reference)
#include <cuda_runtime.h>
#include <math.h>
#include <float.h>
#include <stdint.h>

#define TT   512
#define BB   8
#define DD   512
#define HH   8
#define DHH  64
#define RR   1023
#define BHN  64
#define MROWS 4096

// ---------------- scratch (tf32-bit payloads where noted) ----------------
__device__ float g_q[BHN * TT * DHH];      // tf32 bits  [b*8+h][t][dh]
__device__ float g_k[BHN * TT * DHH];      // tf32 bits
__device__ float g_v[BHN * TT * DHH];      // tf32 bits
__device__ float g_rpe[RR * DD];           // tf32 bits  [r][h*64+dh]
__device__ float g_uk[BHN * TT];
__device__ float g_vr[RR * HH];
__device__ float g_ao[MROWS * DD];         // fp32 (t,b,d)

__device__ __forceinline__ uint32_t f2tf(float f) {
    uint32_t u;
    asm("cvt.rna.tf32.f32 %0, %1;" : "=r"(u) : "f"(f));
    return u;
}

__device__ __forceinline__ void mma8(float* c, const uint32_t* a, const uint32_t* b) {
    asm volatile(
        "mma.sync.aligned.m16n8k8.row.col.f32.tf32.tf32.f32 "
        "{%0,%1,%2,%3},{%4,%5,%6,%7},{%8,%9},{%0,%1,%2,%3};"
        : "+f"(c[0]), "+f"(c[1]), "+f"(c[2]), "+f"(c[3])
        : "r"(a[0]), "r"(a[1]), "r"(a[2]), "r"(a[3]), "r"(b[0]), "r"(b[1]));
}

// ============================================================================
// QKV GEMM: C(4096,1536) = x @ W.  128x128 tile, BK=32, 256 thr, warp 64x32.
// ============================================================================
__global__ void __launch_bounds__(256, 2)
qkv_mma_kernel(const float* __restrict__ x, const float* __restrict__ W) {
    __shared__ uint32_t As[128 * 36];
    __shared__ uint32_t Bs[32 * 132];
    const int m0 = blockIdx.y * 128, n0 = blockIdx.x * 128;
    const int tid = threadIdx.x, lane = tid & 31, wid = tid >> 5;
    const int gi = lane >> 2, ti = lane & 3;
    const int wm = wid >> 2, wn = wid & 3;

    float c_[4][4][4] = {};

    for (int k0 = 0; k0 < 512; k0 += 32) {
#pragma unroll
        for (int rep = 0; rep < 4; ++rep) {
            int s = rep * 256 + tid;
            int row = s >> 3, kseg = s & 7;
            float4 v = *(const float4*)&x[(size_t)(m0 + row) * 512 + k0 + kseg * 4];
            uint32_t* d = &As[row * 36 + kseg * 4];
            d[0] = f2tf(v.x); d[1] = f2tf(v.y); d[2] = f2tf(v.z); d[3] = f2tf(v.w);
        }
#pragma unroll
        for (int rep = 0; rep < 4; ++rep) {
            int s = rep * 256 + tid;
            int row = s >> 5, nseg = s & 31;
            float4 v = *(const float4*)&W[(size_t)(k0 + row) * 1536 + n0 + nseg * 4];
            uint32_t* d = &Bs[row * 132 + nseg * 4];
            d[0] = f2tf(v.x); d[1] = f2tf(v.y); d[2] = f2tf(v.z); d[3] = f2tf(v.w);
        }
        __syncthreads();
#pragma unroll
        for (int kb = 0; kb < 32; kb += 8) {
            uint32_t a[4][4], bb[4][2];
#pragma unroll
            for (int mt = 0; mt < 4; ++mt) {
                int r = wm * 64 + mt * 16 + gi;
                a[mt][0] = As[r * 36 + kb + ti];
                a[mt][1] = As[(r + 8) * 36 + kb + ti];
                a[mt][2] = As[r * 36 + kb + ti + 4];
                a[mt][3] = As[(r + 8) * 36 + kb + ti + 4];
            }
#pragma unroll
            for (int nt = 0; nt < 4; ++nt) {
                int ncol = wn * 32 + nt * 8 + gi;
                bb[nt][0] = Bs[(kb + ti) * 132 + ncol];
                bb[nt][1] = Bs[(kb + ti + 4) * 132 + ncol];
            }
#pragma unroll
            for (int mt = 0; mt < 4; ++mt)
#pragma unroll
                for (int nt = 0; nt < 4; ++nt)
                    mma8(c_[mt][nt], a[mt], bb[nt]);
        }
        __syncthreads();
    }

#pragma unroll
    for (int mt = 0; mt < 4; ++mt) {
        int m = m0 + wm * 64 + mt * 16 + gi;
#pragma unroll
        for (int nt = 0; nt < 4; ++nt) {
            int n = n0 + wn * 32 + nt * 8 + 2 * ti;
            int part = n >> 9, hh = (n >> 6) & 7, dh = n & 63;
            float* dst = (part == 0) ? g_q : ((part == 1) ? g_k : g_v);
            int tr = m >> 3, bi = m & 7;
            size_t off = ((size_t)((bi * 8 + hh) * 512 + tr)) * 64 + dh;
            *(float2*)&dst[off] = make_float2(__uint_as_float(f2tf(c_[mt][nt][0])),
                                              __uint_as_float(f2tf(c_[mt][nt][1])));
            int m2 = m + 8;
            int tr2 = m2 >> 3, bi2 = m2 & 7;
            size_t off2 = ((size_t)((bi2 * 8 + hh) * 512 + tr2)) * 64 + dh;
            *(float2*)&dst[off2] = make_float2(__uint_as_float(f2tf(c_[mt][nt][2])),
                                               __uint_as_float(f2tf(c_[mt][nt][3])));
        }
    }
}

// ============================================================================
// rpe GEMM: g_rpe(1023,512) = sinusoid @ W_pos. 128x64, BK=32 (tf32 epilogue).
// ============================================================================
__global__ void __launch_bounds__(256)
rpe_mma_kernel(const float* __restrict__ Wpos) {
    __shared__ uint32_t As[128 * 36];
    __shared__ uint32_t Bs[32 * 68];
    __shared__ float freqs[512];
    const int m0 = blockIdx.y * 128, n0 = blockIdx.x * 64;
    const int tid = threadIdx.x, lane = tid & 31, wid = tid >> 5;
    const int gi = lane >> 2, ti = lane & 3;
    const int wm = wid >> 1, wn = wid & 1;

    for (int s = tid; s < 512; s += 256) {
        int cc = s & 255;
        freqs[s] = __expf(-9.210340371976184f * (float)cc * (1.0f / 256.0f));
    }
    __syncthreads();

    float c_[2][4][4] = {};

    for (int k0 = 0; k0 < 512; k0 += 32) {
#pragma unroll
        for (int rep = 0; rep < 16; ++rep) {
            int s = rep * 256 + tid;
            int row = s >> 5, kk = s & 31;
            int cgl = k0 + kk;
            float rel = (float)(m0 + row - 511);
            float ang = rel * freqs[cgl];
            float v = (cgl < 256) ? sinf(ang) : cosf(ang);
            As[row * 36 + kk] = f2tf(v);
        }
#pragma unroll
        for (int rep = 0; rep < 2; ++rep) {
            int s = rep * 256 + tid;
            int row = s >> 4, nseg = s & 15;
            float4 v = *(const float4*)&Wpos[(size_t)(k0 + row) * 512 + n0 + nseg * 4];
            uint32_t* d = &Bs[row * 68 + nseg * 4];
            d[0] = f2tf(v.x); d[1] = f2tf(v.y); d[2] = f2tf(v.z); d[3] = f2tf(v.w);
        }
        __syncthreads();
#pragma unroll
        for (int kb = 0; kb < 32; kb += 8) {
            uint32_t a[2][4];
#pragma unroll
            for (int mt = 0; mt < 2; ++mt) {
                int r = wm * 32 + mt * 16 + gi;
                a[mt][0] = As[r * 36 + kb + ti];
                a[mt][1] = As[(r + 8) * 36 + kb + ti];
                a[mt][2] = As[r * 36 + kb + ti + 4];
                a[mt][3] = As[(r + 8) * 36 + kb + ti + 4];
            }
#pragma unroll
            for (int nt = 0; nt < 4; ++nt) {
                uint32_t bf[2];
                int ncol = wn * 32 + nt * 8 + gi;
                bf[0] = Bs[(kb + ti) * 68 + ncol];
                bf[1] = Bs[(kb + ti + 4) * 68 + ncol];
                mma8(c_[0][nt], a[0], bf);
                mma8(c_[1][nt], a[1], bf);
            }
        }
        __syncthreads();
    }

#pragma unroll
    for (int mt = 0; mt < 2; ++mt) {
        int m = m0 + wm * 32 + mt * 16 + gi;
#pragma unroll
        for (int nt = 0; nt < 4; ++nt) {
            int n = n0 + wn * 32 + nt * 8 + 2 * ti;
            if (m < RR)
                *(float2*)&g_rpe[(size_t)m * 512 + n] =
                    make_float2(__uint_as_float(f2tf(c_[mt][nt][0])),
                                __uint_as_float(f2tf(c_[mt][nt][1])));
            if (m + 8 < RR)
                *(float2*)&g_rpe[(size_t)(m + 8) * 512 + n] =
                    make_float2(__uint_as_float(f2tf(c_[mt][nt][2])),
                                __uint_as_float(f2tf(c_[mt][nt][3])));
        }
    }
}

// ============================================================================
// bias kernels: 4 threads per 64-dot, shfl reduce (MLP & occupancy fix)
// ============================================================================
__global__ void uk_kernel(const float* __restrict__ pos_u) {
    int gid = blockIdx.x * 256 + threadIdx.x;     // 131072 threads
    int id = gid >> 2, part = gid & 3;            // id < 32768
    int h = (id >> 9) & 7;
    const float4* kp = (const float4*)(g_k + (size_t)id * 64) + part * 4;
    const float4* up = (const float4*)(pos_u + h * 64) + part * 4;
    float acc = 0.f;
#pragma unroll
    for (int s = 0; s < 4; ++s) {
        float4 kk = kp[s], uu = up[s];
        acc += kk.x * uu.x + kk.y * uu.y + kk.z * uu.z + kk.w * uu.w;
    }
    acc += __shfl_xor_sync(0xffffffffu, acc, 1);
    acc += __shfl_xor_sync(0xffffffffu, acc, 2);
    if (part == 0) g_uk[id] = acc;
}

__global__ void vr_kernel(const float* __restrict__ pos_v) {
    int gid = blockIdx.x * 256 + threadIdx.x;
    int id = gid >> 2, part = gid & 3;
    if (id >= RR * HH) return;
    int r = id >> 3, h = id & 7;
    const float4* rp = (const float4*)(g_rpe + r * 512 + h * 64) + part * 4;
    const float4* vp = (const float4*)(pos_v + h * 64) + part * 4;
    float acc = 0.f;
#pragma unroll
    for (int s = 0; s < 4; ++s) {
        float4 rr = rp[s], vv = vp[s];
        acc += rr.x * vv.x + rr.y * vv.y + rr.z * vv.z + rr.w * vv.w;
    }
    acc += __shfl_xor_sync(0xffffffffu, acc, 1);
    acc += __shfl_xor_sync(0xffffffffu, acc, 2);
    if (part == 0) g_vr[id] = acc;
}

// ============================================================================
// Fused attention. 512 threads, TI=64 i-rows per block, one (b,h).
// A/B fragments loaded DIRECTLY from global (L2) — no staging buffer, no
// staging barriers. Q kept in smem B-frag layout; e_s holds energies.
// ============================================================================
#define LDE 68

__global__ void __launch_bounds__(512, 1)
attn_mma_kernel(const float* __restrict__ tau_ptr) {
    extern __shared__ float sm[];
    float*    e_s = sm;                            // 512*68
    uint32_t* Qf  = (uint32_t*)(e_s + 512 * LDE);  // 4096
    float* uks  = (float*)(Qf + 4096);             // 512
    float* vrs  = uks + 512;                       // 576
    float* red  = vrs + 576;                       // 512
    float* rowm = red + 512;                       // 64
    float* rowl = rowm + 64;                       // 64

    const int bh = blockIdx.y, h = bh & 7, b = bh >> 3;
    const int i0 = blockIdx.x * 64;
    const int tid = threadIdx.x, lane = tid & 31, wid = tid >> 5;
    const int gi = lane >> 2, ti = lane & 3;
    const int wm = wid >> 1, wn = wid & 1;          // AC/BD warp grid 8x2

    // ---- init: Q -> B-frag layout; uk/vr slices ----
    {
        const uint32_t* qg = (const uint32_t*)g_q + ((size_t)bh * TT + i0) * 64;
        for (int s = tid; s < 4096; s += 512) {
            int bidx = s & 1, l = (s >> 1) & 31, ks = (s >> 6) & 7, nt = s >> 9;
            int gg = l >> 2, tt = l & 3;
            int ii = nt * 8 + gg;
            int dh = ks * 8 + bidx * 4 + tt;
            Qf[s] = qg[ii * 64 + dh];
        }
        uks[tid] = g_uk[bh * 512 + tid];
        for (int s = tid; s < 576; s += 512) {
            int u = i0 + s;
            vrs[s] = (u < RR) ? g_vr[u * 8 + h] : 0.f;
        }
    }
    __syncthreads();

    // ---- Phase AC (writes '='): direct-LDG K fragments, no inner syncs ----
    const uint32_t* kbase = (const uint32_t*)g_k + (size_t)bh * TT * 64;
#pragma unroll
    for (int jc = 0; jc < 2; ++jc) {
        const uint32_t* kc = kbase + (size_t)(jc * 256) * 64;
        float c_[2][4][4] = {};
#pragma unroll
        for (int ks = 0; ks < 8; ++ks) {
            uint32_t a[2][4];
#pragma unroll
            for (int m = 0; m < 2; ++m) {
                int r0 = wm * 32 + m * 16 + gi;
                const uint32_t* p0 = kc + (size_t)r0 * 64 + ks * 8 + ti;
                a[m][0] = p0[0];
                a[m][2] = p0[4];
                a[m][1] = p0[512];     // row +8
                a[m][3] = p0[516];
            }
#pragma unroll
            for (int n = 0; n < 4; ++n) {
                int nt = wn * 4 + n;
                uint2 bv = *(const uint2*)&Qf[((nt * 8 + ks) * 32 + lane) * 2];
                uint32_t bb[2] = {bv.x, bv.y};
                mma8(c_[0][n], a[0], bb);
                mma8(c_[1][n], a[1], bb);
            }
        }
#pragma unroll
        for (int m = 0; m < 2; ++m) {
            int j = jc * 256 + wm * 32 + m * 16 + gi;
#pragma unroll
            for (int n = 0; n < 4; ++n) {
                int ii = wn * 32 + n * 8 + 2 * ti;
                *(float2*)&e_s[j * LDE + ii]       = make_float2(c_[m][n][0], c_[m][n][1]);
                *(float2*)&e_s[(j + 8) * LDE + ii] = make_float2(c_[m][n][2], c_[m][n][3]);
            }
        }
    }
    __syncthreads();

    // ---- Phase BD (+=): direct-LDG rpe fragments; race-free scatter ----
    const uint32_t* rc = (const uint32_t*)g_rpe + h * 64;
#pragma unroll
    for (int ch = 0; ch < 3; ++ch) {
        if (ch == 2 && wm >= 2) continue;          // only 64 useful rows in chunk 2
        int ubase = i0 + ch * 256;
        float c_[2][4][4] = {};
#pragma unroll
        for (int ks = 0; ks < 8; ++ks) {
            uint32_t a[2][4];
#pragma unroll
            for (int m = 0; m < 2; ++m) {
                int u0 = ubase + wm * 32 + m * 16 + gi;
                int u1 = u0 + 8;
                const uint32_t* p0 = rc + (size_t)u0 * 512 + ks * 8 + ti;
                const uint32_t* p1 = rc + (size_t)u1 * 512 + ks * 8 + ti;
                bool v0 = (u0 < RR), v1 = (u1 < RR);
                a[m][0] = v0 ? p0[0] : 0u;
                a[m][2] = v0 ? p0[4] : 0u;
                a[m][1] = v1 ? p1[0] : 0u;
                a[m][3] = v1 ? p1[4] : 0u;
            }
#pragma unroll
            for (int n = 0; n < 4; ++n) {
                int nt = wn * 4 + n;
                uint2 bv = *(const uint2*)&Qf[((nt * 8 + ks) * 32 + lane) * 2];
                uint32_t bb[2] = {bv.x, bv.y};
                mma8(c_[0][n], a[0], bb);
                mma8(c_[1][n], a[1], bb);
            }
        }
#pragma unroll
        for (int m = 0; m < 2; ++m) {
            int uloc = ch * 256 + wm * 32 + m * 16 + gi;   // u - i0
#pragma unroll
            for (int n = 0; n < 4; ++n) {
                int ii = wn * 32 + n * 8 + 2 * ti;
                int j0 = ii - uloc + 511;
                int j1 = j0 + 1;
                int j2 = j0 - 8;
                int j3 = j1 - 8;
                if ((unsigned)j0 < 512u) e_s[j0 * LDE + ii]     += c_[m][n][0];
                if ((unsigned)j1 < 512u) e_s[j1 * LDE + ii + 1] += c_[m][n][1];
                if ((unsigned)j2 < 512u) e_s[j2 * LDE + ii]     += c_[m][n][2];
                if ((unsigned)j3 < 512u) e_s[j3 * LDE + ii + 1] += c_[m][n][3];
            }
        }
    }
    __syncthreads();

    // ---- finalize + softmax over j, per column i ----
    {
        const float scale = 0.125f;
        const float tauf = expf(tau_ptr[0]);
        int col = tid & 63, seg = tid >> 6;
        int ig = i0 + col;
        float mloc = -FLT_MAX;
        for (int jj = 0; jj < 64; ++jj) {
            int j = seg * 64 + jj;
            float val = e_s[j * LDE + col];
            val = (val + uks[j] + vrs[col - j + 511]) * scale;
            if (j == ig) val = -FLT_MAX;
            val *= tauf;
            e_s[j * LDE + col] = val;
            mloc = fmaxf(mloc, val);
        }
        red[seg * 64 + col] = mloc;
        __syncthreads();
        if (tid < 64) {
            float m = red[tid];
#pragma unroll
            for (int s = 1; s < 8; ++s) m = fmaxf(m, red[s * 64 + tid]);
            rowm[tid] = m;
        }
        __syncthreads();
        float m = rowm[col];
        float sloc = 0.f;
        for (int jj = 0; jj < 64; ++jj) {
            int j = seg * 64 + jj;
            float p = __expf(e_s[j * LDE + col] - m);
            e_s[j * LDE + col] = p;
            sloc += p;
        }
        red[seg * 64 + col] = sloc;
        __syncthreads();
        if (tid < 64) {
            float s = 0.f;
#pragma unroll
            for (int ss = 0; ss < 8; ++ss) s += red[ss * 64 + tid];
            rowl[tid] = s;
        }
        __syncthreads();
    }

    // ---- Phase PV: A = P (e_s bits), B = V direct-LDG ----
    float o_[2][4] = {};
    const int pwm = wid >> 2;       // i-tile 0..3
    const int pwn = wid & 3;        // dh group 0..3
    const uint32_t* es_u = (const uint32_t*)e_s;
    const uint32_t* vbase = (const uint32_t*)g_v + (size_t)bh * TT * 64;
#pragma unroll
    for (int jc = 0; jc < 2; ++jc) {
        const uint32_t* vc = vbase + (size_t)(jc * 256) * 64;
#pragma unroll 4
        for (int ks = 0; ks < 32; ++ks) {
            int jb = jc * 256 + ks * 8;
            int ibase = pwm * 16 + gi;
            uint32_t a[4];
            a[0] = es_u[(jb + ti) * LDE + ibase];
            a[1] = es_u[(jb + ti) * LDE + ibase + 8];
            a[2] = es_u[(jb + ti + 4) * LDE + ibase];
            a[3] = es_u[(jb + ti + 4) * LDE + ibase + 8];
#pragma unroll
            for (int n = 0; n < 2; ++n) {
                int nt = pwn * 2 + n;
                const uint32_t* pv = vc + (size_t)(ks * 8 + ti) * 64 + nt * 8 + gi;
                uint32_t bb[2] = {pv[0], pv[256]};   // rows ti and ti+4
                mma8(o_[n], a, bb);
            }
        }
    }

    {
        int i1 = pwm * 16 + gi, i2 = i1 + 8;
        float inv1 = 1.f / rowl[i1];
        float inv2 = 1.f / rowl[i2];
#pragma unroll
        for (int n = 0; n < 2; ++n) {
            int dh = pwn * 16 + n * 8 + 2 * ti;
            float* o1 = g_ao + (size_t)(i0 + i1) * (BB * DD) + b * DD + h * 64 + dh;
            float* o2 = g_ao + (size_t)(i0 + i2) * (BB * DD) + b * DD + h * 64 + dh;
            *(float2*)o1 = make_float2(o_[n][0] * inv1, o_[n][1] * inv1);
            *(float2*)o2 = make_float2(o_[n][2] * inv2, o_[n][3] * inv2);
        }
    }
}

// ============================================================================
// Output projection: out(4096,512) = g_ao @ W_out + b_out (tf32 mma)
// ============================================================================
__global__ void __launch_bounds__(256)
out_mma_kernel(const float* __restrict__ W,
               const float* __restrict__ bias,
               float* __restrict__ out) {
    __shared__ uint32_t As[128 * 36];
    __shared__ uint32_t Bs[32 * 68];
    const int m0 = blockIdx.y * 128, n0 = blockIdx.x * 64;
    const int tid = threadIdx.x, lane = tid & 31, wid = tid >> 5;
    const int gi = lane >> 2, ti = lane & 3;
    const int wm = wid >> 1, wn = wid & 1;

    float c_[2][4][4] = {};

    for (int k0 = 0; k0 < 512; k0 += 32) {
#pragma unroll
        for (int rep = 0; rep < 4; ++rep) {
            int s = rep * 256 + tid;
            int row = s >> 3, kseg = s & 7;
            float4 v = *(const float4*)&g_ao[(size_t)(m0 + row) * 512 + k0 + kseg * 4];
            uint32_t* d = &As[row * 36 + kseg * 4];
            d[0] = f2tf(v.x); d[1] = f2tf(v.y); d[2] = f2tf(v.z); d[3] = f2tf(v.w);
        }
#pragma unroll
        for (int rep = 0; rep < 2; ++rep) {
            int s = rep * 256 + tid;
            int row = s >> 4, nseg = s & 15;
            float4 v = *(const float4*)&W[(size_t)(k0 + row) * 512 + n0 + nseg * 4];
            uint32_t* d = &Bs[row * 68 + nseg * 4];
            d[0] = f2tf(v.x); d[1] = f2tf(v.y); d[2] = f2tf(v.z); d[3] = f2tf(v.w);
        }
        __syncthreads();
#pragma unroll
        for (int kb = 0; kb < 32; kb += 8) {
            uint32_t a[2][4];
#pragma unroll
            for (int mt = 0; mt < 2; ++mt) {
                int r = wm * 32 + mt * 16 + gi;
                a[mt][0] = As[r * 36 + kb + ti];
                a[mt][1] = As[(r + 8) * 36 + kb + ti];
                a[mt][2] = As[r * 36 + kb + ti + 4];
                a[mt][3] = As[(r + 8) * 36 + kb + ti + 4];
            }
#pragma unroll
            for (int nt = 0; nt < 4; ++nt) {
                uint32_t bf[2];
                int ncol = wn * 32 + nt * 8 + gi;
                bf[0] = Bs[(kb + ti) * 68 + ncol];
                bf[1] = Bs[(kb + ti + 4) * 68 + ncol];
                mma8(c_[0][nt], a[0], bf);
                mma8(c_[1][nt], a[1], bf);
            }
        }
        __syncthreads();
    }

#pragma unroll
    for (int mt = 0; mt < 2; ++mt) {
        int m = m0 + wm * 32 + mt * 16 + gi;
#pragma unroll
        for (int nt = 0; nt < 4; ++nt) {
            int n = n0 + wn * 32 + nt * 8 + 2 * ti;
            float b0 = bias[n], b1 = bias[n + 1];
            *(float2*)&out[(size_t)m * 512 + n] =
                make_float2(c_[mt][nt][0] + b0, c_[mt][nt][1] + b1);
            *(float2*)&out[(size_t)(m + 8) * 512 + n] =
                make_float2(c_[mt][nt][2] + b0, c_[mt][nt][3] + b1);
        }
    }
}

// ============================================================================
extern "C" void kernel_launch(void* const* d_in, const int* in_sizes, int n_in,
                              void* d_out, int out_size) {
    const float* x     = (const float*)d_in[0];
    const float* Wqkv  = (const float*)d_in[1];
    const float* Wpos  = (const float*)d_in[2];
    const float* pos_u = (const float*)d_in[3];
    const float* pos_v = (const float*)d_in[4];
    const float* Wout  = (const float*)d_in[5];
    const float* bout  = (const float*)d_in[6];
    const float* ltau  = (const float*)d_in[7];
    float* out = (float*)d_out;

    qkv_mma_kernel<<<dim3(12, 32), 256>>>(x, Wqkv);
    rpe_mma_kernel<<<dim3(8, 8), 256>>>(Wpos);
    uk_kernel<<<512, 256>>>(pos_u);
    vr_kernel<<<128, 256>>>(pos_v);

    const size_t smem = (size_t)(512 * LDE + 4096 + 512 + 576 + 512 + 64 + 64) * sizeof(float);
    cudaFuncSetAttribute(attn_mma_kernel, cudaFuncAttributeMaxDynamicSharedMemorySize, (int)smem);
    attn_mma_kernel<<<dim3(8, 64), 512, smem>>>(ltau);

    out_mma_kernel<<<dim3(8, 32), 256>>>(Wout, bout, out);
}

// round 6
// speedup vs baseline: 1.0752x; 1.0752x over previous
#include <cuda_runtime.h>
#include <math.h>
#include <float.h>
#include <stdint.h>

#define TT   512
#define BB   8
#define DD   512
#define HH   8
#define DHH  64
#define RR   1023
#define BHN  64
#define MROWS 4096

// ---------------- scratch (tf32-bit payloads where noted) ----------------
__device__ float g_q[BHN * TT * DHH];      // tf32 bits  [b*8+h][t][dh]
__device__ float g_k[BHN * TT * DHH];      // tf32 bits
__device__ float g_v[BHN * TT * DHH];      // tf32 bits
__device__ float g_rpe[RR * DD];           // tf32 bits  [r][h*64+dh]
__device__ float g_uk[BHN * TT];
__device__ float g_vr[RR * HH];
__device__ float g_ao[MROWS * DD];         // fp32 (t,b,d)

__device__ __forceinline__ uint32_t f2tf(float f) {
    uint32_t u;
    asm("cvt.rna.tf32.f32 %0, %1;" : "=r"(u) : "f"(f));
    return u;
}

__device__ __forceinline__ void mma8(float* c, const uint32_t* a, const uint32_t* b) {
    asm volatile(
        "mma.sync.aligned.m16n8k8.row.col.f32.tf32.tf32.f32 "
        "{%0,%1,%2,%3},{%4,%5,%6,%7},{%8,%9},{%0,%1,%2,%3};"
        : "+f"(c[0]), "+f"(c[1]), "+f"(c[2]), "+f"(c[3])
        : "r"(a[0]), "r"(a[1]), "r"(a[2]), "r"(a[3]), "r"(b[0]), "r"(b[1]));
}

// ============================================================================
// QKV GEMM: C(4096,1536) = x @ W.  128x128 tile, BK=32, 256 thr, warp 64x32.
// ============================================================================
__global__ void __launch_bounds__(256, 2)
qkv_mma_kernel(const float* __restrict__ x, const float* __restrict__ W) {
    __shared__ uint32_t As[128 * 36];
    __shared__ uint32_t Bs[32 * 132];
    const int m0 = blockIdx.y * 128, n0 = blockIdx.x * 128;
    const int tid = threadIdx.x, lane = tid & 31, wid = tid >> 5;
    const int gi = lane >> 2, ti = lane & 3;
    const int wm = wid >> 2, wn = wid & 3;

    float c_[4][4][4] = {};

    for (int k0 = 0; k0 < 512; k0 += 32) {
#pragma unroll
        for (int rep = 0; rep < 4; ++rep) {
            int s = rep * 256 + tid;
            int row = s >> 3, kseg = s & 7;
            float4 v = *(const float4*)&x[(size_t)(m0 + row) * 512 + k0 + kseg * 4];
            uint32_t* d = &As[row * 36 + kseg * 4];
            d[0] = f2tf(v.x); d[1] = f2tf(v.y); d[2] = f2tf(v.z); d[3] = f2tf(v.w);
        }
#pragma unroll
        for (int rep = 0; rep < 4; ++rep) {
            int s = rep * 256 + tid;
            int row = s >> 5, nseg = s & 31;
            float4 v = *(const float4*)&W[(size_t)(k0 + row) * 1536 + n0 + nseg * 4];
            uint32_t* d = &Bs[row * 132 + nseg * 4];
            d[0] = f2tf(v.x); d[1] = f2tf(v.y); d[2] = f2tf(v.z); d[3] = f2tf(v.w);
        }
        __syncthreads();
#pragma unroll
        for (int kb = 0; kb < 32; kb += 8) {
            uint32_t a[4][4], bb[4][2];
#pragma unroll
            for (int mt = 0; mt < 4; ++mt) {
                int r = wm * 64 + mt * 16 + gi;
                a[mt][0] = As[r * 36 + kb + ti];
                a[mt][1] = As[(r + 8) * 36 + kb + ti];
                a[mt][2] = As[r * 36 + kb + ti + 4];
                a[mt][3] = As[(r + 8) * 36 + kb + ti + 4];
            }
#pragma unroll
            for (int nt = 0; nt < 4; ++nt) {
                int ncol = wn * 32 + nt * 8 + gi;
                bb[nt][0] = Bs[(kb + ti) * 132 + ncol];
                bb[nt][1] = Bs[(kb + ti + 4) * 132 + ncol];
            }
#pragma unroll
            for (int mt = 0; mt < 4; ++mt)
#pragma unroll
                for (int nt = 0; nt < 4; ++nt)
                    mma8(c_[mt][nt], a[mt], bb[nt]);
        }
        __syncthreads();
    }

#pragma unroll
    for (int mt = 0; mt < 4; ++mt) {
        int m = m0 + wm * 64 + mt * 16 + gi;
#pragma unroll
        for (int nt = 0; nt < 4; ++nt) {
            int n = n0 + wn * 32 + nt * 8 + 2 * ti;
            int part = n >> 9, hh = (n >> 6) & 7, dh = n & 63;
            float* dst = (part == 0) ? g_q : ((part == 1) ? g_k : g_v);
            int tr = m >> 3, bi = m & 7;
            size_t off = ((size_t)((bi * 8 + hh) * 512 + tr)) * 64 + dh;
            *(float2*)&dst[off] = make_float2(__uint_as_float(f2tf(c_[mt][nt][0])),
                                              __uint_as_float(f2tf(c_[mt][nt][1])));
            int m2 = m + 8;
            int tr2 = m2 >> 3, bi2 = m2 & 7;
            size_t off2 = ((size_t)((bi2 * 8 + hh) * 512 + tr2)) * 64 + dh;
            *(float2*)&dst[off2] = make_float2(__uint_as_float(f2tf(c_[mt][nt][2])),
                                               __uint_as_float(f2tf(c_[mt][nt][3])));
        }
    }
}

// ============================================================================
// rpe GEMM: g_rpe(1023,512) = sinusoid @ W_pos. 128x64, BK=32 (tf32 epilogue).
// ============================================================================
__global__ void __launch_bounds__(256)
rpe_mma_kernel(const float* __restrict__ Wpos) {
    __shared__ uint32_t As[128 * 36];
    __shared__ uint32_t Bs[32 * 68];
    __shared__ float freqs[512];
    const int m0 = blockIdx.y * 128, n0 = blockIdx.x * 64;
    const int tid = threadIdx.x, lane = tid & 31, wid = tid >> 5;
    const int gi = lane >> 2, ti = lane & 3;
    const int wm = wid >> 1, wn = wid & 1;

    for (int s = tid; s < 512; s += 256) {
        int cc = s & 255;
        freqs[s] = __expf(-9.210340371976184f * (float)cc * (1.0f / 256.0f));
    }
    __syncthreads();

    float c_[2][4][4] = {};

    for (int k0 = 0; k0 < 512; k0 += 32) {
#pragma unroll
        for (int rep = 0; rep < 16; ++rep) {
            int s = rep * 256 + tid;
            int row = s >> 5, kk = s & 31;
            int cgl = k0 + kk;
            float rel = (float)(m0 + row - 511);
            float ang = rel * freqs[cgl];
            float v = (cgl < 256) ? sinf(ang) : cosf(ang);
            As[row * 36 + kk] = f2tf(v);
        }
#pragma unroll
        for (int rep = 0; rep < 2; ++rep) {
            int s = rep * 256 + tid;
            int row = s >> 4, nseg = s & 15;
            float4 v = *(const float4*)&Wpos[(size_t)(k0 + row) * 512 + n0 + nseg * 4];
            uint32_t* d = &Bs[row * 68 + nseg * 4];
            d[0] = f2tf(v.x); d[1] = f2tf(v.y); d[2] = f2tf(v.z); d[3] = f2tf(v.w);
        }
        __syncthreads();
#pragma unroll
        for (int kb = 0; kb < 32; kb += 8) {
            uint32_t a[2][4];
#pragma unroll
            for (int mt = 0; mt < 2; ++mt) {
                int r = wm * 32 + mt * 16 + gi;
                a[mt][0] = As[r * 36 + kb + ti];
                a[mt][1] = As[(r + 8) * 36 + kb + ti];
                a[mt][2] = As[r * 36 + kb + ti + 4];
                a[mt][3] = As[(r + 8) * 36 + kb + ti + 4];
            }
#pragma unroll
            for (int nt = 0; nt < 4; ++nt) {
                uint32_t bf[2];
                int ncol = wn * 32 + nt * 8 + gi;
                bf[0] = Bs[(kb + ti) * 68 + ncol];
                bf[1] = Bs[(kb + ti + 4) * 68 + ncol];
                mma8(c_[0][nt], a[0], bf);
                mma8(c_[1][nt], a[1], bf);
            }
        }
        __syncthreads();
    }

#pragma unroll
    for (int mt = 0; mt < 2; ++mt) {
        int m = m0 + wm * 32 + mt * 16 + gi;
#pragma unroll
        for (int nt = 0; nt < 4; ++nt) {
            int n = n0 + wn * 32 + nt * 8 + 2 * ti;
            if (m < RR)
                *(float2*)&g_rpe[(size_t)m * 512 + n] =
                    make_float2(__uint_as_float(f2tf(c_[mt][nt][0])),
                                __uint_as_float(f2tf(c_[mt][nt][1])));
            if (m + 8 < RR)
                *(float2*)&g_rpe[(size_t)(m + 8) * 512 + n] =
                    make_float2(__uint_as_float(f2tf(c_[mt][nt][2])),
                                __uint_as_float(f2tf(c_[mt][nt][3])));
        }
    }
}

// ============================================================================
// bias kernels: 4 threads per 64-dot, shfl reduce
// ============================================================================
__global__ void uk_kernel(const float* __restrict__ pos_u) {
    int gid = blockIdx.x * 256 + threadIdx.x;
    int id = gid >> 2, part = gid & 3;
    int h = (id >> 9) & 7;
    const float4* kp = (const float4*)(g_k + (size_t)id * 64) + part * 4;
    const float4* up = (const float4*)(pos_u + h * 64) + part * 4;
    float acc = 0.f;
#pragma unroll
    for (int s = 0; s < 4; ++s) {
        float4 kk = kp[s], uu = up[s];
        acc += kk.x * uu.x + kk.y * uu.y + kk.z * uu.z + kk.w * uu.w;
    }
    acc += __shfl_xor_sync(0xffffffffu, acc, 1);
    acc += __shfl_xor_sync(0xffffffffu, acc, 2);
    if (part == 0) g_uk[id] = acc;
}

__global__ void vr_kernel(const float* __restrict__ pos_v) {
    int gid = blockIdx.x * 256 + threadIdx.x;
    int id = gid >> 2, part = gid & 3;
    if (id >= RR * HH) return;
    int r = id >> 3, h = id & 7;
    const float4* rp = (const float4*)(g_rpe + r * 512 + h * 64) + part * 4;
    const float4* vp = (const float4*)(pos_v + h * 64) + part * 4;
    float acc = 0.f;
#pragma unroll
    for (int s = 0; s < 4; ++s) {
        float4 rr = rp[s], vv = vp[s];
        acc += rr.x * vv.x + rr.y * vv.y + rr.z * vv.z + rr.w * vv.w;
    }
    acc += __shfl_xor_sync(0xffffffffu, acc, 1);
    acc += __shfl_xor_sync(0xffffffffu, acc, 2);
    if (part == 0) g_vr[id] = acc;
}

// ============================================================================
// Fused attention, software-pipelined staging (double-buffered Tf, 128-row
// chunks). 512 threads, TI=64 i-rows per block, one (b,h).
// ============================================================================
#define LDE 68
#define CH  128                     // rows per chunk
#define TFW 8192                    // words per Tf buffer (128*64)

// ---- A-fragment-layout staging (K / rpe rows) ----
__device__ __forceinline__ void ldg_A_k(uint32_t* r, const uint32_t* src,
                                        int wid, int gg, int tt) {
#pragma unroll
    for (int k = 0; k < 4; ++k) {
        int c = wid + (k << 4);          // [0,64): c = mt*8 + ks
        int mt = c >> 3, ks = c & 7;
#pragma unroll
        for (int aidx = 0; aidx < 4; ++aidx) {
            int row = mt * 16 + (aidx & 1) * 8 + gg;
            int col = ks * 8 + (aidx >> 1) * 4 + tt;
            r[k * 4 + aidx] = src[(size_t)row * 64 + col];
        }
    }
}

__device__ __forceinline__ void ldg_A_rpe(uint32_t* r, const uint32_t* rc,
                                          int ubase, int wid, int gg, int tt) {
#pragma unroll
    for (int k = 0; k < 4; ++k) {
        int c = wid + (k << 4);
        int mt = c >> 3, ks = c & 7;
#pragma unroll
        for (int aidx = 0; aidx < 4; ++aidx) {
            int row = mt * 16 + (aidx & 1) * 8 + gg;
            int col = ks * 8 + (aidx >> 1) * 4 + tt;
            int u = ubase + row;
            r[k * 4 + aidx] = (u < RR) ? rc[(size_t)u * 512 + col] : 0u;
        }
    }
}

__device__ __forceinline__ void sts_A(uint32_t* buf, const uint32_t* r,
                                      int wid, int lane) {
#pragma unroll
    for (int k = 0; k < 4; ++k) {
        int c = wid + (k << 4);
        *(uint4*)&buf[(c * 32 + lane) * 4] =
            make_uint4(r[k * 4], r[k * 4 + 1], r[k * 4 + 2], r[k * 4 + 3]);
    }
}

// ---- B-fragment-layout staging (V rows) ----
__device__ __forceinline__ void ldg_B_v(uint32_t* r, const uint32_t* src,
                                        int wid, int gg, int tt) {
#pragma unroll
    for (int k = 0; k < 8; ++k) {
        int c2 = wid + (k << 4);         // [0,128): c2 = nt*16 + ks
        int nt = c2 >> 4, ks = c2 & 15;
#pragma unroll
        for (int bidx = 0; bidx < 2; ++bidx) {
            int dh = nt * 8 + gg;
            int j = ks * 8 + bidx * 4 + tt;
            r[k * 2 + bidx] = src[(size_t)j * 64 + dh];
        }
    }
}

__device__ __forceinline__ void sts_B(uint32_t* buf, const uint32_t* r,
                                      int wid, int lane) {
#pragma unroll
    for (int k = 0; k < 8; ++k) {
        int c2 = wid + (k << 4);
        *(uint2*)&buf[(c2 * 32 + lane) * 2] = make_uint2(r[k * 2], r[k * 2 + 1]);
    }
}

__global__ void __launch_bounds__(512, 1)
attn_mma_kernel(const float* __restrict__ tau_ptr) {
    extern __shared__ float sm[];
    float*    e_s = sm;                            // 512*68
    uint32_t* Qf  = (uint32_t*)(e_s + 512 * LDE);  // 4096
    uint32_t* Tf0 = Qf + 4096;                     // 8192
    uint32_t* Tf1 = Tf0 + TFW;                     // 8192
    float* uks  = (float*)(Tf1 + TFW);             // 512
    float* vrs  = uks + 512;                       // 576
    float* red  = vrs + 576;                       // 512
    float* rowm = red + 512;                       // 64
    float* rowl = rowm + 64;                       // 64
    uint32_t* Tf[2] = {Tf0, Tf1};

    const int bh = blockIdx.y, h = bh & 7, b = bh >> 3;
    const int i0 = blockIdx.x * 64;
    const int tid = threadIdx.x, lane = tid & 31, wid = tid >> 5;
    const int gi = lane >> 2, ti = lane & 3;
    const int gg = gi, tt = ti;
    const int wm = wid >> 1, wn = wid & 1;          // AC/BD warp grid 8x2

    const uint32_t* kbase = (const uint32_t*)g_k + (size_t)bh * TT * 64;
    const uint32_t* vbase = (const uint32_t*)g_v + (size_t)bh * TT * 64;
    const uint32_t* rc    = (const uint32_t*)g_rpe + h * 64;

    uint32_t r[16];

    // ---- prefetch AC chunk 0 + init Q/uk/vr ----
    ldg_A_k(r, kbase, wid, gg, tt);
    {
        const uint32_t* qg = (const uint32_t*)g_q + ((size_t)bh * TT + i0) * 64;
        for (int s = tid; s < 4096; s += 512) {
            int bidx = s & 1, l = (s >> 1) & 31, ks = (s >> 6) & 7, nt = s >> 9;
            int gg2 = l >> 2, tt2 = l & 3;
            int ii = nt * 8 + gg2;
            int dh = ks * 8 + bidx * 4 + tt2;
            Qf[s] = qg[ii * 64 + dh];
        }
        uks[tid] = g_uk[bh * 512 + tid];
        for (int s = tid; s < 576; s += 512) {
            int u = i0 + s;
            vrs[s] = (u < RR) ? g_vr[u * 8 + h] : 0.f;
        }
    }
    sts_A(Tf[0], r, wid, lane);
    __syncthreads();

    // ---- Phase AC: 4 chunks of 128 j-rows, writes '=' ----
#pragma unroll
    for (int jc = 0; jc < 4; ++jc) {
        if (jc < 3) ldg_A_k(r, kbase + (size_t)(jc + 1) * CH * 64, wid, gg, tt);
        else        ldg_A_rpe(r, rc, i0, wid, gg, tt);     // prefetch BD chunk 0

        float c_[4][4] = {};
        const uint32_t* cur = Tf[jc & 1];
#pragma unroll
        for (int ks = 0; ks < 8; ++ks) {
            uint4 av = *(const uint4*)&cur[((wm * 8 + ks) * 32 + lane) * 4];
            uint32_t a[4] = {av.x, av.y, av.z, av.w};
#pragma unroll
            for (int n = 0; n < 4; ++n) {
                int nt = wn * 4 + n;
                uint2 bv = *(const uint2*)&Qf[((nt * 8 + ks) * 32 + lane) * 2];
                uint32_t bb[2] = {bv.x, bv.y};
                mma8(c_[n], a, bb);
            }
        }
        int j = jc * CH + wm * 16 + gi;
#pragma unroll
        for (int n = 0; n < 4; ++n) {
            int ii = wn * 32 + n * 8 + 2 * ti;
            *(float2*)&e_s[j * LDE + ii]       = make_float2(c_[n][0], c_[n][1]);
            *(float2*)&e_s[(j + 8) * LDE + ii] = make_float2(c_[n][2], c_[n][3]);
        }
        sts_A(Tf[(jc + 1) & 1], r, wid, lane);
        __syncthreads();
    }

    // ---- Phase BD: 5 chunks of 128 u-rows (+=); chunk 4 only 64 useful ----
#pragma unroll
    for (int ch = 0; ch < 5; ++ch) {
        if (ch < 4) ldg_A_rpe(r, rc, i0 + (ch + 1) * CH, wid, gg, tt);
        else        ldg_B_v(r, vbase, wid, gg, tt);        // prefetch PV chunk 0

        if (!(ch == 4 && wm >= 4)) {
            float c_[4][4] = {};
            const uint32_t* cur = Tf[ch & 1];
#pragma unroll
            for (int ks = 0; ks < 8; ++ks) {
                uint4 av = *(const uint4*)&cur[((wm * 8 + ks) * 32 + lane) * 4];
                uint32_t a[4] = {av.x, av.y, av.z, av.w};
#pragma unroll
                for (int n = 0; n < 4; ++n) {
                    int nt = wn * 4 + n;
                    uint2 bv = *(const uint2*)&Qf[((nt * 8 + ks) * 32 + lane) * 2];
                    uint32_t bb[2] = {bv.x, bv.y};
                    mma8(c_[n], a, bb);
                }
            }
            int uloc = ch * CH + wm * 16 + gi;             // u - i0
#pragma unroll
            for (int n = 0; n < 4; ++n) {
                int ii = wn * 32 + n * 8 + 2 * ti;
                int j0 = ii - uloc + 511;
                int j1 = j0 + 1;
                int j2 = j0 - 8;
                int j3 = j1 - 8;
                if ((unsigned)j0 < 512u) e_s[j0 * LDE + ii]     += c_[n][0];
                if ((unsigned)j1 < 512u) e_s[j1 * LDE + ii + 1] += c_[n][1];
                if ((unsigned)j2 < 512u) e_s[j2 * LDE + ii]     += c_[n][2];
                if ((unsigned)j3 < 512u) e_s[j3 * LDE + ii + 1] += c_[n][3];
            }
        }
        if (ch < 4) sts_A(Tf[(ch + 1) & 1], r, wid, lane);
        else        sts_B(Tf[1], r, wid, lane);            // PV chunk 0 -> buf1
        __syncthreads();
    }

    // ---- finalize + softmax over j, per column i ----
    {
        const float scale = 0.125f;
        const float tauf = expf(tau_ptr[0]);
        int col = tid & 63, seg = tid >> 6;
        int ig = i0 + col;
        float mloc = -FLT_MAX;
        for (int jj = 0; jj < 64; ++jj) {
            int j = seg * 64 + jj;
            float val = e_s[j * LDE + col];
            val = (val + uks[j] + vrs[col - j + 511]) * scale;
            if (j == ig) val = -FLT_MAX;
            val *= tauf;
            e_s[j * LDE + col] = val;
            mloc = fmaxf(mloc, val);
        }
        red[seg * 64 + col] = mloc;
        __syncthreads();
        if (tid < 64) {
            float m = red[tid];
#pragma unroll
            for (int s = 1; s < 8; ++s) m = fmaxf(m, red[s * 64 + tid]);
            rowm[tid] = m;
        }
        __syncthreads();
        float m = rowm[col];
        float sloc = 0.f;
        for (int jj = 0; jj < 64; ++jj) {
            int j = seg * 64 + jj;
            float p = __expf(e_s[j * LDE + col] - m);
            e_s[j * LDE + col] = p;
            sloc += p;
        }
        red[seg * 64 + col] = sloc;
        __syncthreads();
        if (tid < 64) {
            float s = 0.f;
#pragma unroll
            for (int ss = 0; ss < 8; ++ss) s += red[ss * 64 + tid];
            rowl[tid] = s;
        }
        __syncthreads();
    }

    // ---- Phase PV: 4 chunks; A = P (e_s bits), B = V staged (B-frag) ----
    // chunk jc lives in buffer (jc^1)&1  (chunk 0 pre-staged into buf1)
    float o_[2][4] = {};
    const int pwm = wid >> 2;       // i-tile 0..3
    const int pwn = wid & 3;        // dh group 0..3
    const uint32_t* es_u = (const uint32_t*)e_s;
#pragma unroll
    for (int jc = 0; jc < 4; ++jc) {
        if (jc < 3) ldg_B_v(r, vbase + (size_t)(jc + 1) * CH * 64, wid, gg, tt);

        const uint32_t* cur = Tf[(jc ^ 1) & 1];
#pragma unroll
        for (int ks = 0; ks < 16; ++ks) {
            int jb = jc * CH + ks * 8;
            int ibase = pwm * 16 + gi;
            uint32_t a[4];
            a[0] = es_u[(jb + ti) * LDE + ibase];
            a[1] = es_u[(jb + ti) * LDE + ibase + 8];
            a[2] = es_u[(jb + ti + 4) * LDE + ibase];
            a[3] = es_u[(jb + ti + 4) * LDE + ibase + 8];
#pragma unroll
            for (int n = 0; n < 2; ++n) {
                int nt = pwn * 2 + n;
                uint2 bv = *(const uint2*)&cur[((nt * 16 + ks) * 32 + lane) * 2];
                uint32_t bb[2] = {bv.x, bv.y};
                mma8(o_[n], a, bb);
            }
        }
        if (jc < 3) sts_B(Tf[jc & 1], r, wid, lane);
        __syncthreads();
    }

    {
        int i1 = pwm * 16 + gi, i2 = i1 + 8;
        float inv1 = 1.f / rowl[i1];
        float inv2 = 1.f / rowl[i2];
#pragma unroll
        for (int n = 0; n < 2; ++n) {
            int dh = pwn * 16 + n * 8 + 2 * ti;
            float* o1 = g_ao + (size_t)(i0 + i1) * (BB * DD) + b * DD + h * 64 + dh;
            float* o2 = g_ao + (size_t)(i0 + i2) * (BB * DD) + b * DD + h * 64 + dh;
            *(float2*)o1 = make_float2(o_[n][0] * inv1, o_[n][1] * inv1);
            *(float2*)o2 = make_float2(o_[n][2] * inv2, o_[n][3] * inv2);
        }
    }
}

// ============================================================================
// Output projection: out(4096,512) = g_ao @ W_out + b_out (tf32 mma)
// ============================================================================
__global__ void __launch_bounds__(256)
out_mma_kernel(const float* __restrict__ W,
               const float* __restrict__ bias,
               float* __restrict__ out) {
    __shared__ uint32_t As[128 * 36];
    __shared__ uint32_t Bs[32 * 68];
    const int m0 = blockIdx.y * 128, n0 = blockIdx.x * 64;
    const int tid = threadIdx.x, lane = tid & 31, wid = tid >> 5;
    const int gi = lane >> 2, ti = lane & 3;
    const int wm = wid >> 1, wn = wid & 1;

    float c_[2][4][4] = {};

    for (int k0 = 0; k0 < 512; k0 += 32) {
#pragma unroll
        for (int rep = 0; rep < 4; ++rep) {
            int s = rep * 256 + tid;
            int row = s >> 3, kseg = s & 7;
            float4 v = *(const float4*)&g_ao[(size_t)(m0 + row) * 512 + k0 + kseg * 4];
            uint32_t* d = &As[row * 36 + kseg * 4];
            d[0] = f2tf(v.x); d[1] = f2tf(v.y); d[2] = f2tf(v.z); d[3] = f2tf(v.w);
        }
#pragma unroll
        for (int rep = 0; rep < 2; ++rep) {
            int s = rep * 256 + tid;
            int row = s >> 4, nseg = s & 15;
            float4 v = *(const float4*)&W[(size_t)(k0 + row) * 512 + n0 + nseg * 4];
            uint32_t* d = &Bs[row * 68 + nseg * 4];
            d[0] = f2tf(v.x); d[1] = f2tf(v.y); d[2] = f2tf(v.z); d[3] = f2tf(v.w);
        }
        __syncthreads();
#pragma unroll
        for (int kb = 0; kb < 32; kb += 8) {
            uint32_t a[2][4];
#pragma unroll
            for (int mt = 0; mt < 2; ++mt) {
                int r = wm * 32 + mt * 16 + gi;
                a[mt][0] = As[r * 36 + kb + ti];
                a[mt][1] = As[(r + 8) * 36 + kb + ti];
                a[mt][2] = As[r * 36 + kb + ti + 4];
                a[mt][3] = As[(r + 8) * 36 + kb + ti + 4];
            }
#pragma unroll
            for (int nt = 0; nt < 4; ++nt) {
                uint32_t bf[2];
                int ncol = wn * 32 + nt * 8 + gi;
                bf[0] = Bs[(kb + ti) * 68 + ncol];
                bf[1] = Bs[(kb + ti + 4) * 68 + ncol];
                mma8(c_[0][nt], a[0], bf);
                mma8(c_[1][nt], a[1], bf);
            }
        }
        __syncthreads();
    }

#pragma unroll
    for (int mt = 0; mt < 2; ++mt) {
        int m = m0 + wm * 32 + mt * 16 + gi;
#pragma unroll
        for (int nt = 0; nt < 4; ++nt) {
            int n = n0 + wn * 32 + nt * 8 + 2 * ti;
            float b0 = bias[n], b1 = bias[n + 1];
            *(float2*)&out[(size_t)m * 512 + n] =
                make_float2(c_[mt][nt][0] + b0, c_[mt][nt][1] + b1);
            *(float2*)&out[(size_t)(m + 8) * 512 + n] =
                make_float2(c_[mt][nt][2] + b0, c_[mt][nt][3] + b1);
        }
    }
}

// ============================================================================
extern "C" void kernel_launch(void* const* d_in, const int* in_sizes, int n_in,
                              void* d_out, int out_size) {
    const float* x     = (const float*)d_in[0];
    const float* Wqkv  = (const float*)d_in[1];
    const float* Wpos  = (const float*)d_in[2];
    const float* pos_u = (const float*)d_in[3];
    const float* pos_v = (const float*)d_in[4];
    const float* Wout  = (const float*)d_in[5];
    const float* bout  = (const float*)d_in[6];
    const float* ltau  = (const float*)d_in[7];
    float* out = (float*)d_out;

    qkv_mma_kernel<<<dim3(12, 32), 256>>>(x, Wqkv);
    rpe_mma_kernel<<<dim3(8, 8), 256>>>(Wpos);
    uk_kernel<<<512, 256>>>(pos_u);
    vr_kernel<<<128, 256>>>(pos_v);

    const size_t smem = (size_t)(512 * LDE + 4096 + 2 * TFW + 512 + 576 + 512 + 64 + 64) * sizeof(float);
    cudaFuncSetAttribute(attn_mma_kernel, cudaFuncAttributeMaxDynamicSharedMemorySize, (int)smem);
    attn_mma_kernel<<<dim3(8, 64), 512, smem>>>(ltau);

    out_mma_kernel<<<dim3(8, 32), 256>>>(Wout, bout, out);
}

// round 8
// speedup vs baseline: 1.2640x; 1.1756x over previous
#include <cuda_runtime.h>
#include <cuda_fp16.h>
#include <math.h>
#include <float.h>
#include <stdint.h>

#define TT   512
#define BB   8
#define DD   512
#define HH   8
#define DHH  64
#define RR   1023
#define BHN  64
#define MROWS 4096

// ---------------- scratch (fp16 payloads) ----------------
__device__ __half g_q[BHN * TT * DHH];      // [b*8+h][t][dh]
__device__ __half g_k[BHN * TT * DHH];
__device__ __half g_vT[BHN * DHH * TT];     // [b*8+h][dh][t]  (transposed V)
__device__ __half g_rpe[RR * DD];           // [r][h*64+dh]
__device__ __half g_xh[MROWS * DD];         // x as half
__device__ __half g_wqh[1536 * 512];        // W_qkv^T [n][k]
__device__ __half g_wph[512 * 512];         // W_pos^T [n][k]
__device__ __half g_woh[512 * 512];         // W_out^T [n][k]
__device__ __half g_aoh[MROWS * DD];        // attention out, (t,b,d) rows, half
__device__ float  g_uk[BHN * TT];
__device__ float  g_vr[RR * HH];

__device__ __forceinline__ void mma16(float* c, const uint32_t* a, const uint32_t* b) {
    asm volatile(
        "mma.sync.aligned.m16n8k16.row.col.f32.f16.f16.f32 "
        "{%0,%1,%2,%3},{%4,%5,%6,%7},{%8,%9},{%0,%1,%2,%3};"
        : "+f"(c[0]), "+f"(c[1]), "+f"(c[2]), "+f"(c[3])
        : "r"(a[0]), "r"(a[1]), "r"(a[2]), "r"(a[3]), "r"(b[0]), "r"(b[1]));
}

__device__ __forceinline__ uint32_t packh2(float lo, float hi) {
    __half2 h = __floats2half2_rn(lo, hi);
    return *(uint32_t*)&h;
}

// ============================================================================
// prep kernels
// ============================================================================
__global__ void xhalf_kernel(const float* __restrict__ src) {
    int i = blockIdx.x * 256 + threadIdx.x;          // 2M elements / 4
    float4 v = *(const float4*)&src[(size_t)i * 4];
    uint32_t w0 = packh2(v.x, v.y), w1 = packh2(v.z, v.w);
    *(uint32_t*)&g_xh[(size_t)i * 4]     = w0;
    *(uint32_t*)&g_xh[(size_t)i * 4 + 2] = w1;
}

__global__ void transpose_half(const float* __restrict__ src, __half* __restrict__ dst,
                               int K, int N) {
    __shared__ float t[32][33];
    int n0 = blockIdx.x * 32, k0 = blockIdx.y * 32;
    int tx = threadIdx.x & 31, ty = threadIdx.x >> 5;   // 256 thr
    for (int r = ty; r < 32; r += 8)
        t[r][tx] = src[(size_t)(k0 + r) * N + n0 + tx];
    __syncthreads();
    for (int r = ty; r < 32; r += 8)
        dst[(size_t)(n0 + r) * K + k0 + tx] = __float2half(t[tx][r]);
}

// ============================================================================
// QKV GEMM fp16: C(4096,1536) = x @ W.  128x128 tile, BK=64 halves, 256 thr,
// warp 64x32. Epilogue: q,k -> [bh][t][dh]; v -> [bh][dh][t] transposed.
// ============================================================================
__global__ void __launch_bounds__(256, 2)
qkv_fp16_kernel() {
    __shared__ uint32_t As[128 * 36];   // [m][kw] 32 words used
    __shared__ uint32_t Bs[128 * 36];   // [n][kw]
    const int m0 = blockIdx.y * 128, n0 = blockIdx.x * 128;
    const int tid = threadIdx.x, lane = tid & 31, wid = tid >> 5;
    const int gi = lane >> 2, ti = lane & 3;
    const int wm = wid >> 2, wn = wid & 3;

    const uint32_t* aw = (const uint32_t*)g_xh;    // 256 words/row
    const uint32_t* bw = (const uint32_t*)g_wqh;

    float c_[4][4][4] = {};

    for (int k0 = 0; k0 < 8; ++k0) {               // 8 iters of 32 words
#pragma unroll
        for (int rep = 0; rep < 4; ++rep) {
            int s = rep * 256 + tid;               // 1024 uint4 slots
            int row = s >> 3, seg = s & 7;
            *(uint4*)&As[row * 36 + seg * 4] =
                *(const uint4*)&aw[(size_t)(m0 + row) * 256 + k0 * 32 + seg * 4];
        }
#pragma unroll
        for (int rep = 0; rep < 4; ++rep) {
            int s = rep * 256 + tid;
            int row = s >> 3, seg = s & 7;
            *(uint4*)&Bs[row * 36 + seg * 4] =
                *(const uint4*)&bw[(size_t)(n0 + row) * 256 + k0 * 32 + seg * 4];
        }
        __syncthreads();
#pragma unroll
        for (int kb = 0; kb < 4; ++kb) {
            uint32_t a[4][4], bb[4][2];
#pragma unroll
            for (int mt = 0; mt < 4; ++mt) {
                int r = wm * 64 + mt * 16 + gi;
                a[mt][0] = As[r * 36 + kb * 8 + ti];
                a[mt][1] = As[(r + 8) * 36 + kb * 8 + ti];
                a[mt][2] = As[r * 36 + kb * 8 + ti + 4];
                a[mt][3] = As[(r + 8) * 36 + kb * 8 + ti + 4];
            }
#pragma unroll
            for (int nt = 0; nt < 4; ++nt) {
                int ncol = wn * 32 + nt * 8 + gi;
                bb[nt][0] = Bs[ncol * 36 + kb * 8 + ti];
                bb[nt][1] = Bs[ncol * 36 + kb * 8 + ti + 4];
            }
#pragma unroll
            for (int mt = 0; mt < 4; ++mt)
#pragma unroll
                for (int nt = 0; nt < 4; ++nt)
                    mma16(c_[mt][nt], a[mt], bb[nt]);
        }
        __syncthreads();
    }

#pragma unroll
    for (int mt = 0; mt < 4; ++mt) {
        int m = m0 + wm * 64 + mt * 16 + gi;
#pragma unroll
        for (int nt = 0; nt < 4; ++nt) {
            int n = n0 + wn * 32 + nt * 8 + 2 * ti;
            int part = n >> 9, hh = (n >> 6) & 7, dh = n & 63;
#pragma unroll
            for (int half = 0; half < 2; ++half) {
                int mm = m + half * 8;
                float v0 = c_[mt][nt][half * 2], v1 = c_[mt][nt][half * 2 + 1];
                int tr = mm >> 3, bi = mm & 7;
                int bh = bi * 8 + hh;
                if (part == 2) {
                    g_vT[((size_t)bh * 64 + dh) * 512 + tr]     = __float2half(v0);
                    g_vT[((size_t)bh * 64 + dh + 1) * 512 + tr] = __float2half(v1);
                } else {
                    __half* dst = (part == 0) ? g_q : g_k;
                    uint32_t w = packh2(v0, v1);
                    *(uint32_t*)&dst[((size_t)bh * 512 + tr) * 64 + dh] = w;
                }
            }
        }
    }
}

// ============================================================================
// rpe GEMM fp16: g_rpe(1023,512) = sinusoid(1024,512) @ W_pos (A generated)
// ============================================================================
__global__ void __launch_bounds__(256)
rpe_fp16_kernel() {
    __shared__ uint32_t As[128 * 36];
    __shared__ uint32_t Bs[128 * 36];
    __shared__ float freqs[512];
    const int m0 = blockIdx.y * 128, n0 = blockIdx.x * 128;
    const int tid = threadIdx.x, lane = tid & 31, wid = tid >> 5;
    const int gi = lane >> 2, ti = lane & 3;
    const int wm = wid >> 2, wn = wid & 3;

    for (int s = tid; s < 512; s += 256) {
        int cc = s & 255;
        freqs[s] = __expf(-9.210340371976184f * (float)cc * (1.0f / 256.0f));
    }
    __syncthreads();

    const uint32_t* bw = (const uint32_t*)g_wph;
    float c_[4][4][4] = {};

    for (int k0 = 0; k0 < 8; ++k0) {
#pragma unroll
        for (int rep = 0; rep < 16; ++rep) {
            int s = rep * 256 + tid;               // 4096 words
            int row = s >> 5, w = s & 31;
            int kg = k0 * 64 + 2 * w;
            float rel = (float)(m0 + row - 511);
            float a0 = rel * freqs[kg], a1 = rel * freqs[kg + 1];
            float f0 = (kg < 256) ? sinf(a0) : cosf(a0);
            float f1 = (kg + 1 < 256) ? sinf(a1) : cosf(a1);
            As[row * 36 + w] = packh2(f0, f1);
        }
#pragma unroll
        for (int rep = 0; rep < 4; ++rep) {
            int s = rep * 256 + tid;
            int row = s >> 3, seg = s & 7;
            *(uint4*)&Bs[row * 36 + seg * 4] =
                *(const uint4*)&bw[(size_t)(n0 + row) * 256 + k0 * 32 + seg * 4];
        }
        __syncthreads();
#pragma unroll
        for (int kb = 0; kb < 4; ++kb) {
            uint32_t a[4][4], bb[4][2];
#pragma unroll
            for (int mt = 0; mt < 4; ++mt) {
                int r = wm * 64 + mt * 16 + gi;
                a[mt][0] = As[r * 36 + kb * 8 + ti];
                a[mt][1] = As[(r + 8) * 36 + kb * 8 + ti];
                a[mt][2] = As[r * 36 + kb * 8 + ti + 4];
                a[mt][3] = As[(r + 8) * 36 + kb * 8 + ti + 4];
            }
#pragma unroll
            for (int nt = 0; nt < 4; ++nt) {
                int ncol = wn * 32 + nt * 8 + gi;
                bb[nt][0] = Bs[ncol * 36 + kb * 8 + ti];
                bb[nt][1] = Bs[ncol * 36 + kb * 8 + ti + 4];
            }
#pragma unroll
            for (int mt = 0; mt < 4; ++mt)
#pragma unroll
                for (int nt = 0; nt < 4; ++nt)
                    mma16(c_[mt][nt], a[mt], bb[nt]);
        }
        __syncthreads();
    }

#pragma unroll
    for (int mt = 0; mt < 4; ++mt) {
        int m = m0 + wm * 64 + mt * 16 + gi;
#pragma unroll
        for (int nt = 0; nt < 4; ++nt) {
            int n = n0 + wn * 32 + nt * 8 + 2 * ti;
            if (m < RR)
                *(uint32_t*)&g_rpe[(size_t)m * 512 + n] = packh2(c_[mt][nt][0], c_[mt][nt][1]);
            if (m + 8 < RR)
                *(uint32_t*)&g_rpe[(size_t)(m + 8) * 512 + n] = packh2(c_[mt][nt][2], c_[mt][nt][3]);
        }
    }
}

// ============================================================================
// bias kernels (half inputs)
// ============================================================================
__global__ void uk_kernel(const float* __restrict__ pos_u) {
    int gid = blockIdx.x * 256 + threadIdx.x;
    int id = gid >> 2, part = gid & 3;
    int h = (id >> 9) & 7;
    const __half2* kp = (const __half2*)(g_k + (size_t)id * 64) + part * 8;
    const float* up = pos_u + h * 64 + part * 16;
    float acc = 0.f;
#pragma unroll
    for (int s = 0; s < 8; ++s) {
        float2 kf = __half22float2(kp[s]);
        acc += kf.x * up[2 * s] + kf.y * up[2 * s + 1];
    }
    acc += __shfl_xor_sync(0xffffffffu, acc, 1);
    acc += __shfl_xor_sync(0xffffffffu, acc, 2);
    if (part == 0) g_uk[id] = acc;
}

__global__ void vr_kernel(const float* __restrict__ pos_v) {
    int gid = blockIdx.x * 256 + threadIdx.x;
    int id = gid >> 2, part = gid & 3;
    if (id >= RR * HH) return;
    int r = id >> 3, h = id & 7;
    const __half2* rp = (const __half2*)(g_rpe + (size_t)r * 512 + h * 64) + part * 8;
    const float* vp = pos_v + h * 64 + part * 16;
    float acc = 0.f;
#pragma unroll
    for (int s = 0; s < 8; ++s) {
        float2 rf = __half22float2(rp[s]);
        acc += rf.x * vp[2 * s] + rf.y * vp[2 * s + 1];
    }
    acc += __shfl_xor_sync(0xffffffffu, acc, 1);
    acc += __shfl_xor_sync(0xffffffffu, acc, 2);
    if (part == 0) g_vr[id] = acc;
}

// ============================================================================
// Fused attention fp16. 512 thr, TI=64 i-rows per block, one (b,h).
// Pipelined double-buffered staging. All mma = m16n8k16 fp16.
// ============================================================================
#define LDE 68
#define CH  128
#define TFW 4608    // words per Tf buffer (A-chunks 4096, Vt-chunks 64*68=4352)

// ---- A-frag staging: K rows ([t][dh] half, 32 words/row) ----
__device__ __forceinline__ void ldg_A_k(uint32_t* r, const uint32_t* src,
                                        int wid, int gg, int tt) {
#pragma unroll
    for (int k = 0; k < 2; ++k) {
        int c = wid + (k << 4);          // c = mt*4 + ks, c in [0,32)
        int mt = c >> 2, ks = c & 3;
#pragma unroll
        for (int aidx = 0; aidx < 4; ++aidx) {
            int row = mt * 16 + (aidx & 1) * 8 + gg;
            int col = ks * 8 + (aidx >> 1) * 4 + tt;
            r[k * 4 + aidx] = src[(size_t)row * 32 + col];
        }
    }
}

// ---- A-frag staging: rpe rows ([r][256 words], h-offset applied) ----
__device__ __forceinline__ void ldg_A_rpe(uint32_t* r, const uint32_t* rc,
                                          int ubase, int wid, int gg, int tt) {
#pragma unroll
    for (int k = 0; k < 2; ++k) {
        int c = wid + (k << 4);
        int mt = c >> 2, ks = c & 3;
#pragma unroll
        for (int aidx = 0; aidx < 4; ++aidx) {
            int row = mt * 16 + (aidx & 1) * 8 + gg;
            int col = ks * 8 + (aidx >> 1) * 4 + tt;
            int u = ubase + row;
            r[k * 4 + aidx] = (u < RR) ? rc[(size_t)u * 256 + col] : 0u;
        }
    }
}

__device__ __forceinline__ void sts_A(uint32_t* buf, const uint32_t* r,
                                      int wid, int lane) {
#pragma unroll
    for (int k = 0; k < 2; ++k) {
        int c = wid + (k << 4);
        *(uint4*)&buf[(c * 32 + lane) * 4] =
            make_uint4(r[k * 4], r[k * 4 + 1], r[k * 4 + 2], r[k * 4 + 3]);
    }
}

// ---- V staging from g_vT ([dh][t] half -> chunk tile [dh][64 words], ld 68) ----
__device__ __forceinline__ void ldg_B_v(uint32_t* r, const uint32_t* src, int tid) {
#pragma unroll
    for (int k = 0; k < 8; ++k) {
        int idx = k * 512 + tid;         // 4096 words
        int dh = idx >> 6, w = idx & 63;
        r[k] = src[(size_t)dh * 256 + w];
    }
}

__device__ __forceinline__ void sts_B(uint32_t* buf, const uint32_t* r, int tid) {
#pragma unroll
    for (int k = 0; k < 8; ++k) {
        int idx = k * 512 + tid;
        int dh = idx >> 6, w = idx & 63;
        buf[dh * 68 + w] = r[k];
    }
}

__global__ void __launch_bounds__(512, 1)
attn_fp16_kernel(const float* __restrict__ tau_ptr) {
    extern __shared__ float sm[];
    float*    e_s = sm;                             // 512*68 fp32
    uint32_t* Qf  = (uint32_t*)(e_s + 512 * LDE);   // 2048
    uint32_t* Tf0 = Qf + 2048;                      // 4608
    uint32_t* Tf1 = Tf0 + TFW;                      // 4608
    float* uks  = (float*)(Tf1 + TFW);              // 512
    float* vrs  = uks + 512;                        // 576
    float* red  = vrs + 576;                        // 512
    float* rowm = red + 512;                        // 64
    float* rowl = rowm + 64;                        // 64
    uint32_t* Tf[2] = {Tf0, Tf1};

    const int bh = blockIdx.y, h = bh & 7, b = bh >> 3;
    const int i0 = blockIdx.x * 64;
    const int tid = threadIdx.x, lane = tid & 31, wid = tid >> 5;
    const int gi = lane >> 2, ti = lane & 3;
    const int wm = wid >> 1, wn = wid & 1;          // AC/BD warp grid 8x2

    const uint32_t* kbase = (const uint32_t*)g_k + (size_t)bh * TT * 32;
    const uint32_t* vTbase = (const uint32_t*)g_vT + (size_t)bh * 64 * 256;
    const uint32_t* rc = (const uint32_t*)g_rpe + h * 32;

    uint32_t r[8];

    // ---- prefetch AC chunk 0 + init Q (B-frag layout), uk, vr ----
    ldg_A_k(r, kbase, wid, gi, ti);
    {
        const uint32_t* qg = (const uint32_t*)g_q + ((size_t)bh * TT + i0) * 32;
        for (int s = tid; s < 2048; s += 512) {
            int bidx = s & 1, l = (s >> 1) & 31, ks = (s >> 6) & 3, nt = s >> 8;
            int gg2 = l >> 2, tt2 = l & 3;
            int ii = nt * 8 + gg2;
            int dhw = ks * 8 + bidx * 4 + tt2;
            Qf[s] = qg[ii * 32 + dhw];
        }
        uks[tid] = g_uk[bh * 512 + tid];
        for (int s = tid; s < 576; s += 512) {
            int u = i0 + s;
            vrs[s] = (u < RR) ? g_vr[u * 8 + h] : 0.f;
        }
    }
    sts_A(Tf[0], r, wid, lane);
    __syncthreads();

    // ---- Phase AC: 4 chunks of 128 j-rows, writes '=' ----
#pragma unroll
    for (int jc = 0; jc < 4; ++jc) {
        if (jc < 3) ldg_A_k(r, kbase + (size_t)(jc + 1) * CH * 32, wid, gi, ti);
        else        ldg_A_rpe(r, rc, i0, wid, gi, ti);     // prefetch BD chunk 0

        float c_[4][4] = {};
        const uint32_t* cur = Tf[jc & 1];
#pragma unroll
        for (int ks = 0; ks < 4; ++ks) {
            uint4 av = *(const uint4*)&cur[((wm * 4 + ks) * 32 + lane) * 4];
            uint32_t a[4] = {av.x, av.y, av.z, av.w};
#pragma unroll
            for (int n = 0; n < 4; ++n) {
                int nt = wn * 4 + n;
                uint2 bv = *(const uint2*)&Qf[((nt * 4 + ks) * 32 + lane) * 2];
                uint32_t bb[2] = {bv.x, bv.y};
                mma16(c_[n], a, bb);
            }
        }
        int j = jc * CH + wm * 16 + gi;
#pragma unroll
        for (int n = 0; n < 4; ++n) {
            int ii = wn * 32 + n * 8 + 2 * ti;
            *(float2*)&e_s[j * LDE + ii]       = make_float2(c_[n][0], c_[n][1]);
            *(float2*)&e_s[(j + 8) * LDE + ii] = make_float2(c_[n][2], c_[n][3]);
        }
        sts_A(Tf[(jc + 1) & 1], r, wid, lane);
        __syncthreads();
    }

    // ---- Phase BD: 5 chunks of 128 u-rows (+=); chunk 4 only 64 useful ----
#pragma unroll
    for (int ch = 0; ch < 5; ++ch) {
        if (ch < 4) ldg_A_rpe(r, rc, i0 + (ch + 1) * CH, wid, gi, ti);
        else        ldg_B_v(r, vTbase, tid);               // prefetch PV chunk 0

        if (!(ch == 4 && wm >= 4)) {
            float c_[4][4] = {};
            const uint32_t* cur = Tf[ch & 1];
#pragma unroll
            for (int ks = 0; ks < 4; ++ks) {
                uint4 av = *(const uint4*)&cur[((wm * 4 + ks) * 32 + lane) * 4];
                uint32_t a[4] = {av.x, av.y, av.z, av.w};
#pragma unroll
                for (int n = 0; n < 4; ++n) {
                    int nt = wn * 4 + n;
                    uint2 bv = *(const uint2*)&Qf[((nt * 4 + ks) * 32 + lane) * 2];
                    uint32_t bb[2] = {bv.x, bv.y};
                    mma16(c_[n], a, bb);
                }
            }
            int uloc = ch * CH + wm * 16 + gi;             // u - i0
#pragma unroll
            for (int n = 0; n < 4; ++n) {
                int ii = wn * 32 + n * 8 + 2 * ti;
                int j0 = ii - uloc + 511;
                int j1 = j0 + 1;
                int j2 = j0 - 8;
                int j3 = j1 - 8;
                if ((unsigned)j0 < 512u) e_s[j0 * LDE + ii]     += c_[n][0];
                if ((unsigned)j1 < 512u) e_s[j1 * LDE + ii + 1] += c_[n][1];
                if ((unsigned)j2 < 512u) e_s[j2 * LDE + ii]     += c_[n][2];
                if ((unsigned)j3 < 512u) e_s[j3 * LDE + ii + 1] += c_[n][3];
            }
        }
        if (ch < 4) sts_A(Tf[(ch + 1) & 1], r, wid, lane);
        else        sts_B(Tf[1], r, tid);                  // PV chunk 0 -> buf1
        __syncthreads();
    }

    // ---- finalize + softmax over j, per column i ----
    {
        const float scale = 0.125f;
        const float tauf = expf(tau_ptr[0]);
        int col = tid & 63, seg = tid >> 6;
        int ig = i0 + col;
        float mloc = -FLT_MAX;
        for (int jj = 0; jj < 64; ++jj) {
            int j = seg * 64 + jj;
            float val = e_s[j * LDE + col];
            val = (val + uks[j] + vrs[col - j + 511]) * scale;
            if (j == ig) val = -FLT_MAX;
            val *= tauf;
            e_s[j * LDE + col] = val;
            mloc = fmaxf(mloc, val);
        }
        red[seg * 64 + col] = mloc;
        __syncthreads();
        if (tid < 64) {
            float m = red[tid];
#pragma unroll
            for (int s = 1; s < 8; ++s) m = fmaxf(m, red[s * 64 + tid]);
            rowm[tid] = m;
        }
        __syncthreads();
        float m = rowm[col];
        float sloc = 0.f;
        for (int jj = 0; jj < 64; ++jj) {
            int j = seg * 64 + jj;
            float p = __expf(e_s[j * LDE + col] - m);
            e_s[j * LDE + col] = p;
            sloc += p;
        }
        red[seg * 64 + col] = sloc;
        __syncthreads();
        if (tid < 64) {
            float s = 0.f;
#pragma unroll
            for (int ss = 0; ss < 8; ++ss) s += red[ss * 64 + tid];
            rowl[tid] = s;
        }
        __syncthreads();
    }

    // ---- Phase PV: A = P (cvt from e_s fp32), B = V staged ([dh][jw], ld 68) ----
    float o_[2][4] = {};
    const int pwm = wid >> 2;       // i-tile 0..3
    const int pwn = wid & 3;        // dh group 0..3
#pragma unroll
    for (int jc = 0; jc < 4; ++jc) {
        if (jc < 3) ldg_B_v(r, vTbase + (size_t)(jc + 1) * 64, tid);

        const uint32_t* cur = Tf[(jc ^ 1) & 1];
        int ibase = pwm * 16 + gi;
#pragma unroll
        for (int ks = 0; ks < 8; ++ks) {
            int jb = jc * CH + ks * 16;
            uint32_t a[4];
            {
                int je = jb + 2 * ti;
                float p00 = e_s[je * LDE + ibase],       p01 = e_s[(je + 1) * LDE + ibase];
                float p10 = e_s[je * LDE + ibase + 8],   p11 = e_s[(je + 1) * LDE + ibase + 8];
                float p20 = e_s[(je + 8) * LDE + ibase],     p21 = e_s[(je + 9) * LDE + ibase];
                float p30 = e_s[(je + 8) * LDE + ibase + 8], p31 = e_s[(je + 9) * LDE + ibase + 8];
                a[0] = packh2(p00, p01);
                a[1] = packh2(p10, p11);
                a[2] = packh2(p20, p21);
                a[3] = packh2(p30, p31);
            }
#pragma unroll
            for (int n = 0; n < 2; ++n) {
                int ncol = pwn * 16 + n * 8 + gi;
                uint32_t bb[2];
                bb[0] = cur[ncol * 68 + ks * 8 + ti];
                bb[1] = cur[ncol * 68 + ks * 8 + ti + 4];
                mma16(o_[n], a, bb);
            }
        }
        if (jc < 3) sts_B(Tf[jc & 1], r, tid);
        __syncthreads();
    }

    // ---- epilogue: normalize, write half to g_aoh (t,b,d) rows ----
    {
        int i1 = pwm * 16 + gi, i2 = i1 + 8;
        float inv1 = 1.f / rowl[i1];
        float inv2 = 1.f / rowl[i2];
#pragma unroll
        for (int n = 0; n < 2; ++n) {
            int dh = pwn * 16 + n * 8 + 2 * ti;
            size_t o1 = ((size_t)(i0 + i1) * 8 + b) * 512 + h * 64 + dh;
            size_t o2 = ((size_t)(i0 + i2) * 8 + b) * 512 + h * 64 + dh;
            *(uint32_t*)&g_aoh[o1] = packh2(o_[n][0] * inv1, o_[n][1] * inv1);
            *(uint32_t*)&g_aoh[o2] = packh2(o_[n][2] * inv2, o_[n][3] * inv2);
        }
    }
}

// ============================================================================
// Output projection fp16: out(4096,512) = g_aoh @ W_out + b_out (fp32 out)
// ============================================================================
__global__ void __launch_bounds__(256, 2)
out_fp16_kernel(const float* __restrict__ bias, float* __restrict__ out) {
    __shared__ uint32_t As[128 * 36];
    __shared__ uint32_t Bs[128 * 36];
    const int m0 = blockIdx.y * 128, n0 = blockIdx.x * 128;
    const int tid = threadIdx.x, lane = tid & 31, wid = tid >> 5;
    const int gi = lane >> 2, ti = lane & 3;
    const int wm = wid >> 2, wn = wid & 3;

    const uint32_t* aw = (const uint32_t*)g_aoh;
    const uint32_t* bw = (const uint32_t*)g_woh;

    float c_[4][4][4] = {};

    for (int k0 = 0; k0 < 8; ++k0) {
#pragma unroll
        for (int rep = 0; rep < 4; ++rep) {
            int s = rep * 256 + tid;
            int row = s >> 3, seg = s & 7;
            *(uint4*)&As[row * 36 + seg * 4] =
                *(const uint4*)&aw[(size_t)(m0 + row) * 256 + k0 * 32 + seg * 4];
        }
#pragma unroll
        for (int rep = 0; rep < 4; ++rep) {
            int s = rep * 256 + tid;
            int row = s >> 3, seg = s & 7;
            *(uint4*)&Bs[row * 36 + seg * 4] =
                *(const uint4*)&bw[(size_t)(n0 + row) * 256 + k0 * 32 + seg * 4];
        }
        __syncthreads();
#pragma unroll
        for (int kb = 0; kb < 4; ++kb) {
            uint32_t a[4][4], bb[4][2];
#pragma unroll
            for (int mt = 0; mt < 4; ++mt) {
                int r = wm * 64 + mt * 16 + gi;
                a[mt][0] = As[r * 36 + kb * 8 + ti];
                a[mt][1] = As[(r + 8) * 36 + kb * 8 + ti];
                a[mt][2] = As[r * 36 + kb * 8 + ti + 4];
                a[mt][3] = As[(r + 8) * 36 + kb * 8 + ti + 4];
            }
#pragma unroll
            for (int nt = 0; nt < 4; ++nt) {
                int ncol = wn * 32 + nt * 8 + gi;
                bb[nt][0] = Bs[ncol * 36 + kb * 8 + ti];
                bb[nt][1] = Bs[ncol * 36 + kb * 8 + ti + 4];
            }
#pragma unroll
            for (int mt = 0; mt < 4; ++mt)
#pragma unroll
                for (int nt = 0; nt < 4; ++nt)
                    mma16(c_[mt][nt], a[mt], bb[nt]);
        }
        __syncthreads();
    }

#pragma unroll
    for (int mt = 0; mt < 4; ++mt) {
        int m = m0 + wm * 64 + mt * 16 + gi;
#pragma unroll
        for (int nt = 0; nt < 4; ++nt) {
            int n = n0 + wn * 32 + nt * 8 + 2 * ti;
            float b0 = bias[n], b1 = bias[n + 1];
            *(float2*)&out[(size_t)m * 512 + n] =
                make_float2(c_[mt][nt][0] + b0, c_[mt][nt][1] + b1);
            *(float2*)&out[(size_t)(m + 8) * 512 + n] =
                make_float2(c_[mt][nt][2] + b0, c_[mt][nt][3] + b1);
        }
    }
}

// ============================================================================
extern "C" void kernel_launch(void* const* d_in, const int* in_sizes, int n_in,
                              void* d_out, int out_size) {
    const float* x     = (const float*)d_in[0];
    const float* Wqkv  = (const float*)d_in[1];
    const float* Wpos  = (const float*)d_in[2];
    const float* pos_u = (const float*)d_in[3];
    const float* pos_v = (const float*)d_in[4];
    const float* Wout  = (const float*)d_in[5];
    const float* bout  = (const float*)d_in[6];
    const float* ltau  = (const float*)d_in[7];
    float* out = (float*)d_out;

    __half *wqh, *wph, *woh;
    cudaGetSymbolAddress((void**)&wqh, g_wqh);
    cudaGetSymbolAddress((void**)&wph, g_wph);
    cudaGetSymbolAddress((void**)&woh, g_woh);

    xhalf_kernel<<<2048, 256>>>(x);
    transpose_half<<<dim3(48, 16), 256>>>(Wqkv, wqh, 512, 1536);
    transpose_half<<<dim3(16, 16), 256>>>(Wpos, wph, 512, 512);
    transpose_half<<<dim3(16, 16), 256>>>(Wout, woh, 512, 512);

    qkv_fp16_kernel<<<dim3(12, 32), 256>>>();
    rpe_fp16_kernel<<<dim3(4, 8), 256>>>();
    uk_kernel<<<512, 256>>>(pos_u);
    vr_kernel<<<128, 256>>>(pos_v);

    const size_t smem = (size_t)(512 * LDE + 2048 + 2 * TFW + 512 + 576 + 512 + 64 + 64) * sizeof(float);
    cudaFuncSetAttribute(attn_fp16_kernel, cudaFuncAttributeMaxDynamicSharedMemorySize, (int)smem);
    attn_fp16_kernel<<<dim3(8, 64), 512, smem>>>(ltau);

    out_fp16_kernel<<<dim3(4, 32), 256>>>(bout, out);
}

// round 9
// speedup vs baseline: 1.4761x; 1.1677x over previous
#include <cuda_runtime.h>
#include <cuda_fp16.h>
#include <math.h>
#include <float.h>
#include <stdint.h>

#define TT   512
#define BB   8
#define DD   512
#define HH   8
#define DHH  64
#define RR   1023
#define BHN  64
#define MROWS 4096

// ---------------- scratch (fp16 payloads) ----------------
__device__ __half g_q[BHN * TT * DHH];      // [b*8+h][t][dh]
__device__ __half g_k[BHN * TT * DHH];
__device__ __half g_vT[BHN * DHH * TT];     // [b*8+h][dh][t]
__device__ __half g_rpe[RR * DD];           // [r][h*64+dh]
__device__ __half g_xh[MROWS * DD];
__device__ __half g_wqh[1536 * 512];        // W_qkv^T [n][k]
__device__ __half g_wph[512 * 512];         // W_pos^T [n][k]
__device__ __half g_woh[512 * 512];         // W_out^T [n][k]
__device__ __half g_aoh[MROWS * DD];        // attention out (t,b,d), half
__device__ float  g_uk[BHN * TT];
__device__ float  g_vr[RR * HH];

__device__ __forceinline__ void mma16(float* c, const uint32_t* a, const uint32_t* b) {
    asm volatile(
        "mma.sync.aligned.m16n8k16.row.col.f32.f16.f16.f32 "
        "{%0,%1,%2,%3},{%4,%5,%6,%7},{%8,%9},{%0,%1,%2,%3};"
        : "+f"(c[0]), "+f"(c[1]), "+f"(c[2]), "+f"(c[3])
        : "r"(a[0]), "r"(a[1]), "r"(a[2]), "r"(a[3]), "r"(b[0]), "r"(b[1]));
}

__device__ __forceinline__ uint32_t packh2(float lo, float hi) {
    __half2 h = __floats2half2_rn(lo, hi);
    return *(uint32_t*)&h;
}

// ============================================================================
// PREP (fused): blocks [0,2048) xhalf; [2048,2816) Wqkv^T; [2816,3072) Wpos^T;
// [3072,3328) Wout^T.
// ============================================================================
__global__ void __launch_bounds__(256)
prep_kernel(const float* __restrict__ x, const float* __restrict__ Wqkv,
            const float* __restrict__ Wpos, const float* __restrict__ Wout) {
    __shared__ float t[32][33];
    int bid = blockIdx.x, tid = threadIdx.x;

    if (bid < 2048) {
        int i = bid * 256 + tid;
        float4 v = *(const float4*)&x[(size_t)i * 4];
        *(uint32_t*)&g_xh[(size_t)i * 4]     = packh2(v.x, v.y);
        *(uint32_t*)&g_xh[(size_t)i * 4 + 2] = packh2(v.z, v.w);
        return;
    }

    const float* src; __half* dst; int N, bx, by;
    if (bid < 2816)      { int b = bid - 2048; src = Wqkv; dst = g_wqh; N = 1536; bx = b % 48, by = b / 48; }
    else if (bid < 3072) { int b = bid - 2816; src = Wpos; dst = g_wph; N = 512;  bx = b % 16, by = b / 16; }
    else                 { int b = bid - 3072; src = Wout; dst = g_woh; N = 512;  bx = b % 16, by = b / 16; }

    int n0 = bx * 32, k0 = by * 32;
    int tx = tid & 31, ty = tid >> 5;
    for (int r = ty; r < 32; r += 8)
        t[r][tx] = src[(size_t)(k0 + r) * N + n0 + tx];
    __syncthreads();
    for (int r = ty; r < 32; r += 8)
        dst[(size_t)(n0 + r) * 512 + k0 + tx] = __float2half(t[tx][r]);
}

// ============================================================================
// FUSED GEMM: blocks [0,768) = QKV (m 32 x n 24 tiles), [768,832) = rpe (8x8).
// 128x64 tile, BK=64 halves, 256 thr (8 warps 4x2), warp 32x32. occ 3.
// ============================================================================
__global__ void __launch_bounds__(256, 3)
gemm_fused_kernel() {
    __shared__ uint32_t As[128 * 36];
    __shared__ uint32_t Bs[64 * 36];
    __shared__ float freqs[512];
    const int bid = blockIdx.x, tid = threadIdx.x;
    const int lane = tid & 31, wid = tid >> 5;
    const int gi = lane >> 2, ti = lane & 3;
    const int wm = wid >> 1, wn = wid & 1;

    const bool is_rpe = (bid >= 768);
    int m0, n0;
    const uint32_t *aw = 0, *bw;
    if (!is_rpe) {
        m0 = (bid / 24) * 128; n0 = (bid % 24) * 64;
        aw = (const uint32_t*)g_xh; bw = (const uint32_t*)g_wqh;
    } else {
        int b = bid - 768;
        m0 = (b / 8) * 128; n0 = (b % 8) * 64;
        bw = (const uint32_t*)g_wph;
        for (int s = tid; s < 512; s += 256) {
            int cc = s & 255;
            freqs[s] = __expf(-9.210340371976184f * (float)cc * (1.0f / 256.0f));
        }
        __syncthreads();
    }

    float c_[2][4][4] = {};

    for (int k0 = 0; k0 < 8; ++k0) {
        if (!is_rpe) {
#pragma unroll
            for (int rep = 0; rep < 4; ++rep) {
                int s = rep * 256 + tid;            // 1024 uint4
                int row = s >> 3, seg = s & 7;
                *(uint4*)&As[row * 36 + seg * 4] =
                    *(const uint4*)&aw[(size_t)(m0 + row) * 256 + k0 * 32 + seg * 4];
            }
        } else {
#pragma unroll
            for (int rep = 0; rep < 16; ++rep) {
                int s = rep * 256 + tid;            // 4096 words
                int row = s >> 5, w = s & 31;
                int kg = k0 * 64 + 2 * w;
                float rel = (float)(m0 + row - 511);
                float a0 = rel * freqs[kg], a1 = rel * freqs[kg + 1];
                float f0 = (kg < 256) ? sinf(a0) : cosf(a0);
                float f1 = (kg + 1 < 256) ? sinf(a1) : cosf(a1);
                As[row * 36 + w] = packh2(f0, f1);
            }
        }
#pragma unroll
        for (int rep = 0; rep < 2; ++rep) {
            int s = rep * 256 + tid;                // 512 uint4
            int row = s >> 3, seg = s & 7;
            *(uint4*)&Bs[row * 36 + seg * 4] =
                *(const uint4*)&bw[(size_t)(n0 + row) * 256 + k0 * 32 + seg * 4];
        }
        __syncthreads();
#pragma unroll
        for (int kb = 0; kb < 4; ++kb) {
            uint32_t a[2][4], bb[4][2];
#pragma unroll
            for (int mt = 0; mt < 2; ++mt) {
                int r = wm * 32 + mt * 16 + gi;
                a[mt][0] = As[r * 36 + kb * 8 + ti];
                a[mt][1] = As[(r + 8) * 36 + kb * 8 + ti];
                a[mt][2] = As[r * 36 + kb * 8 + ti + 4];
                a[mt][3] = As[(r + 8) * 36 + kb * 8 + ti + 4];
            }
#pragma unroll
            for (int nt = 0; nt < 4; ++nt) {
                int ncol = wn * 32 + nt * 8 + gi;
                bb[nt][0] = Bs[ncol * 36 + kb * 8 + ti];
                bb[nt][1] = Bs[ncol * 36 + kb * 8 + ti + 4];
            }
#pragma unroll
            for (int mt = 0; mt < 2; ++mt)
#pragma unroll
                for (int nt = 0; nt < 4; ++nt)
                    mma16(c_[mt][nt], a[mt], bb[nt]);
        }
        __syncthreads();
    }

    if (!is_rpe) {
#pragma unroll
        for (int mt = 0; mt < 2; ++mt) {
            int m = m0 + wm * 32 + mt * 16 + gi;
#pragma unroll
            for (int nt = 0; nt < 4; ++nt) {
                int n = n0 + wn * 32 + nt * 8 + 2 * ti;
                int part = n >> 9, hh = (n >> 6) & 7, dh = n & 63;
#pragma unroll
                for (int half = 0; half < 2; ++half) {
                    int mm = m + half * 8;
                    float v0 = c_[mt][nt][half * 2], v1 = c_[mt][nt][half * 2 + 1];
                    int tr = mm >> 3, bi = mm & 7;
                    int bh = bi * 8 + hh;
                    if (part == 2) {
                        g_vT[((size_t)bh * 64 + dh) * 512 + tr]     = __float2half(v0);
                        g_vT[((size_t)bh * 64 + dh + 1) * 512 + tr] = __float2half(v1);
                    } else {
                        __half* dst = (part == 0) ? g_q : g_k;
                        *(uint32_t*)&dst[((size_t)bh * 512 + tr) * 64 + dh] = packh2(v0, v1);
                    }
                }
            }
        }
    } else {
#pragma unroll
        for (int mt = 0; mt < 2; ++mt) {
            int m = m0 + wm * 32 + mt * 16 + gi;
#pragma unroll
            for (int nt = 0; nt < 4; ++nt) {
                int n = n0 + wn * 32 + nt * 8 + 2 * ti;
                if (m < RR)
                    *(uint32_t*)&g_rpe[(size_t)m * 512 + n] = packh2(c_[mt][nt][0], c_[mt][nt][1]);
                if (m + 8 < RR)
                    *(uint32_t*)&g_rpe[(size_t)(m + 8) * 512 + n] = packh2(c_[mt][nt][2], c_[mt][nt][3]);
            }
        }
    }
}

// ============================================================================
// BIAS (fused): blocks [0,512) uk, [512,640) vr
// ============================================================================
__global__ void __launch_bounds__(256)
bias_kernel(const float* __restrict__ pos_u, const float* __restrict__ pos_v) {
    int bid = blockIdx.x, tid = threadIdx.x;
    if (bid < 512) {
        int gid = bid * 256 + tid;
        int id = gid >> 2, part = gid & 3;
        int h = (id >> 9) & 7;
        const __half2* kp = (const __half2*)(g_k + (size_t)id * 64) + part * 8;
        const float* up = pos_u + h * 64 + part * 16;
        float acc = 0.f;
#pragma unroll
        for (int s = 0; s < 8; ++s) {
            float2 kf = __half22float2(kp[s]);
            acc += kf.x * up[2 * s] + kf.y * up[2 * s + 1];
        }
        acc += __shfl_xor_sync(0xffffffffu, acc, 1);
        acc += __shfl_xor_sync(0xffffffffu, acc, 2);
        if (part == 0) g_uk[id] = acc;
    } else {
        int gid = (bid - 512) * 256 + tid;
        int id = gid >> 2, part = gid & 3;
        if (id >= RR * HH) return;
        int r = id >> 3, h = id & 7;
        const __half2* rp = (const __half2*)(g_rpe + (size_t)r * 512 + h * 64) + part * 8;
        const float* vp = pos_v + h * 64 + part * 16;
        float acc = 0.f;
#pragma unroll
        for (int s = 0; s < 8; ++s) {
            float2 rf = __half22float2(rp[s]);
            acc += rf.x * vp[2 * s] + rf.y * vp[2 * s + 1];
        }
        acc += __shfl_xor_sync(0xffffffffu, acc, 1);
        acc += __shfl_xor_sync(0xffffffffu, acc, 2);
        if (part == 0) g_vr[id] = acc;
    }
}

// ============================================================================
// Fused attention fp16 (unchanged from R8)
// ============================================================================
#define LDE 68
#define CH  128
#define TFW 4608

__device__ __forceinline__ void ldg_A_k(uint32_t* r, const uint32_t* src,
                                        int wid, int gg, int tt) {
#pragma unroll
    for (int k = 0; k < 2; ++k) {
        int c = wid + (k << 4);
        int mt = c >> 2, ks = c & 3;
#pragma unroll
        for (int aidx = 0; aidx < 4; ++aidx) {
            int row = mt * 16 + (aidx & 1) * 8 + gg;
            int col = ks * 8 + (aidx >> 1) * 4 + tt;
            r[k * 4 + aidx] = src[(size_t)row * 32 + col];
        }
    }
}

__device__ __forceinline__ void ldg_A_rpe(uint32_t* r, const uint32_t* rc,
                                          int ubase, int wid, int gg, int tt) {
#pragma unroll
    for (int k = 0; k < 2; ++k) {
        int c = wid + (k << 4);
        int mt = c >> 2, ks = c & 3;
#pragma unroll
        for (int aidx = 0; aidx < 4; ++aidx) {
            int row = mt * 16 + (aidx & 1) * 8 + gg;
            int col = ks * 8 + (aidx >> 1) * 4 + tt;
            int u = ubase + row;
            r[k * 4 + aidx] = (u < RR) ? rc[(size_t)u * 256 + col] : 0u;
        }
    }
}

__device__ __forceinline__ void sts_A(uint32_t* buf, const uint32_t* r,
                                      int wid, int lane) {
#pragma unroll
    for (int k = 0; k < 2; ++k) {
        int c = wid + (k << 4);
        *(uint4*)&buf[(c * 32 + lane) * 4] =
            make_uint4(r[k * 4], r[k * 4 + 1], r[k * 4 + 2], r[k * 4 + 3]);
    }
}

__device__ __forceinline__ void ldg_B_v(uint32_t* r, const uint32_t* src, int tid) {
#pragma unroll
    for (int k = 0; k < 8; ++k) {
        int idx = k * 512 + tid;
        int dh = idx >> 6, w = idx & 63;
        r[k] = src[(size_t)dh * 256 + w];
    }
}

__device__ __forceinline__ void sts_B(uint32_t* buf, const uint32_t* r, int tid) {
#pragma unroll
    for (int k = 0; k < 8; ++k) {
        int idx = k * 512 + tid;
        int dh = idx >> 6, w = idx & 63;
        buf[dh * 68 + w] = r[k];
    }
}

__global__ void __launch_bounds__(512, 1)
attn_fp16_kernel(const float* __restrict__ tau_ptr) {
    extern __shared__ float sm[];
    float*    e_s = sm;
    uint32_t* Qf  = (uint32_t*)(e_s + 512 * LDE);
    uint32_t* Tf0 = Qf + 2048;
    uint32_t* Tf1 = Tf0 + TFW;
    float* uks  = (float*)(Tf1 + TFW);
    float* vrs  = uks + 512;
    float* red  = vrs + 576;
    float* rowm = red + 512;
    float* rowl = rowm + 64;
    uint32_t* Tf[2] = {Tf0, Tf1};

    const int bh = blockIdx.y, h = bh & 7, b = bh >> 3;
    const int i0 = blockIdx.x * 64;
    const int tid = threadIdx.x, lane = tid & 31, wid = tid >> 5;
    const int gi = lane >> 2, ti = lane & 3;
    const int wm = wid >> 1, wn = wid & 1;

    const uint32_t* kbase = (const uint32_t*)g_k + (size_t)bh * TT * 32;
    const uint32_t* vTbase = (const uint32_t*)g_vT + (size_t)bh * 64 * 256;
    const uint32_t* rc = (const uint32_t*)g_rpe + h * 32;

    uint32_t r[8];

    ldg_A_k(r, kbase, wid, gi, ti);
    {
        const uint32_t* qg = (const uint32_t*)g_q + ((size_t)bh * TT + i0) * 32;
        for (int s = tid; s < 2048; s += 512) {
            int bidx = s & 1, l = (s >> 1) & 31, ks = (s >> 6) & 3, nt = s >> 8;
            int gg2 = l >> 2, tt2 = l & 3;
            int ii = nt * 8 + gg2;
            int dhw = ks * 8 + bidx * 4 + tt2;
            Qf[s] = qg[ii * 32 + dhw];
        }
        uks[tid] = g_uk[bh * 512 + tid];
        for (int s = tid; s < 576; s += 512) {
            int u = i0 + s;
            vrs[s] = (u < RR) ? g_vr[u * 8 + h] : 0.f;
        }
    }
    sts_A(Tf[0], r, wid, lane);
    __syncthreads();

#pragma unroll
    for (int jc = 0; jc < 4; ++jc) {
        if (jc < 3) ldg_A_k(r, kbase + (size_t)(jc + 1) * CH * 32, wid, gi, ti);
        else        ldg_A_rpe(r, rc, i0, wid, gi, ti);

        float c_[4][4] = {};
        const uint32_t* cur = Tf[jc & 1];
#pragma unroll
        for (int ks = 0; ks < 4; ++ks) {
            uint4 av = *(const uint4*)&cur[((wm * 4 + ks) * 32 + lane) * 4];
            uint32_t a[4] = {av.x, av.y, av.z, av.w};
#pragma unroll
            for (int n = 0; n < 4; ++n) {
                int nt = wn * 4 + n;
                uint2 bv = *(const uint2*)&Qf[((nt * 4 + ks) * 32 + lane) * 2];
                uint32_t bb[2] = {bv.x, bv.y};
                mma16(c_[n], a, bb);
            }
        }
        int j = jc * CH + wm * 16 + gi;
#pragma unroll
        for (int n = 0; n < 4; ++n) {
            int ii = wn * 32 + n * 8 + 2 * ti;
            *(float2*)&e_s[j * LDE + ii]       = make_float2(c_[n][0], c_[n][1]);
            *(float2*)&e_s[(j + 8) * LDE + ii] = make_float2(c_[n][2], c_[n][3]);
        }
        sts_A(Tf[(jc + 1) & 1], r, wid, lane);
        __syncthreads();
    }

#pragma unroll
    for (int ch = 0; ch < 5; ++ch) {
        if (ch < 4) ldg_A_rpe(r, rc, i0 + (ch + 1) * CH, wid, gi, ti);
        else        ldg_B_v(r, vTbase, tid);

        if (!(ch == 4 && wm >= 4)) {
            float c_[4][4] = {};
            const uint32_t* cur = Tf[ch & 1];
#pragma unroll
            for (int ks = 0; ks < 4; ++ks) {
                uint4 av = *(const uint4*)&cur[((wm * 4 + ks) * 32 + lane) * 4];
                uint32_t a[4] = {av.x, av.y, av.z, av.w};
#pragma unroll
                for (int n = 0; n < 4; ++n) {
                    int nt = wn * 4 + n;
                    uint2 bv = *(const uint2*)&Qf[((nt * 4 + ks) * 32 + lane) * 2];
                    uint32_t bb[2] = {bv.x, bv.y};
                    mma16(c_[n], a, bb);
                }
            }
            int uloc = ch * CH + wm * 16 + gi;
#pragma unroll
            for (int n = 0; n < 4; ++n) {
                int ii = wn * 32 + n * 8 + 2 * ti;
                int j0 = ii - uloc + 511;
                int j1 = j0 + 1;
                int j2 = j0 - 8;
                int j3 = j1 - 8;
                if ((unsigned)j0 < 512u) e_s[j0 * LDE + ii]     += c_[n][0];
                if ((unsigned)j1 < 512u) e_s[j1 * LDE + ii + 1] += c_[n][1];
                if ((unsigned)j2 < 512u) e_s[j2 * LDE + ii]     += c_[n][2];
                if ((unsigned)j3 < 512u) e_s[j3 * LDE + ii + 1] += c_[n][3];
            }
        }
        if (ch < 4) sts_A(Tf[(ch + 1) & 1], r, wid, lane);
        else        sts_B(Tf[1], r, tid);
        __syncthreads();
    }

    {
        const float scale = 0.125f;
        const float tauf = expf(tau_ptr[0]);
        int col = tid & 63, seg = tid >> 6;
        int ig = i0 + col;
        float mloc = -FLT_MAX;
        for (int jj = 0; jj < 64; ++jj) {
            int j = seg * 64 + jj;
            float val = e_s[j * LDE + col];
            val = (val + uks[j] + vrs[col - j + 511]) * scale;
            if (j == ig) val = -FLT_MAX;
            val *= tauf;
            e_s[j * LDE + col] = val;
            mloc = fmaxf(mloc, val);
        }
        red[seg * 64 + col] = mloc;
        __syncthreads();
        if (tid < 64) {
            float m = red[tid];
#pragma unroll
            for (int s = 1; s < 8; ++s) m = fmaxf(m, red[s * 64 + tid]);
            rowm[tid] = m;
        }
        __syncthreads();
        float m = rowm[col];
        float sloc = 0.f;
        for (int jj = 0; jj < 64; ++jj) {
            int j = seg * 64 + jj;
            float p = __expf(e_s[j * LDE + col] - m);
            e_s[j * LDE + col] = p;
            sloc += p;
        }
        red[seg * 64 + col] = sloc;
        __syncthreads();
        if (tid < 64) {
            float s = 0.f;
#pragma unroll
            for (int ss = 0; ss < 8; ++ss) s += red[ss * 64 + tid];
            rowl[tid] = s;
        }
        __syncthreads();
    }

    float o_[2][4] = {};
    const int pwm = wid >> 2;
    const int pwn = wid & 3;
#pragma unroll
    for (int jc = 0; jc < 4; ++jc) {
        if (jc < 3) ldg_B_v(r, vTbase + (size_t)(jc + 1) * 64, tid);

        const uint32_t* cur = Tf[(jc ^ 1) & 1];
        int ibase = pwm * 16 + gi;
#pragma unroll
        for (int ks = 0; ks < 8; ++ks) {
            int jb = jc * CH + ks * 16;
            uint32_t a[4];
            {
                int je = jb + 2 * ti;
                float p00 = e_s[je * LDE + ibase],       p01 = e_s[(je + 1) * LDE + ibase];
                float p10 = e_s[je * LDE + ibase + 8],   p11 = e_s[(je + 1) * LDE + ibase + 8];
                float p20 = e_s[(je + 8) * LDE + ibase],     p21 = e_s[(je + 9) * LDE + ibase];
                float p30 = e_s[(je + 8) * LDE + ibase + 8], p31 = e_s[(je + 9) * LDE + ibase + 8];
                a[0] = packh2(p00, p01);
                a[1] = packh2(p10, p11);
                a[2] = packh2(p20, p21);
                a[3] = packh2(p30, p31);
            }
#pragma unroll
            for (int n = 0; n < 2; ++n) {
                int ncol = pwn * 16 + n * 8 + gi;
                uint32_t bb[2];
                bb[0] = cur[ncol * 68 + ks * 8 + ti];
                bb[1] = cur[ncol * 68 + ks * 8 + ti + 4];
                mma16(o_[n], a, bb);
            }
        }
        if (jc < 3) sts_B(Tf[jc & 1], r, tid);
        __syncthreads();
    }

    {
        int i1 = pwm * 16 + gi, i2 = i1 + 8;
        float inv1 = 1.f / rowl[i1];
        float inv2 = 1.f / rowl[i2];
#pragma unroll
        for (int n = 0; n < 2; ++n) {
            int dh = pwn * 16 + n * 8 + 2 * ti;
            size_t o1 = ((size_t)(i0 + i1) * 8 + b) * 512 + h * 64 + dh;
            size_t o2 = ((size_t)(i0 + i2) * 8 + b) * 512 + h * 64 + dh;
            *(uint32_t*)&g_aoh[o1] = packh2(o_[n][0] * inv1, o_[n][1] * inv1);
            *(uint32_t*)&g_aoh[o2] = packh2(o_[n][2] * inv2, o_[n][3] * inv2);
        }
    }
}

// ============================================================================
// Output projection: 128x64 tile, occ 3. out = g_aoh @ W_out + b_out
// ============================================================================
__global__ void __launch_bounds__(256, 3)
out_fp16_kernel(const float* __restrict__ bias, float* __restrict__ out) {
    __shared__ uint32_t As[128 * 36];
    __shared__ uint32_t Bs[64 * 36];
    const int bid = blockIdx.x, tid = threadIdx.x;
    const int m0 = (bid / 8) * 128, n0 = (bid % 8) * 64;
    const int lane = tid & 31, wid = tid >> 5;
    const int gi = lane >> 2, ti = lane & 3;
    const int wm = wid >> 1, wn = wid & 1;

    const uint32_t* aw = (const uint32_t*)g_aoh;
    const uint32_t* bw = (const uint32_t*)g_woh;

    float c_[2][4][4] = {};

    for (int k0 = 0; k0 < 8; ++k0) {
#pragma unroll
        for (int rep = 0; rep < 4; ++rep) {
            int s = rep * 256 + tid;
            int row = s >> 3, seg = s & 7;
            *(uint4*)&As[row * 36 + seg * 4] =
                *(const uint4*)&aw[(size_t)(m0 + row) * 256 + k0 * 32 + seg * 4];
        }
#pragma unroll
        for (int rep = 0; rep < 2; ++rep) {
            int s = rep * 256 + tid;
            int row = s >> 3, seg = s & 7;
            *(uint4*)&Bs[row * 36 + seg * 4] =
                *(const uint4*)&bw[(size_t)(n0 + row) * 256 + k0 * 32 + seg * 4];
        }
        __syncthreads();
#pragma unroll
        for (int kb = 0; kb < 4; ++kb) {
            uint32_t a[2][4], bb[4][2];
#pragma unroll
            for (int mt = 0; mt < 2; ++mt) {
                int r = wm * 32 + mt * 16 + gi;
                a[mt][0] = As[r * 36 + kb * 8 + ti];
                a[mt][1] = As[(r + 8) * 36 + kb * 8 + ti];
                a[mt][2] = As[r * 36 + kb * 8 + ti + 4];
                a[mt][3] = As[(r + 8) * 36 + kb * 8 + ti + 4];
            }
#pragma unroll
            for (int nt = 0; nt < 4; ++nt) {
                int ncol = wn * 32 + nt * 8 + gi;
                bb[nt][0] = Bs[ncol * 36 + kb * 8 + ti];
                bb[nt][1] = Bs[ncol * 36 + kb * 8 + ti + 4];
            }
#pragma unroll
            for (int mt = 0; mt < 2; ++mt)
#pragma unroll
                for (int nt = 0; nt < 4; ++nt)
                    mma16(c_[mt][nt], a[mt], bb[nt]);
        }
        __syncthreads();
    }

#pragma unroll
    for (int mt = 0; mt < 2; ++mt) {
        int m = m0 + wm * 32 + mt * 16 + gi;
#pragma unroll
        for (int nt = 0; nt < 4; ++nt) {
            int n = n0 + wn * 32 + nt * 8 + 2 * ti;
            float b0 = bias[n], b1 = bias[n + 1];
            *(float2*)&out[(size_t)m * 512 + n] =
                make_float2(c_[mt][nt][0] + b0, c_[mt][nt][1] + b1);
            *(float2*)&out[(size_t)(m + 8) * 512 + n] =
                make_float2(c_[mt][nt][2] + b0, c_[mt][nt][3] + b1);
        }
    }
}

// ============================================================================
extern "C" void kernel_launch(void* const* d_in, const int* in_sizes, int n_in,
                              void* d_out, int out_size) {
    const float* x     = (const float*)d_in[0];
    const float* Wqkv  = (const float*)d_in[1];
    const float* Wpos  = (const float*)d_in[2];
    const float* pos_u = (const float*)d_in[3];
    const float* pos_v = (const float*)d_in[4];
    const float* Wout  = (const float*)d_in[5];
    const float* bout  = (const float*)d_in[6];
    const float* ltau  = (const float*)d_in[7];
    float* out = (float*)d_out;

    prep_kernel<<<3328, 256>>>(x, Wqkv, Wpos, Wout);
    gemm_fused_kernel<<<832, 256>>>();
    bias_kernel<<<640, 256>>>(pos_u, pos_v);

    const size_t smem = (size_t)(512 * LDE + 2048 + 2 * TFW + 512 + 576 + 512 + 64 + 64) * sizeof(float);
    cudaFuncSetAttribute(attn_fp16_kernel, cudaFuncAttributeMaxDynamicSharedMemorySize, (int)smem);
    attn_fp16_kernel<<<dim3(8, 64), 512, smem>>>(ltau);

    out_fp16_kernel<<<256, 256>>>(bout, out);
}

// round 10
// speedup vs baseline: 1.5665x; 1.0613x over previous
#include <cuda_runtime.h>
#include <cuda_fp16.h>
#include <math.h>
#include <float.h>
#include <stdint.h>

#define TT   512
#define BB   8
#define DD   512
#define HH   8
#define DHH  64
#define RR   1023
#define BHN  64
#define MROWS 4096

// ---------------- scratch (fp16 payloads) ----------------
__device__ __half g_q[BHN * TT * DHH];      // [b*8+h][t][dh]
__device__ __half g_k[BHN * TT * DHH];
__device__ __half g_vT[BHN * DHH * TT];     // [b*8+h][dh][t]
__device__ __half g_rpe[RR * DD];           // [r][h*64+dh]
__device__ __half g_xh[MROWS * DD];
__device__ __half g_wqh[1536 * 512];        // W_qkv^T [n][k]
__device__ __half g_wph[512 * 512];         // W_pos^T [n][k]
__device__ __half g_woh[512 * 512];         // W_out^T [n][k]
__device__ __half g_aoh[MROWS * DD];        // attention out (t,b,d), half
__device__ float  g_uk[BHN * TT];
__device__ float  g_vr[RR * HH];

__device__ __forceinline__ void mma16(float* c, const uint32_t* a, const uint32_t* b) {
    asm volatile(
        "mma.sync.aligned.m16n8k16.row.col.f32.f16.f16.f32 "
        "{%0,%1,%2,%3},{%4,%5,%6,%7},{%8,%9},{%0,%1,%2,%3};"
        : "+f"(c[0]), "+f"(c[1]), "+f"(c[2]), "+f"(c[3])
        : "r"(a[0]), "r"(a[1]), "r"(a[2]), "r"(a[3]), "r"(b[0]), "r"(b[1]));
}

__device__ __forceinline__ uint32_t packh2(float lo, float hi) {
    __half2 h = __floats2half2_rn(lo, hi);
    return *(uint32_t*)&h;
}

__device__ __forceinline__ uint32_t smem_u32(const void* p) {
    uint32_t a;
    asm("{ .reg .u64 t; cvta.to.shared.u64 t, %1; cvt.u32.u64 %0, t; }" : "=r"(a) : "l"(p));
    return a;
}

// ============================================================================
// PREP (fused): blocks [0,2048) xhalf; [2048,2816) Wqkv^T; [2816,3072) Wpos^T;
// [3072,3328) Wout^T.
// ============================================================================
__global__ void __launch_bounds__(256)
prep_kernel(const float* __restrict__ x, const float* __restrict__ Wqkv,
            const float* __restrict__ Wpos, const float* __restrict__ Wout) {
    __shared__ float t[32][33];
    int bid = blockIdx.x, tid = threadIdx.x;

    if (bid < 2048) {
        int i = bid * 256 + tid;
        float4 v = *(const float4*)&x[(size_t)i * 4];
        *(uint32_t*)&g_xh[(size_t)i * 4]     = packh2(v.x, v.y);
        *(uint32_t*)&g_xh[(size_t)i * 4 + 2] = packh2(v.z, v.w);
        return;
    }

    const float* src; __half* dst; int N, bx, by;
    if (bid < 2816)      { int b = bid - 2048; src = Wqkv; dst = g_wqh; N = 1536; bx = b % 48, by = b / 48; }
    else if (bid < 3072) { int b = bid - 2816; src = Wpos; dst = g_wph; N = 512;  bx = b % 16, by = b / 16; }
    else                 { int b = bid - 3072; src = Wout; dst = g_woh; N = 512;  bx = b % 16, by = b / 16; }

    int n0 = bx * 32, k0 = by * 32;
    int tx = tid & 31, ty = tid >> 5;
    for (int r = ty; r < 32; r += 8)
        t[r][tx] = src[(size_t)(k0 + r) * N + n0 + tx];
    __syncthreads();
    for (int r = ty; r < 32; r += 8)
        dst[(size_t)(n0 + r) * 512 + k0 + tx] = __float2half(t[tx][r]);
}

// ============================================================================
// FUSED GEMM: blocks [0,768) = QKV, [768,832) = rpe. 128x64 tile, occ 3.
// ============================================================================
__global__ void __launch_bounds__(256, 3)
gemm_fused_kernel() {
    __shared__ uint32_t As[128 * 36];
    __shared__ uint32_t Bs[64 * 36];
    __shared__ float freqs[512];
    const int bid = blockIdx.x, tid = threadIdx.x;
    const int lane = tid & 31, wid = tid >> 5;
    const int gi = lane >> 2, ti = lane & 3;
    const int wm = wid >> 1, wn = wid & 1;

    const bool is_rpe = (bid >= 768);
    int m0, n0;
    const uint32_t *aw = 0, *bw;
    if (!is_rpe) {
        m0 = (bid / 24) * 128; n0 = (bid % 24) * 64;
        aw = (const uint32_t*)g_xh; bw = (const uint32_t*)g_wqh;
    } else {
        int b = bid - 768;
        m0 = (b / 8) * 128; n0 = (b % 8) * 64;
        bw = (const uint32_t*)g_wph;
        for (int s = tid; s < 512; s += 256) {
            int cc = s & 255;
            freqs[s] = __expf(-9.210340371976184f * (float)cc * (1.0f / 256.0f));
        }
        __syncthreads();
    }

    float c_[2][4][4] = {};

    for (int k0 = 0; k0 < 8; ++k0) {
        if (!is_rpe) {
#pragma unroll
            for (int rep = 0; rep < 4; ++rep) {
                int s = rep * 256 + tid;
                int row = s >> 3, seg = s & 7;
                *(uint4*)&As[row * 36 + seg * 4] =
                    *(const uint4*)&aw[(size_t)(m0 + row) * 256 + k0 * 32 + seg * 4];
            }
        } else {
#pragma unroll
            for (int rep = 0; rep < 16; ++rep) {
                int s = rep * 256 + tid;
                int row = s >> 5, w = s & 31;
                int kg = k0 * 64 + 2 * w;
                float rel = (float)(m0 + row - 511);
                float a0 = rel * freqs[kg], a1 = rel * freqs[kg + 1];
                float f0 = (kg < 256) ? sinf(a0) : cosf(a0);
                float f1 = (kg + 1 < 256) ? sinf(a1) : cosf(a1);
                As[row * 36 + w] = packh2(f0, f1);
            }
        }
#pragma unroll
        for (int rep = 0; rep < 2; ++rep) {
            int s = rep * 256 + tid;
            int row = s >> 3, seg = s & 7;
            *(uint4*)&Bs[row * 36 + seg * 4] =
                *(const uint4*)&bw[(size_t)(n0 + row) * 256 + k0 * 32 + seg * 4];
        }
        __syncthreads();
#pragma unroll
        for (int kb = 0; kb < 4; ++kb) {
            uint32_t a[2][4], bb[4][2];
#pragma unroll
            for (int mt = 0; mt < 2; ++mt) {
                int r = wm * 32 + mt * 16 + gi;
                a[mt][0] = As[r * 36 + kb * 8 + ti];
                a[mt][1] = As[(r + 8) * 36 + kb * 8 + ti];
                a[mt][2] = As[r * 36 + kb * 8 + ti + 4];
                a[mt][3] = As[(r + 8) * 36 + kb * 8 + ti + 4];
            }
#pragma unroll
            for (int nt = 0; nt < 4; ++nt) {
                int ncol = wn * 32 + nt * 8 + gi;
                bb[nt][0] = Bs[ncol * 36 + kb * 8 + ti];
                bb[nt][1] = Bs[ncol * 36 + kb * 8 + ti + 4];
            }
#pragma unroll
            for (int mt = 0; mt < 2; ++mt)
#pragma unroll
                for (int nt = 0; nt < 4; ++nt)
                    mma16(c_[mt][nt], a[mt], bb[nt]);
        }
        __syncthreads();
    }

    if (!is_rpe) {
#pragma unroll
        for (int mt = 0; mt < 2; ++mt) {
            int m = m0 + wm * 32 + mt * 16 + gi;
#pragma unroll
            for (int nt = 0; nt < 4; ++nt) {
                int n = n0 + wn * 32 + nt * 8 + 2 * ti;
                int part = n >> 9, hh = (n >> 6) & 7, dh = n & 63;
#pragma unroll
                for (int half = 0; half < 2; ++half) {
                    int mm = m + half * 8;
                    float v0 = c_[mt][nt][half * 2], v1 = c_[mt][nt][half * 2 + 1];
                    int tr = mm >> 3, bi = mm & 7;
                    int bh = bi * 8 + hh;
                    if (part == 2) {
                        g_vT[((size_t)bh * 64 + dh) * 512 + tr]     = __float2half(v0);
                        g_vT[((size_t)bh * 64 + dh + 1) * 512 + tr] = __float2half(v1);
                    } else {
                        __half* dst = (part == 0) ? g_q : g_k;
                        *(uint32_t*)&dst[((size_t)bh * 512 + tr) * 64 + dh] = packh2(v0, v1);
                    }
                }
            }
        }
    } else {
#pragma unroll
        for (int mt = 0; mt < 2; ++mt) {
            int m = m0 + wm * 32 + mt * 16 + gi;
#pragma unroll
            for (int nt = 0; nt < 4; ++nt) {
                int n = n0 + wn * 32 + nt * 8 + 2 * ti;
                if (m < RR)
                    *(uint32_t*)&g_rpe[(size_t)m * 512 + n] = packh2(c_[mt][nt][0], c_[mt][nt][1]);
                if (m + 8 < RR)
                    *(uint32_t*)&g_rpe[(size_t)(m + 8) * 512 + n] = packh2(c_[mt][nt][2], c_[mt][nt][3]);
            }
        }
    }
}

// ============================================================================
// BIAS (fused): blocks [0,512) uk, [512,640) vr
// ============================================================================
__global__ void __launch_bounds__(256)
bias_kernel(const float* __restrict__ pos_u, const float* __restrict__ pos_v) {
    int bid = blockIdx.x, tid = threadIdx.x;
    if (bid < 512) {
        int gid = bid * 256 + tid;
        int id = gid >> 2, part = gid & 3;
        int h = (id >> 9) & 7;
        const __half2* kp = (const __half2*)(g_k + (size_t)id * 64) + part * 8;
        const float* up = pos_u + h * 64 + part * 16;
        float acc = 0.f;
#pragma unroll
        for (int s = 0; s < 8; ++s) {
            float2 kf = __half22float2(kp[s]);
            acc += kf.x * up[2 * s] + kf.y * up[2 * s + 1];
        }
        acc += __shfl_xor_sync(0xffffffffu, acc, 1);
        acc += __shfl_xor_sync(0xffffffffu, acc, 2);
        if (part == 0) g_uk[id] = acc;
    } else {
        int gid = (bid - 512) * 256 + tid;
        int id = gid >> 2, part = gid & 3;
        if (id >= RR * HH) return;
        int r = id >> 3, h = id & 7;
        const __half2* rp = (const __half2*)(g_rpe + (size_t)r * 512 + h * 64) + part * 8;
        const float* vp = pos_v + h * 64 + part * 16;
        float acc = 0.f;
#pragma unroll
        for (int s = 0; s < 8; ++s) {
            float2 rf = __half22float2(rp[s]);
            acc += rf.x * vp[2 * s] + rf.y * vp[2 * s + 1];
        }
        acc += __shfl_xor_sync(0xffffffffu, acc, 1);
        acc += __shfl_xor_sync(0xffffffffu, acc, 2);
        if (part == 0) g_vr[id] = acc;
    }
}

// ============================================================================
// Fused attention fp16, low-smem-traffic version.
// e_h: fp16 energy/P buffer [512 j][36 words] (in-place E -> P).
// bdt: fp16 BD^T buffer [576 u_loc][36 words] (direct mma store, gather later).
// PV A-fragments via ldmatrix.x4.trans from e_h.
// ============================================================================
#define EW  36      // words per e_h / bdt row
#define EH2 72      // halves per row
#define CH  128
#define TFW 4608

__device__ __forceinline__ void ldg_A_k(uint32_t* r, const uint32_t* src,
                                        int wid, int gg, int tt) {
#pragma unroll
    for (int k = 0; k < 2; ++k) {
        int c = wid + (k << 4);
        int mt = c >> 2, ks = c & 3;
#pragma unroll
        for (int aidx = 0; aidx < 4; ++aidx) {
            int row = mt * 16 + (aidx & 1) * 8 + gg;
            int col = ks * 8 + (aidx >> 1) * 4 + tt;
            r[k * 4 + aidx] = src[(size_t)row * 32 + col];
        }
    }
}

__device__ __forceinline__ void ldg_A_rpe(uint32_t* r, const uint32_t* rc,
                                          int ubase, int wid, int gg, int tt) {
#pragma unroll
    for (int k = 0; k < 2; ++k) {
        int c = wid + (k << 4);
        int mt = c >> 2, ks = c & 3;
#pragma unroll
        for (int aidx = 0; aidx < 4; ++aidx) {
            int row = mt * 16 + (aidx & 1) * 8 + gg;
            int col = ks * 8 + (aidx >> 1) * 4 + tt;
            int u = ubase + row;
            r[k * 4 + aidx] = (u < RR) ? rc[(size_t)u * 256 + col] : 0u;
        }
    }
}

__device__ __forceinline__ void sts_A(uint32_t* buf, const uint32_t* r,
                                      int wid, int lane) {
#pragma unroll
    for (int k = 0; k < 2; ++k) {
        int c = wid + (k << 4);
        *(uint4*)&buf[(c * 32 + lane) * 4] =
            make_uint4(r[k * 4], r[k * 4 + 1], r[k * 4 + 2], r[k * 4 + 3]);
    }
}

__device__ __forceinline__ void ldg_B_v(uint32_t* r, const uint32_t* src, int tid) {
#pragma unroll
    for (int k = 0; k < 8; ++k) {
        int idx = k * 512 + tid;
        int dh = idx >> 6, w = idx & 63;
        r[k] = src[(size_t)dh * 256 + w];
    }
}

__device__ __forceinline__ void sts_B(uint32_t* buf, const uint32_t* r, int tid) {
#pragma unroll
    for (int k = 0; k < 8; ++k) {
        int idx = k * 512 + tid;
        int dh = idx >> 6, w = idx & 63;
        buf[dh * 68 + w] = r[k];
    }
}

__global__ void __launch_bounds__(512, 1)
attn_fp16_kernel(const float* __restrict__ tau_ptr) {
    extern __shared__ uint32_t smw[];
    uint32_t* e_h = smw;                     // 18432 words
    uint32_t* bdt = e_h + 512 * EW;          // 20736 words
    uint32_t* Qf  = bdt + 576 * EW;          // 2048
    uint32_t* Tf0 = Qf + 2048;               // 4608
    uint32_t* Tf1 = Tf0 + TFW;               // 4608
    float* uks  = (float*)(Tf1 + TFW);       // 512
    float* vrs  = uks + 512;                 // 576
    float* red  = vrs + 576;                 // 512
    float* rowm = red + 512;                 // 64
    float* rowl = rowm + 64;                 // 64
    uint32_t* Tf[2] = {Tf0, Tf1};
    __half* e_hh  = (__half*)e_h;
    __half* bdth  = (__half*)bdt;

    const int bh = blockIdx.y, h = bh & 7, b = bh >> 3;
    const int i0 = blockIdx.x * 64;
    const int tid = threadIdx.x, lane = tid & 31, wid = tid >> 5;
    const int gi = lane >> 2, ti = lane & 3;
    const int wm = wid >> 1, wn = wid & 1;

    const uint32_t* kbase = (const uint32_t*)g_k + (size_t)bh * TT * 32;
    const uint32_t* vTbase = (const uint32_t*)g_vT + (size_t)bh * 64 * 256;
    const uint32_t* rc = (const uint32_t*)g_rpe + h * 32;

    uint32_t r[8];

    // ---- prefetch AC chunk 0 + init Q (B-frag layout), uk, vr ----
    ldg_A_k(r, kbase, wid, gi, ti);
    {
        const uint32_t* qg = (const uint32_t*)g_q + ((size_t)bh * TT + i0) * 32;
        for (int s = tid; s < 2048; s += 512) {
            int bidx = s & 1, l = (s >> 1) & 31, ks = (s >> 6) & 3, nt = s >> 8;
            int gg2 = l >> 2, tt2 = l & 3;
            int ii = nt * 8 + gg2;
            int dhw = ks * 8 + bidx * 4 + tt2;
            Qf[s] = qg[ii * 32 + dhw];
        }
        uks[tid] = g_uk[bh * 512 + tid];
        for (int s = tid; s < 576; s += 512) {
            int u = i0 + s;
            vrs[s] = (u < RR) ? g_vr[u * 8 + h] : 0.f;
        }
    }
    sts_A(Tf[0], r, wid, lane);
    __syncthreads();

    // ---- Phase AC: 4 chunks of 128 j-rows -> e_h fp16 ----
#pragma unroll
    for (int jc = 0; jc < 4; ++jc) {
        if (jc < 3) ldg_A_k(r, kbase + (size_t)(jc + 1) * CH * 32, wid, gi, ti);
        else        ldg_A_rpe(r, rc, i0, wid, gi, ti);

        float c_[4][4] = {};
        const uint32_t* cur = Tf[jc & 1];
#pragma unroll
        for (int ks = 0; ks < 4; ++ks) {
            uint4 av = *(const uint4*)&cur[((wm * 4 + ks) * 32 + lane) * 4];
            uint32_t a[4] = {av.x, av.y, av.z, av.w};
#pragma unroll
            for (int n = 0; n < 4; ++n) {
                int nt = wn * 4 + n;
                uint2 bv = *(const uint2*)&Qf[((nt * 4 + ks) * 32 + lane) * 2];
                uint32_t bb[2] = {bv.x, bv.y};
                mma16(c_[n], a, bb);
            }
        }
        int j = jc * CH + wm * 16 + gi;
#pragma unroll
        for (int n = 0; n < 4; ++n) {
            int iw = wn * 16 + n * 4 + ti;
            e_h[j * EW + iw]       = packh2(c_[n][0], c_[n][1]);
            e_h[(j + 8) * EW + iw] = packh2(c_[n][2], c_[n][3]);
        }
        sts_A(Tf[(jc + 1) & 1], r, wid, lane);
        __syncthreads();
    }

    // ---- Phase BD: 5 chunks -> bdt fp16 (direct store, no RMW) ----
#pragma unroll
    for (int ch = 0; ch < 5; ++ch) {
        if (ch < 4) ldg_A_rpe(r, rc, i0 + (ch + 1) * CH, wid, gi, ti);
        else        ldg_B_v(r, vTbase, tid);

        if (!(ch == 4 && wm >= 4)) {
            float c_[4][4] = {};
            const uint32_t* cur = Tf[ch & 1];
#pragma unroll
            for (int ks = 0; ks < 4; ++ks) {
                uint4 av = *(const uint4*)&cur[((wm * 4 + ks) * 32 + lane) * 4];
                uint32_t a[4] = {av.x, av.y, av.z, av.w};
#pragma unroll
                for (int n = 0; n < 4; ++n) {
                    int nt = wn * 4 + n;
                    uint2 bv = *(const uint2*)&Qf[((nt * 4 + ks) * 32 + lane) * 2];
                    uint32_t bb[2] = {bv.x, bv.y};
                    mma16(c_[n], a, bb);
                }
            }
            int u = ch * CH + wm * 16 + gi;     // u_loc, max 575
#pragma unroll
            for (int n = 0; n < 4; ++n) {
                int iw = wn * 16 + n * 4 + ti;
                bdt[u * EW + iw]       = packh2(c_[n][0], c_[n][1]);
                bdt[(u + 8) * EW + iw] = packh2(c_[n][2], c_[n][3]);
            }
        }
        if (ch < 4) sts_A(Tf[(ch + 1) & 1], r, wid, lane);
        else        sts_B(Tf[1], r, tid);
        __syncthreads();
    }

    // ---- finalize + softmax (in-place E -> P in e_h) ----
    {
        const float scale = 0.125f;
        const float tauf = expf(tau_ptr[0]);
        int col = tid & 63, seg = tid >> 6;
        int ig = i0 + col;
        float mloc = -FLT_MAX;
        for (int jj = 0; jj < 64; ++jj) {
            int j = seg * 64 + jj;
            int ur = col - j + 511;
            float e  = __half2float(e_hh[j * EH2 + col]);
            float bd = __half2float(bdth[ur * EH2 + col]);
            float val = (e + bd + uks[j] + vrs[ur]) * scale;
            if (j == ig) val = -FLT_MAX;
            val *= tauf;
            __half hv = __float2half(val);      // -FLT_MAX -> -inf (fine)
            e_hh[j * EH2 + col] = hv;
            mloc = fmaxf(mloc, __half2float(hv));
        }
        red[seg * 64 + col] = mloc;
        __syncthreads();
        if (tid < 64) {
            float m = red[tid];
#pragma unroll
            for (int s = 1; s < 8; ++s) m = fmaxf(m, red[s * 64 + tid]);
            rowm[tid] = m;
        }
        __syncthreads();
        float m = rowm[col];
        float sloc = 0.f;
        for (int jj = 0; jj < 64; ++jj) {
            int j = seg * 64 + jj;
            float e = __half2float(e_hh[j * EH2 + col]);
            float p = __expf(e - m);
            e_hh[j * EH2 + col] = __float2half(p);
            sloc += p;
        }
        red[seg * 64 + col] = sloc;
        __syncthreads();
        if (tid < 64) {
            float s = 0.f;
#pragma unroll
            for (int ss = 0; ss < 8; ++ss) s += red[ss * 64 + tid];
            rowl[tid] = s;
        }
        __syncthreads();
    }

    // ---- Phase PV: A = P via ldmatrix.x4.trans, B = V staged ----
    float o_[2][4] = {};
    const int pwm = wid >> 2;       // i-tile 0..3
    const int pwn = wid & 3;        // dh group 0..3
    const uint32_t ehb = smem_u32(e_h);
    const int grp = lane >> 3, lr = lane & 7;
    const int rsel = (grp & 2) ? 8 : 0;
    const int csel = (grp & 1) ? 8 : 0;
    const int i0w = pwm * 16 + csel;
#pragma unroll
    for (int jc = 0; jc < 4; ++jc) {
        if (jc < 3) ldg_B_v(r, vTbase + (size_t)(jc + 1) * 64, tid);

        const uint32_t* cur = Tf[(jc ^ 1) & 1];
#pragma unroll
        for (int ks = 0; ks < 8; ++ks) {
            int jb = jc * CH + ks * 16;
            uint32_t addr = ehb + (uint32_t)(((jb + rsel + lr) * EH2 + i0w) * 2);
            uint32_t a[4];
            asm volatile(
                "ldmatrix.sync.aligned.m8n8.x4.trans.shared.b16 {%0,%1,%2,%3}, [%4];"
                : "=r"(a[0]), "=r"(a[1]), "=r"(a[2]), "=r"(a[3]) : "r"(addr));
#pragma unroll
            for (int n = 0; n < 2; ++n) {
                int ncol = pwn * 16 + n * 8 + gi;
                uint32_t bb[2];
                bb[0] = cur[ncol * 68 + ks * 8 + ti];
                bb[1] = cur[ncol * 68 + ks * 8 + ti + 4];
                mma16(o_[n], a, bb);
            }
        }
        if (jc < 3) sts_B(Tf[jc & 1], r, tid);
        __syncthreads();
    }

    // ---- epilogue: normalize, write half to g_aoh (t,b,d) rows ----
    {
        int i1 = pwm * 16 + gi, i2 = i1 + 8;
        float inv1 = 1.f / rowl[i1];
        float inv2 = 1.f / rowl[i2];
#pragma unroll
        for (int n = 0; n < 2; ++n) {
            int dh = pwn * 16 + n * 8 + 2 * ti;
            size_t o1 = ((size_t)(i0 + i1) * 8 + b) * 512 + h * 64 + dh;
            size_t o2 = ((size_t)(i0 + i2) * 8 + b) * 512 + h * 64 + dh;
            *(uint32_t*)&g_aoh[o1] = packh2(o_[n][0] * inv1, o_[n][1] * inv1);
            *(uint32_t*)&g_aoh[o2] = packh2(o_[n][2] * inv2, o_[n][3] * inv2);
        }
    }
}

// ============================================================================
// Output projection: 128x64 tile, occ 3. out = g_aoh @ W_out + b_out
// ============================================================================
__global__ void __launch_bounds__(256, 3)
out_fp16_kernel(const float* __restrict__ bias, float* __restrict__ out) {
    __shared__ uint32_t As[128 * 36];
    __shared__ uint32_t Bs[64 * 36];
    const int bid = blockIdx.x, tid = threadIdx.x;
    const int m0 = (bid / 8) * 128, n0 = (bid % 8) * 64;
    const int lane = tid & 31, wid = tid >> 5;
    const int gi = lane >> 2, ti = lane & 3;
    const int wm = wid >> 1, wn = wid & 1;

    const uint32_t* aw = (const uint32_t*)g_aoh;
    const uint32_t* bw = (const uint32_t*)g_woh;

    float c_[2][4][4] = {};

    for (int k0 = 0; k0 < 8; ++k0) {
#pragma unroll
        for (int rep = 0; rep < 4; ++rep) {
            int s = rep * 256 + tid;
            int row = s >> 3, seg = s & 7;
            *(uint4*)&As[row * 36 + seg * 4] =
                *(const uint4*)&aw[(size_t)(m0 + row) * 256 + k0 * 32 + seg * 4];
        }
#pragma unroll
        for (int rep = 0; rep < 2; ++rep) {
            int s = rep * 256 + tid;
            int row = s >> 3, seg = s & 7;
            *(uint4*)&Bs[row * 36 + seg * 4] =
                *(const uint4*)&bw[(size_t)(n0 + row) * 256 + k0 * 32 + seg * 4];
        }
        __syncthreads();
#pragma unroll
        for (int kb = 0; kb < 4; ++kb) {
            uint32_t a[2][4], bb[4][2];
#pragma unroll
            for (int mt = 0; mt < 2; ++mt) {
                int r = wm * 32 + mt * 16 + gi;
                a[mt][0] = As[r * 36 + kb * 8 + ti];
                a[mt][1] = As[(r + 8) * 36 + kb * 8 + ti];
                a[mt][2] = As[r * 36 + kb * 8 + ti + 4];
                a[mt][3] = As[(r + 8) * 36 + kb * 8 + ti + 4];
            }
#pragma unroll
            for (int nt = 0; nt < 4; ++nt) {
                int ncol = wn * 32 + nt * 8 + gi;
                bb[nt][0] = Bs[ncol * 36 + kb * 8 + ti];
                bb[nt][1] = Bs[ncol * 36 + kb * 8 + ti + 4];
            }
#pragma unroll
            for (int mt = 0; mt < 2; ++mt)
#pragma unroll
                for (int nt = 0; nt < 4; ++nt)
                    mma16(c_[mt][nt], a[mt], bb[nt]);
        }
        __syncthreads();
    }

#pragma unroll
    for (int mt = 0; mt < 2; ++mt) {
        int m = m0 + wm * 32 + mt * 16 + gi;
#pragma unroll
        for (int nt = 0; nt < 4; ++nt) {
            int n = n0 + wn * 32 + nt * 8 + 2 * ti;
            float b0 = bias[n], b1 = bias[n + 1];
            *(float2*)&out[(size_t)m * 512 + n] =
                make_float2(c_[mt][nt][0] + b0, c_[mt][nt][1] + b1);
            *(float2*)&out[(size_t)(m + 8) * 512 + n] =
                make_float2(c_[mt][nt][2] + b0, c_[mt][nt][3] + b1);
        }
    }
}

// ============================================================================
extern "C" void kernel_launch(void* const* d_in, const int* in_sizes, int n_in,
                              void* d_out, int out_size) {
    const float* x     = (const float*)d_in[0];
    const float* Wqkv  = (const float*)d_in[1];
    const float* Wpos  = (const float*)d_in[2];
    const float* pos_u = (const float*)d_in[3];
    const float* pos_v = (const float*)d_in[4];
    const float* Wout  = (const float*)d_in[5];
    const float* bout  = (const float*)d_in[6];
    const float* ltau  = (const float*)d_in[7];
    float* out = (float*)d_out;

    prep_kernel<<<3328, 256>>>(x, Wqkv, Wpos, Wout);
    gemm_fused_kernel<<<832, 256>>>();
    bias_kernel<<<640, 256>>>(pos_u, pos_v);

    const size_t smem = (size_t)(512 * EW + 576 * EW + 2048 + 2 * TFW
                                 + 512 + 576 + 512 + 64 + 64) * sizeof(uint32_t);
    cudaFuncSetAttribute(attn_fp16_kernel, cudaFuncAttributeMaxDynamicSharedMemorySize, (int)smem);
    attn_fp16_kernel<<<dim3(8, 64), 512, smem>>>(ltau);

    out_fp16_kernel<<<256, 256>>>(bout, out);
}

// round 11
// speedup vs baseline: 1.6019x; 1.0226x over previous
#include <cuda_runtime.h>
#include <cuda_fp16.h>
#include <math.h>
#include <float.h>
#include <stdint.h>

#define TT   512
#define BB   8
#define DD   512
#define HH   8
#define DHH  64
#define RR   1023
#define BHN  64
#define MROWS 4096

// ---------------- scratch (fp16 payloads) ----------------
__device__ __half g_q[BHN * TT * DHH];      // [b*8+h][t][dh]
__device__ __half g_k[BHN * TT * DHH];
__device__ __half g_vT[BHN * DHH * TT];     // [b*8+h][dh][t]
__device__ __half g_rpe[RR * DD];           // [r][h*64+dh]
__device__ __half g_xh[MROWS * DD];
__device__ __half g_wqh[1536 * 512];        // W_qkv^T [n][k]
__device__ __half g_wph[512 * 512];         // W_pos^T [n][k]
__device__ __half g_woh[512 * 512];         // W_out^T [n][k]
__device__ __half g_aoh[MROWS * DD];        // attention out (t,b,d), half
__device__ float  g_uk[BHN * TT];
__device__ float  g_vr[RR * HH];

__device__ __forceinline__ void mma16(float* c, const uint32_t* a, const uint32_t* b) {
    asm volatile(
        "mma.sync.aligned.m16n8k16.row.col.f32.f16.f16.f32 "
        "{%0,%1,%2,%3},{%4,%5,%6,%7},{%8,%9},{%0,%1,%2,%3};"
        : "+f"(c[0]), "+f"(c[1]), "+f"(c[2]), "+f"(c[3])
        : "r"(a[0]), "r"(a[1]), "r"(a[2]), "r"(a[3]), "r"(b[0]), "r"(b[1]));
}

__device__ __forceinline__ uint32_t packh2(float lo, float hi) {
    __half2 h = __floats2half2_rn(lo, hi);
    return *(uint32_t*)&h;
}

__device__ __forceinline__ uint32_t smem_u32(const void* p) {
    uint32_t a;
    asm("{ .reg .u64 t; cvta.to.shared.u64 t, %1; cvt.u32.u64 %0, t; }" : "=r"(a) : "l"(p));
    return a;
}

// ============================================================================
// PREP (fused)
// ============================================================================
__global__ void __launch_bounds__(256)
prep_kernel(const float* __restrict__ x, const float* __restrict__ Wqkv,
            const float* __restrict__ Wpos, const float* __restrict__ Wout) {
    __shared__ float t[32][33];
    int bid = blockIdx.x, tid = threadIdx.x;

    if (bid < 2048) {
        int i = bid * 256 + tid;
        float4 v = *(const float4*)&x[(size_t)i * 4];
        *(uint32_t*)&g_xh[(size_t)i * 4]     = packh2(v.x, v.y);
        *(uint32_t*)&g_xh[(size_t)i * 4 + 2] = packh2(v.z, v.w);
        return;
    }

    const float* src; __half* dst; int N, bx, by;
    if (bid < 2816)      { int b = bid - 2048; src = Wqkv; dst = g_wqh; N = 1536; bx = b % 48, by = b / 48; }
    else if (bid < 3072) { int b = bid - 2816; src = Wpos; dst = g_wph; N = 512;  bx = b % 16, by = b / 16; }
    else                 { int b = bid - 3072; src = Wout; dst = g_woh; N = 512;  bx = b % 16, by = b / 16; }

    int n0 = bx * 32, k0 = by * 32;
    int tx = tid & 31, ty = tid >> 5;
    for (int r = ty; r < 32; r += 8)
        t[r][tx] = src[(size_t)(k0 + r) * N + n0 + tx];
    __syncthreads();
    for (int r = ty; r < 32; r += 8)
        dst[(size_t)(n0 + r) * 512 + k0 + tx] = __float2half(t[tx][r]);
}

// ============================================================================
// FUSED GEMM: QKV + rpe (unchanged from R9)
// ============================================================================
__global__ void __launch_bounds__(256, 3)
gemm_fused_kernel() {
    __shared__ uint32_t As[128 * 36];
    __shared__ uint32_t Bs[64 * 36];
    __shared__ float freqs[512];
    const int bid = blockIdx.x, tid = threadIdx.x;
    const int lane = tid & 31, wid = tid >> 5;
    const int gi = lane >> 2, ti = lane & 3;
    const int wm = wid >> 1, wn = wid & 1;

    const bool is_rpe = (bid >= 768);
    int m0, n0;
    const uint32_t *aw = 0, *bw;
    if (!is_rpe) {
        m0 = (bid / 24) * 128; n0 = (bid % 24) * 64;
        aw = (const uint32_t*)g_xh; bw = (const uint32_t*)g_wqh;
    } else {
        int b = bid - 768;
        m0 = (b / 8) * 128; n0 = (b % 8) * 64;
        bw = (const uint32_t*)g_wph;
        for (int s = tid; s < 512; s += 256) {
            int cc = s & 255;
            freqs[s] = __expf(-9.210340371976184f * (float)cc * (1.0f / 256.0f));
        }
        __syncthreads();
    }

    float c_[2][4][4] = {};

    for (int k0 = 0; k0 < 8; ++k0) {
        if (!is_rpe) {
#pragma unroll
            for (int rep = 0; rep < 4; ++rep) {
                int s = rep * 256 + tid;
                int row = s >> 3, seg = s & 7;
                *(uint4*)&As[row * 36 + seg * 4] =
                    *(const uint4*)&aw[(size_t)(m0 + row) * 256 + k0 * 32 + seg * 4];
            }
        } else {
#pragma unroll
            for (int rep = 0; rep < 16; ++rep) {
                int s = rep * 256 + tid;
                int row = s >> 5, w = s & 31;
                int kg = k0 * 64 + 2 * w;
                float rel = (float)(m0 + row - 511);
                float a0 = rel * freqs[kg], a1 = rel * freqs[kg + 1];
                float f0 = (kg < 256) ? sinf(a0) : cosf(a0);
                float f1 = (kg + 1 < 256) ? sinf(a1) : cosf(a1);
                As[row * 36 + w] = packh2(f0, f1);
            }
        }
#pragma unroll
        for (int rep = 0; rep < 2; ++rep) {
            int s = rep * 256 + tid;
            int row = s >> 3, seg = s & 7;
            *(uint4*)&Bs[row * 36 + seg * 4] =
                *(const uint4*)&bw[(size_t)(n0 + row) * 256 + k0 * 32 + seg * 4];
        }
        __syncthreads();
#pragma unroll
        for (int kb = 0; kb < 4; ++kb) {
            uint32_t a[2][4], bb[4][2];
#pragma unroll
            for (int mt = 0; mt < 2; ++mt) {
                int r = wm * 32 + mt * 16 + gi;
                a[mt][0] = As[r * 36 + kb * 8 + ti];
                a[mt][1] = As[(r + 8) * 36 + kb * 8 + ti];
                a[mt][2] = As[r * 36 + kb * 8 + ti + 4];
                a[mt][3] = As[(r + 8) * 36 + kb * 8 + ti + 4];
            }
#pragma unroll
            for (int nt = 0; nt < 4; ++nt) {
                int ncol = wn * 32 + nt * 8 + gi;
                bb[nt][0] = Bs[ncol * 36 + kb * 8 + ti];
                bb[nt][1] = Bs[ncol * 36 + kb * 8 + ti + 4];
            }
#pragma unroll
            for (int mt = 0; mt < 2; ++mt)
#pragma unroll
                for (int nt = 0; nt < 4; ++nt)
                    mma16(c_[mt][nt], a[mt], bb[nt]);
        }
        __syncthreads();
    }

    if (!is_rpe) {
#pragma unroll
        for (int mt = 0; mt < 2; ++mt) {
            int m = m0 + wm * 32 + mt * 16 + gi;
#pragma unroll
            for (int nt = 0; nt < 4; ++nt) {
                int n = n0 + wn * 32 + nt * 8 + 2 * ti;
                int part = n >> 9, hh = (n >> 6) & 7, dh = n & 63;
#pragma unroll
                for (int half = 0; half < 2; ++half) {
                    int mm = m + half * 8;
                    float v0 = c_[mt][nt][half * 2], v1 = c_[mt][nt][half * 2 + 1];
                    int tr = mm >> 3, bi = mm & 7;
                    int bh = bi * 8 + hh;
                    if (part == 2) {
                        g_vT[((size_t)bh * 64 + dh) * 512 + tr]     = __float2half(v0);
                        g_vT[((size_t)bh * 64 + dh + 1) * 512 + tr] = __float2half(v1);
                    } else {
                        __half* dst = (part == 0) ? g_q : g_k;
                        *(uint32_t*)&dst[((size_t)bh * 512 + tr) * 64 + dh] = packh2(v0, v1);
                    }
                }
            }
        }
    } else {
#pragma unroll
        for (int mt = 0; mt < 2; ++mt) {
            int m = m0 + wm * 32 + mt * 16 + gi;
#pragma unroll
            for (int nt = 0; nt < 4; ++nt) {
                int n = n0 + wn * 32 + nt * 8 + 2 * ti;
                if (m < RR)
                    *(uint32_t*)&g_rpe[(size_t)m * 512 + n] = packh2(c_[mt][nt][0], c_[mt][nt][1]);
                if (m + 8 < RR)
                    *(uint32_t*)&g_rpe[(size_t)(m + 8) * 512 + n] = packh2(c_[mt][nt][2], c_[mt][nt][3]);
            }
        }
    }
}

// ============================================================================
// BIAS (fused)
// ============================================================================
__global__ void __launch_bounds__(256)
bias_kernel(const float* __restrict__ pos_u, const float* __restrict__ pos_v) {
    int bid = blockIdx.x, tid = threadIdx.x;
    if (bid < 512) {
        int gid = bid * 256 + tid;
        int id = gid >> 2, part = gid & 3;
        int h = (id >> 9) & 7;
        const __half2* kp = (const __half2*)(g_k + (size_t)id * 64) + part * 8;
        const float* up = pos_u + h * 64 + part * 16;
        float acc = 0.f;
#pragma unroll
        for (int s = 0; s < 8; ++s) {
            float2 kf = __half22float2(kp[s]);
            acc += kf.x * up[2 * s] + kf.y * up[2 * s + 1];
        }
        acc += __shfl_xor_sync(0xffffffffu, acc, 1);
        acc += __shfl_xor_sync(0xffffffffu, acc, 2);
        if (part == 0) g_uk[id] = acc;
    } else {
        int gid = (bid - 512) * 256 + tid;
        int id = gid >> 2, part = gid & 3;
        if (id >= RR * HH) return;
        int r = id >> 3, h = id & 7;
        const __half2* rp = (const __half2*)(g_rpe + (size_t)r * 512 + h * 64) + part * 8;
        const float* vp = pos_v + h * 64 + part * 16;
        float acc = 0.f;
#pragma unroll
        for (int s = 0; s < 8; ++s) {
            float2 rf = __half22float2(rp[s]);
            acc += rf.x * vp[2 * s] + rf.y * vp[2 * s + 1];
        }
        acc += __shfl_xor_sync(0xffffffffu, acc, 1);
        acc += __shfl_xor_sync(0xffffffffu, acc, 2);
        if (part == 0) g_vr[id] = acc;
    }
}

// ============================================================================
// Fused attention: BD first (bdt), AC epilogue folds bd+uk+vr+scale+mask+tau,
// vectorized half2 softmax, PV via ldmatrix.
// ============================================================================
#define EW  36
#define EH2 72
#define CH  128
#define TFW 4608

__device__ __forceinline__ void ldg_A_k(uint32_t* r, const uint32_t* src,
                                        int wid, int gg, int tt) {
#pragma unroll
    for (int k = 0; k < 2; ++k) {
        int c = wid + (k << 4);
        int mt = c >> 2, ks = c & 3;
#pragma unroll
        for (int aidx = 0; aidx < 4; ++aidx) {
            int row = mt * 16 + (aidx & 1) * 8 + gg;
            int col = ks * 8 + (aidx >> 1) * 4 + tt;
            r[k * 4 + aidx] = src[(size_t)row * 32 + col];
        }
    }
}

__device__ __forceinline__ void ldg_A_rpe(uint32_t* r, const uint32_t* rc,
                                          int ubase, int wid, int gg, int tt) {
#pragma unroll
    for (int k = 0; k < 2; ++k) {
        int c = wid + (k << 4);
        int mt = c >> 2, ks = c & 3;
#pragma unroll
        for (int aidx = 0; aidx < 4; ++aidx) {
            int row = mt * 16 + (aidx & 1) * 8 + gg;
            int col = ks * 8 + (aidx >> 1) * 4 + tt;
            int u = ubase + row;
            r[k * 4 + aidx] = (u < RR) ? rc[(size_t)u * 256 + col] : 0u;
        }
    }
}

__device__ __forceinline__ void sts_A(uint32_t* buf, const uint32_t* r,
                                      int wid, int lane) {
#pragma unroll
    for (int k = 0; k < 2; ++k) {
        int c = wid + (k << 4);
        *(uint4*)&buf[(c * 32 + lane) * 4] =
            make_uint4(r[k * 4], r[k * 4 + 1], r[k * 4 + 2], r[k * 4 + 3]);
    }
}

__device__ __forceinline__ void ldg_B_v(uint32_t* r, const uint32_t* src, int tid) {
#pragma unroll
    for (int k = 0; k < 8; ++k) {
        int idx = k * 512 + tid;
        int dh = idx >> 6, w = idx & 63;
        r[k] = src[(size_t)dh * 256 + w];
    }
}

__device__ __forceinline__ void sts_B(uint32_t* buf, const uint32_t* r, int tid) {
#pragma unroll
    for (int k = 0; k < 8; ++k) {
        int idx = k * 512 + tid;
        int dh = idx >> 6, w = idx & 63;
        buf[dh * 68 + w] = r[k];
    }
}

__global__ void __launch_bounds__(512, 1)
attn_fp16_kernel(const float* __restrict__ tau_ptr) {
    extern __shared__ uint32_t smw[];
    uint32_t* e_h = smw;                     // 18432
    uint32_t* bdt = e_h + 512 * EW;          // 20736
    uint32_t* Qf  = bdt + 576 * EW;          // 2048
    uint32_t* Tf0 = Qf + 2048;               // 4608
    uint32_t* Tf1 = Tf0 + TFW;               // 4608
    float* uks  = (float*)(Tf1 + TFW);       // 512
    float* vrs  = uks + 512;                 // 576
    float* red  = vrs + 576;                 // 1024 (16 segs x 64 cols)
    float* rowm = red + 1024;                // 64
    float* rowl = rowm + 64;                 // 64
    uint32_t* Tf[2] = {Tf0, Tf1};
    __half* e_hh = (__half*)e_h;
    __half* bdth = (__half*)bdt;

    const int bh = blockIdx.y, h = bh & 7, b = bh >> 3;
    const int i0 = blockIdx.x * 64;
    const int tid = threadIdx.x, lane = tid & 31, wid = tid >> 5;
    const int gi = lane >> 2, ti = lane & 3;
    const int wm = wid >> 1, wn = wid & 1;

    const uint32_t* kbase = (const uint32_t*)g_k + (size_t)bh * TT * 32;
    const uint32_t* vTbase = (const uint32_t*)g_vT + (size_t)bh * 64 * 256;
    const uint32_t* rc = (const uint32_t*)g_rpe + h * 32;

    uint32_t r[8];

    // ---- prefetch BD chunk 0 + init Q (B-frag), uk, vr ----
    ldg_A_rpe(r, rc, i0, wid, gi, ti);
    {
        const uint32_t* qg = (const uint32_t*)g_q + ((size_t)bh * TT + i0) * 32;
        for (int s = tid; s < 2048; s += 512) {
            int bidx = s & 1, l = (s >> 1) & 31, ks = (s >> 6) & 3, nt = s >> 8;
            int gg2 = l >> 2, tt2 = l & 3;
            int ii = nt * 8 + gg2;
            int dhw = ks * 8 + bidx * 4 + tt2;
            Qf[s] = qg[ii * 32 + dhw];
        }
        uks[tid] = g_uk[bh * 512 + tid];
        for (int s = tid; s < 576; s += 512) {
            int u = i0 + s;
            vrs[s] = (u < RR) ? g_vr[u * 8 + h] : 0.f;
        }
    }
    sts_A(Tf[0], r, wid, lane);
    __syncthreads();

    // ---- Phase BD (first): 5 chunks -> bdt fp16 direct store ----
#pragma unroll
    for (int ch = 0; ch < 5; ++ch) {
        if (ch < 4) ldg_A_rpe(r, rc, i0 + (ch + 1) * CH, wid, gi, ti);
        else        ldg_A_k(r, kbase, wid, gi, ti);        // prefetch AC chunk 0

        if (!(ch == 4 && wm >= 4)) {
            float c_[4][4] = {};
            const uint32_t* cur = Tf[ch & 1];
#pragma unroll
            for (int ks = 0; ks < 4; ++ks) {
                uint4 av = *(const uint4*)&cur[((wm * 4 + ks) * 32 + lane) * 4];
                uint32_t a[4] = {av.x, av.y, av.z, av.w};
#pragma unroll
                for (int n = 0; n < 4; ++n) {
                    int nt = wn * 4 + n;
                    uint2 bv = *(const uint2*)&Qf[((nt * 4 + ks) * 32 + lane) * 2];
                    uint32_t bb[2] = {bv.x, bv.y};
                    mma16(c_[n], a, bb);
                }
            }
            int u = ch * CH + wm * 16 + gi;
#pragma unroll
            for (int n = 0; n < 4; ++n) {
                int iw = wn * 16 + n * 4 + ti;
                bdt[u * EW + iw]       = packh2(c_[n][0], c_[n][1]);
                bdt[(u + 8) * EW + iw] = packh2(c_[n][2], c_[n][3]);
            }
        }
        sts_A(Tf[(ch + 1) & 1], r, wid, lane);
        __syncthreads();
    }

    // ---- Phase AC: 4 chunks; epilogue folds bd+uk+vr, scale, mask, tau ----
    const float scale = 0.125f;
    const float tauf = expf(tau_ptr[0]);
#pragma unroll
    for (int jc = 0; jc < 4; ++jc) {
        if (jc < 3) ldg_A_k(r, kbase + (size_t)(jc + 1) * CH * 32, wid, gi, ti);
        else        ldg_B_v(r, vTbase, tid);               // prefetch PV chunk 0

        float c_[4][4] = {};
        const uint32_t* cur = Tf[(jc ^ 1) & 1];
#pragma unroll
        for (int ks = 0; ks < 4; ++ks) {
            uint4 av = *(const uint4*)&cur[((wm * 4 + ks) * 32 + lane) * 4];
            uint32_t a[4] = {av.x, av.y, av.z, av.w};
#pragma unroll
            for (int n = 0; n < 4; ++n) {
                int nt = wn * 4 + n;
                uint2 bv = *(const uint2*)&Qf[((nt * 4 + ks) * 32 + lane) * 2];
                uint32_t bb[2] = {bv.x, bv.y};
                mma16(c_[n], a, bb);
            }
        }
        int j = jc * CH + wm * 16 + gi;
        float uk0 = uks[j], uk1 = uks[j + 8];
#pragma unroll
        for (int n = 0; n < 4; ++n) {
            int ii = wn * 32 + n * 8 + 2 * ti;          // local i (even)
            int iw = wn * 16 + n * 4 + ti;
#pragma unroll
            for (int rr = 0; rr < 2; ++rr) {
                int jj = j + rr * 8;
                float ukv = rr ? uk1 : uk0;
                int ur0 = ii - jj + 511;
                int ur1 = ur0 + 1;
                float bd0 = __half2float(bdth[ur0 * EH2 + ii]);
                float bd1 = __half2float(bdth[ur1 * EH2 + ii + 1]);
                float v0 = (c_[n][rr * 2]     + bd0 + ukv + vrs[ur0]) * scale;
                float v1 = (c_[n][rr * 2 + 1] + bd1 + ukv + vrs[ur1]) * scale;
                if (jj == i0 + ii)     v0 = -FLT_MAX;
                if (jj == i0 + ii + 1) v1 = -FLT_MAX;
                e_h[jj * EW + iw] = packh2(v0 * tauf, v1 * tauf);
            }
        }
        sts_A_dummy: ;
        if (jc < 3) sts_A(Tf[jc & 1], r, wid, lane);
        else        sts_B(Tf[1], r, tid);                  // PV chunk 0 -> buf1
        __syncthreads();
    }

    // ---- softmax (vectorized half2 over column pairs) ----
    {
        int cp = tid & 31, seg = tid >> 5;                 // 32 col-pairs, 16 segs
        float m0 = -FLT_MAX, m1 = -FLT_MAX;
        for (int jj = 0; jj < 32; ++jj) {
            int j = seg * 32 + jj;
            __half2 hv = *(__half2*)&e_h[j * EW + cp];
            float2 f = __half22float2(hv);
            m0 = fmaxf(m0, f.x); m1 = fmaxf(m1, f.y);
        }
        red[seg * 64 + 2 * cp]     = m0;
        red[seg * 64 + 2 * cp + 1] = m1;
        __syncthreads();
        if (tid < 64) {
            float m = red[tid];
#pragma unroll
            for (int s = 1; s < 16; ++s) m = fmaxf(m, red[s * 64 + tid]);
            rowm[tid] = m;
        }
        __syncthreads();
        m0 = rowm[2 * cp]; m1 = rowm[2 * cp + 1];
        float s0 = 0.f, s1 = 0.f;
        for (int jj = 0; jj < 32; ++jj) {
            int j = seg * 32 + jj;
            __half2 hv = *(__half2*)&e_h[j * EW + cp];
            float2 f = __half22float2(hv);
            float p0 = __expf(f.x - m0), p1 = __expf(f.y - m1);
            e_h[j * EW + cp] = packh2(p0, p1);
            s0 += p0; s1 += p1;
        }
        red[seg * 64 + 2 * cp]     = s0;
        red[seg * 64 + 2 * cp + 1] = s1;
        __syncthreads();
        if (tid < 64) {
            float s = 0.f;
#pragma unroll
            for (int ss = 0; ss < 16; ++ss) s += red[ss * 64 + tid];
            rowl[tid] = s;
        }
        __syncthreads();
    }

    // ---- Phase PV: A = P via ldmatrix.x4.trans, B = V staged ----
    float o_[2][4] = {};
    const int pwm = wid >> 2;
    const int pwn = wid & 3;
    const uint32_t ehb = smem_u32(e_h);
    const int grp = lane >> 3, lr = lane & 7;
    const int rsel = (grp & 2) ? 8 : 0;
    const int csel = (grp & 1) ? 8 : 0;
    const int i0w = pwm * 16 + csel;
#pragma unroll
    for (int jc = 0; jc < 4; ++jc) {
        if (jc < 3) ldg_B_v(r, vTbase + (size_t)(jc + 1) * 64, tid);

        const uint32_t* cur = Tf[(jc ^ 1) & 1];
#pragma unroll
        for (int ks = 0; ks < 8; ++ks) {
            int jb = jc * CH + ks * 16;
            uint32_t addr = ehb + (uint32_t)(((jb + rsel + lr) * EH2 + i0w) * 2);
            uint32_t a[4];
            asm volatile(
                "ldmatrix.sync.aligned.m8n8.x4.trans.shared.b16 {%0,%1,%2,%3}, [%4];"
                : "=r"(a[0]), "=r"(a[1]), "=r"(a[2]), "=r"(a[3]) : "r"(addr));
#pragma unroll
            for (int n = 0; n < 2; ++n) {
                int ncol = pwn * 16 + n * 8 + gi;
                uint32_t bb[2];
                bb[0] = cur[ncol * 68 + ks * 8 + ti];
                bb[1] = cur[ncol * 68 + ks * 8 + ti + 4];
                mma16(o_[n], a, bb);
            }
        }
        if (jc < 3) sts_B(Tf[jc & 1], r, tid);
        __syncthreads();
    }

    // ---- epilogue ----
    {
        int i1 = pwm * 16 + gi, i2 = i1 + 8;
        float inv1 = 1.f / rowl[i1];
        float inv2 = 1.f / rowl[i2];
#pragma unroll
        for (int n = 0; n < 2; ++n) {
            int dh = pwn * 16 + n * 8 + 2 * ti;
            size_t o1 = ((size_t)(i0 + i1) * 8 + b) * 512 + h * 64 + dh;
            size_t o2 = ((size_t)(i0 + i2) * 8 + b) * 512 + h * 64 + dh;
            *(uint32_t*)&g_aoh[o1] = packh2(o_[n][0] * inv1, o_[n][1] * inv1);
            *(uint32_t*)&g_aoh[o2] = packh2(o_[n][2] * inv2, o_[n][3] * inv2);
        }
    }
}

// ============================================================================
// Output projection (unchanged from R9)
// ============================================================================
__global__ void __launch_bounds__(256, 3)
out_fp16_kernel(const float* __restrict__ bias, float* __restrict__ out) {
    __shared__ uint32_t As[128 * 36];
    __shared__ uint32_t Bs[64 * 36];
    const int bid = blockIdx.x, tid = threadIdx.x;
    const int m0 = (bid / 8) * 128, n0 = (bid % 8) * 64;
    const int lane = tid & 31, wid = tid >> 5;
    const int gi = lane >> 2, ti = lane & 3;
    const int wm = wid >> 1, wn = wid & 1;

    const uint32_t* aw = (const uint32_t*)g_aoh;
    const uint32_t* bw = (const uint32_t*)g_woh;

    float c_[2][4][4] = {};

    for (int k0 = 0; k0 < 8; ++k0) {
#pragma unroll
        for (int rep = 0; rep < 4; ++rep) {
            int s = rep * 256 + tid;
            int row = s >> 3, seg = s & 7;
            *(uint4*)&As[row * 36 + seg * 4] =
                *(const uint4*)&aw[(size_t)(m0 + row) * 256 + k0 * 32 + seg * 4];
        }
#pragma unroll
        for (int rep = 0; rep < 2; ++rep) {
            int s = rep * 256 + tid;
            int row = s >> 3, seg = s & 7;
            *(uint4*)&Bs[row * 36 + seg * 4] =
                *(const uint4*)&bw[(size_t)(n0 + row) * 256 + k0 * 32 + seg * 4];
        }
        __syncthreads();
#pragma unroll
        for (int kb = 0; kb < 4; ++kb) {
            uint32_t a[2][4], bb[4][2];
#pragma unroll
            for (int mt = 0; mt < 2; ++mt) {
                int r = wm * 32 + mt * 16 + gi;
                a[mt][0] = As[r * 36 + kb * 8 + ti];
                a[mt][1] = As[(r + 8) * 36 + kb * 8 + ti];
                a[mt][2] = As[r * 36 + kb * 8 + ti + 4];
                a[mt][3] = As[(r + 8) * 36 + kb * 8 + ti + 4];
            }
#pragma unroll
            for (int nt = 0; nt < 4; ++nt) {
                int ncol = wn * 32 + nt * 8 + gi;
                bb[nt][0] = Bs[ncol * 36 + kb * 8 + ti];
                bb[nt][1] = Bs[ncol * 36 + kb * 8 + ti + 4];
            }
#pragma unroll
            for (int mt = 0; mt < 2; ++mt)
#pragma unroll
                for (int nt = 0; nt < 4; ++nt)
                    mma16(c_[mt][nt], a[mt], bb[nt]);
        }
        __syncthreads();
    }

#pragma unroll
    for (int mt = 0; mt < 2; ++mt) {
        int m = m0 + wm * 32 + mt * 16 + gi;
#pragma unroll
        for (int nt = 0; nt < 4; ++nt) {
            int n = n0 + wn * 32 + nt * 8 + 2 * ti;
            float b0 = bias[n], b1 = bias[n + 1];
            *(float2*)&out[(size_t)m * 512 + n] =
                make_float2(c_[mt][nt][0] + b0, c_[mt][nt][1] + b1);
            *(float2*)&out[(size_t)(m + 8) * 512 + n] =
                make_float2(c_[mt][nt][2] + b0, c_[mt][nt][3] + b1);
        }
    }
}

// ============================================================================
extern "C" void kernel_launch(void* const* d_in, const int* in_sizes, int n_in,
                              void* d_out, int out_size) {
    const float* x     = (const float*)d_in[0];
    const float* Wqkv  = (const float*)d_in[1];
    const float* Wpos  = (const float*)d_in[2];
    const float* pos_u = (const float*)d_in[3];
    const float* pos_v = (const float*)d_in[4];
    const float* Wout  = (const float*)d_in[5];
    const float* bout  = (const float*)d_in[6];
    const float* ltau  = (const float*)d_in[7];
    float* out = (float*)d_out;

    prep_kernel<<<3328, 256>>>(x, Wqkv, Wpos, Wout);
    gemm_fused_kernel<<<832, 256>>>();
    bias_kernel<<<640, 256>>>(pos_u, pos_v);

    const size_t smem = (size_t)(512 * EW + 576 * EW + 2048 + 2 * TFW
                                 + 512 + 576 + 1024 + 64 + 64) * sizeof(uint32_t);
    cudaFuncSetAttribute(attn_fp16_kernel, cudaFuncAttributeMaxDynamicSharedMemorySize, (int)smem);
    attn_fp16_kernel<<<dim3(8, 64), 512, smem>>>(ltau);

    out_fp16_kernel<<<256, 256>>>(bout, out);
}

// round 12
// speedup vs baseline: 1.6485x; 1.0290x over previous
#include <cuda_runtime.h>
#include <cuda_fp16.h>
#include <math.h>
#include <float.h>
#include <stdint.h>

#define TT   512
#define BB   8
#define DD   512
#define HH   8
#define DHH  64
#define RR   1023
#define BHN  64
#define MROWS 4096

// ---------------- scratch (fp16 payloads) ----------------
__device__ __half g_q[BHN * TT * DHH];      // [b*8+h][t][dh]
__device__ __half g_k[BHN * TT * DHH];
__device__ __half g_vT[BHN * DHH * TT];     // [b*8+h][dh][t]
__device__ __half g_rpe[RR * DD];           // [r][h*64+dh]
__device__ __half g_xh[MROWS * DD];
__device__ __half g_wqh[1536 * 512];        // W_qkv^T [n][k]
__device__ __half g_wph[512 * 512];         // W_pos^T [n][k]
__device__ __half g_woh[512 * 512];         // W_out^T [n][k]
__device__ __half g_aoh[MROWS * DD];        // attention out (t,b,d), half
__device__ float  g_uk[BHN * TT];
__device__ float  g_vr[RR * HH];

__device__ __forceinline__ void mma16(float* c, const uint32_t* a, const uint32_t* b) {
    asm volatile(
        "mma.sync.aligned.m16n8k16.row.col.f32.f16.f16.f32 "
        "{%0,%1,%2,%3},{%4,%5,%6,%7},{%8,%9},{%0,%1,%2,%3};"
        : "+f"(c[0]), "+f"(c[1]), "+f"(c[2]), "+f"(c[3])
        : "r"(a[0]), "r"(a[1]), "r"(a[2]), "r"(a[3]), "r"(b[0]), "r"(b[1]));
}

__device__ __forceinline__ uint32_t packh2(float lo, float hi) {
    __half2 h = __floats2half2_rn(lo, hi);
    return *(uint32_t*)&h;
}

__device__ __forceinline__ uint32_t smem_u32(const void* p) {
    uint32_t a;
    asm("{ .reg .u64 t; cvta.to.shared.u64 t, %1; cvt.u32.u64 %0, t; }" : "=r"(a) : "l"(p));
    return a;
}

// ============================================================================
// PREP (fused)
// ============================================================================
__global__ void __launch_bounds__(256)
prep_kernel(const float* __restrict__ x, const float* __restrict__ Wqkv,
            const float* __restrict__ Wpos, const float* __restrict__ Wout) {
    __shared__ float t[32][33];
    int bid = blockIdx.x, tid = threadIdx.x;

    if (bid < 2048) {
        int i = bid * 256 + tid;
        float4 v = *(const float4*)&x[(size_t)i * 4];
        *(uint32_t*)&g_xh[(size_t)i * 4]     = packh2(v.x, v.y);
        *(uint32_t*)&g_xh[(size_t)i * 4 + 2] = packh2(v.z, v.w);
        return;
    }

    const float* src; __half* dst; int N, bx, by;
    if (bid < 2816)      { int b = bid - 2048; src = Wqkv; dst = g_wqh; N = 1536; bx = b % 48, by = b / 48; }
    else if (bid < 3072) { int b = bid - 2816; src = Wpos; dst = g_wph; N = 512;  bx = b % 16, by = b / 16; }
    else                 { int b = bid - 3072; src = Wout; dst = g_woh; N = 512;  bx = b % 16, by = b / 16; }

    int n0 = bx * 32, k0 = by * 32;
    int tx = tid & 31, ty = tid >> 5;
    for (int r = ty; r < 32; r += 8)
        t[r][tx] = src[(size_t)(k0 + r) * N + n0 + tx];
    __syncthreads();
    for (int r = ty; r < 32; r += 8)
        dst[(size_t)(n0 + r) * 512 + k0 + tx] = __float2half(t[tx][r]);
}

// ============================================================================
// FUSED GEMM: QKV + rpe (unchanged)
// ============================================================================
__global__ void __launch_bounds__(256, 3)
gemm_fused_kernel() {
    __shared__ uint32_t As[128 * 36];
    __shared__ uint32_t Bs[64 * 36];
    __shared__ float freqs[512];
    const int bid = blockIdx.x, tid = threadIdx.x;
    const int lane = tid & 31, wid = tid >> 5;
    const int gi = lane >> 2, ti = lane & 3;
    const int wm = wid >> 1, wn = wid & 1;

    const bool is_rpe = (bid >= 768);
    int m0, n0;
    const uint32_t *aw = 0, *bw;
    if (!is_rpe) {
        m0 = (bid / 24) * 128; n0 = (bid % 24) * 64;
        aw = (const uint32_t*)g_xh; bw = (const uint32_t*)g_wqh;
    } else {
        int b = bid - 768;
        m0 = (b / 8) * 128; n0 = (b % 8) * 64;
        bw = (const uint32_t*)g_wph;
        for (int s = tid; s < 512; s += 256) {
            int cc = s & 255;
            freqs[s] = __expf(-9.210340371976184f * (float)cc * (1.0f / 256.0f));
        }
        __syncthreads();
    }

    float c_[2][4][4] = {};

    for (int k0 = 0; k0 < 8; ++k0) {
        if (!is_rpe) {
#pragma unroll
            for (int rep = 0; rep < 4; ++rep) {
                int s = rep * 256 + tid;
                int row = s >> 3, seg = s & 7;
                *(uint4*)&As[row * 36 + seg * 4] =
                    *(const uint4*)&aw[(size_t)(m0 + row) * 256 + k0 * 32 + seg * 4];
            }
        } else {
#pragma unroll
            for (int rep = 0; rep < 16; ++rep) {
                int s = rep * 256 + tid;
                int row = s >> 5, w = s & 31;
                int kg = k0 * 64 + 2 * w;
                float rel = (float)(m0 + row - 511);
                float a0 = rel * freqs[kg], a1 = rel * freqs[kg + 1];
                float f0 = (kg < 256) ? sinf(a0) : cosf(a0);
                float f1 = (kg + 1 < 256) ? sinf(a1) : cosf(a1);
                As[row * 36 + w] = packh2(f0, f1);
            }
        }
#pragma unroll
        for (int rep = 0; rep < 2; ++rep) {
            int s = rep * 256 + tid;
            int row = s >> 3, seg = s & 7;
            *(uint4*)&Bs[row * 36 + seg * 4] =
                *(const uint4*)&bw[(size_t)(n0 + row) * 256 + k0 * 32 + seg * 4];
        }
        __syncthreads();
#pragma unroll
        for (int kb = 0; kb < 4; ++kb) {
            uint32_t a[2][4], bb[4][2];
#pragma unroll
            for (int mt = 0; mt < 2; ++mt) {
                int r = wm * 32 + mt * 16 + gi;
                a[mt][0] = As[r * 36 + kb * 8 + ti];
                a[mt][1] = As[(r + 8) * 36 + kb * 8 + ti];
                a[mt][2] = As[r * 36 + kb * 8 + ti + 4];
                a[mt][3] = As[(r + 8) * 36 + kb * 8 + ti + 4];
            }
#pragma unroll
            for (int nt = 0; nt < 4; ++nt) {
                int ncol = wn * 32 + nt * 8 + gi;
                bb[nt][0] = Bs[ncol * 36 + kb * 8 + ti];
                bb[nt][1] = Bs[ncol * 36 + kb * 8 + ti + 4];
            }
#pragma unroll
            for (int mt = 0; mt < 2; ++mt)
#pragma unroll
                for (int nt = 0; nt < 4; ++nt)
                    mma16(c_[mt][nt], a[mt], bb[nt]);
        }
        __syncthreads();
    }

    if (!is_rpe) {
#pragma unroll
        for (int mt = 0; mt < 2; ++mt) {
            int m = m0 + wm * 32 + mt * 16 + gi;
#pragma unroll
            for (int nt = 0; nt < 4; ++nt) {
                int n = n0 + wn * 32 + nt * 8 + 2 * ti;
                int part = n >> 9, hh = (n >> 6) & 7, dh = n & 63;
#pragma unroll
                for (int half = 0; half < 2; ++half) {
                    int mm = m + half * 8;
                    float v0 = c_[mt][nt][half * 2], v1 = c_[mt][nt][half * 2 + 1];
                    int tr = mm >> 3, bi = mm & 7;
                    int bh = bi * 8 + hh;
                    if (part == 2) {
                        g_vT[((size_t)bh * 64 + dh) * 512 + tr]     = __float2half(v0);
                        g_vT[((size_t)bh * 64 + dh + 1) * 512 + tr] = __float2half(v1);
                    } else {
                        __half* dst = (part == 0) ? g_q : g_k;
                        *(uint32_t*)&dst[((size_t)bh * 512 + tr) * 64 + dh] = packh2(v0, v1);
                    }
                }
            }
        }
    } else {
#pragma unroll
        for (int mt = 0; mt < 2; ++mt) {
            int m = m0 + wm * 32 + mt * 16 + gi;
#pragma unroll
            for (int nt = 0; nt < 4; ++nt) {
                int n = n0 + wn * 32 + nt * 8 + 2 * ti;
                if (m < RR)
                    *(uint32_t*)&g_rpe[(size_t)m * 512 + n] = packh2(c_[mt][nt][0], c_[mt][nt][1]);
                if (m + 8 < RR)
                    *(uint32_t*)&g_rpe[(size_t)(m + 8) * 512 + n] = packh2(c_[mt][nt][2], c_[mt][nt][3]);
            }
        }
    }
}

// ============================================================================
// BIAS (fused)
// ============================================================================
__global__ void __launch_bounds__(256)
bias_kernel(const float* __restrict__ pos_u, const float* __restrict__ pos_v) {
    int bid = blockIdx.x, tid = threadIdx.x;
    if (bid < 512) {
        int gid = bid * 256 + tid;
        int id = gid >> 2, part = gid & 3;
        int h = (id >> 9) & 7;
        const __half2* kp = (const __half2*)(g_k + (size_t)id * 64) + part * 8;
        const float* up = pos_u + h * 64 + part * 16;
        float acc = 0.f;
#pragma unroll
        for (int s = 0; s < 8; ++s) {
            float2 kf = __half22float2(kp[s]);
            acc += kf.x * up[2 * s] + kf.y * up[2 * s + 1];
        }
        acc += __shfl_xor_sync(0xffffffffu, acc, 1);
        acc += __shfl_xor_sync(0xffffffffu, acc, 2);
        if (part == 0) g_uk[id] = acc;
    } else {
        int gid = (bid - 512) * 256 + tid;
        int id = gid >> 2, part = gid & 3;
        if (id >= RR * HH) return;
        int r = id >> 3, h = id & 7;
        const __half2* rp = (const __half2*)(g_rpe + (size_t)r * 512 + h * 64) + part * 8;
        const float* vp = pos_v + h * 64 + part * 16;
        float acc = 0.f;
#pragma unroll
        for (int s = 0; s < 8; ++s) {
            float2 rf = __half22float2(rp[s]);
            acc += rf.x * vp[2 * s] + rf.y * vp[2 * s + 1];
        }
        acc += __shfl_xor_sync(0xffffffffu, acc, 1);
        acc += __shfl_xor_sync(0xffffffffu, acc, 2);
        if (part == 0) g_vr[id] = acc;
    }
}

// ============================================================================
// Fused attention: 4x4 warp grid for BD/AC, Q fragments hoisted to registers
// (loaded once from gmem), BD->bdt direct store, AC epilogue folds everything,
// vectorized softmax, PV via ldmatrix. No Qf smem buffer.
// ============================================================================
#define EW  36
#define EH2 72
#define CH  128
#define TFW 4608

__device__ __forceinline__ void ldg_A_k(uint32_t* r, const uint32_t* src,
                                        int wid, int gg, int tt) {
#pragma unroll
    for (int k = 0; k < 2; ++k) {
        int c = wid + (k << 4);
        int mt = c >> 2, ks = c & 3;
#pragma unroll
        for (int aidx = 0; aidx < 4; ++aidx) {
            int row = mt * 16 + (aidx & 1) * 8 + gg;
            int col = ks * 8 + (aidx >> 1) * 4 + tt;
            r[k * 4 + aidx] = src[(size_t)row * 32 + col];
        }
    }
}

__device__ __forceinline__ void ldg_A_rpe(uint32_t* r, const uint32_t* rc,
                                          int ubase, int wid, int gg, int tt) {
#pragma unroll
    for (int k = 0; k < 2; ++k) {
        int c = wid + (k << 4);
        int mt = c >> 2, ks = c & 3;
#pragma unroll
        for (int aidx = 0; aidx < 4; ++aidx) {
            int row = mt * 16 + (aidx & 1) * 8 + gg;
            int col = ks * 8 + (aidx >> 1) * 4 + tt;
            int u = ubase + row;
            r[k * 4 + aidx] = (u < RR) ? rc[(size_t)u * 256 + col] : 0u;
        }
    }
}

__device__ __forceinline__ void sts_A(uint32_t* buf, const uint32_t* r,
                                      int wid, int lane) {
#pragma unroll
    for (int k = 0; k < 2; ++k) {
        int c = wid + (k << 4);
        *(uint4*)&buf[(c * 32 + lane) * 4] =
            make_uint4(r[k * 4], r[k * 4 + 1], r[k * 4 + 2], r[k * 4 + 3]);
    }
}

__device__ __forceinline__ void ldg_B_v(uint32_t* r, const uint32_t* src, int tid) {
#pragma unroll
    for (int k = 0; k < 8; ++k) {
        int idx = k * 512 + tid;
        int dh = idx >> 6, w = idx & 63;
        r[k] = src[(size_t)dh * 256 + w];
    }
}

__device__ __forceinline__ void sts_B(uint32_t* buf, const uint32_t* r, int tid) {
#pragma unroll
    for (int k = 0; k < 8; ++k) {
        int idx = k * 512 + tid;
        int dh = idx >> 6, w = idx & 63;
        buf[dh * 68 + w] = r[k];
    }
}

__global__ void __launch_bounds__(512, 1)
attn_fp16_kernel(const float* __restrict__ tau_ptr) {
    extern __shared__ uint32_t smw[];
    uint32_t* e_h = smw;                     // 18432
    uint32_t* bdt = e_h + 512 * EW;          // 20736
    uint32_t* Tf0 = bdt + 576 * EW;          // 4608
    uint32_t* Tf1 = Tf0 + TFW;               // 4608
    float* uks  = (float*)(Tf1 + TFW);       // 512
    float* vrs  = uks + 512;                 // 576
    float* red  = vrs + 576;                 // 1024
    float* rowm = red + 1024;                // 64
    float* rowl = rowm + 64;                 // 64
    uint32_t* Tf[2] = {Tf0, Tf1};
    __half* bdth = (__half*)bdt;

    const int bh = blockIdx.y, h = bh & 7, b = bh >> 3;
    const int i0 = blockIdx.x * 64;
    const int tid = threadIdx.x, lane = tid & 31, wid = tid >> 5;
    const int gi = lane >> 2, ti = lane & 3;
    const int wm = wid >> 2, wn = wid & 3;     // 4x4 warp grid (BD/AC)

    const uint32_t* kbase = (const uint32_t*)g_k + (size_t)bh * TT * 32;
    const uint32_t* vTbase = (const uint32_t*)g_vT + (size_t)bh * 64 * 256;
    const uint32_t* rc = (const uint32_t*)g_rpe + h * 32;
    const uint32_t* qg = (const uint32_t*)g_q + ((size_t)bh * TT + i0) * 32;

    uint32_t r[8];
    uint32_t qreg[2][4][2];                    // Q B-fragments, loop-invariant

    // ---- prefetch BD chunk 0; load Q fragments from gmem; uk/vr ----
    ldg_A_rpe(r, rc, i0, wid, gi, ti);
#pragma unroll
    for (int n = 0; n < 2; ++n) {
        int irow = (wn * 2 + n) * 8 + gi;
#pragma unroll
        for (int ks = 0; ks < 4; ++ks) {
            qreg[n][ks][0] = qg[irow * 32 + ks * 8 + ti];
            qreg[n][ks][1] = qg[irow * 32 + ks * 8 + 4 + ti];
        }
    }
    uks[tid] = g_uk[bh * 512 + tid];
    for (int s = tid; s < 576; s += 512) {
        int u = i0 + s;
        vrs[s] = (u < RR) ? g_vr[u * 8 + h] : 0.f;
    }
    sts_A(Tf[0], r, wid, lane);
    __syncthreads();

    // ---- Phase BD: 5 chunks -> bdt fp16 direct store ----
#pragma unroll
    for (int ch = 0; ch < 5; ++ch) {
        if (ch < 4) ldg_A_rpe(r, rc, i0 + (ch + 1) * CH, wid, gi, ti);
        else        ldg_A_k(r, kbase, wid, gi, ti);

        if (!(ch == 4 && wm >= 2)) {
            float c_[2][2][4] = {};
            const uint32_t* cur = Tf[ch & 1];
#pragma unroll
            for (int ks = 0; ks < 4; ++ks) {
                uint32_t a[2][4];
#pragma unroll
                for (int mt = 0; mt < 2; ++mt) {
                    int mtg = wm * 2 + mt;
                    uint4 av = *(const uint4*)&cur[((mtg * 4 + ks) * 32 + lane) * 4];
                    a[mt][0] = av.x; a[mt][1] = av.y; a[mt][2] = av.z; a[mt][3] = av.w;
                }
#pragma unroll
                for (int n = 0; n < 2; ++n) {
                    mma16(c_[0][n], a[0], qreg[n][ks]);
                    mma16(c_[1][n], a[1], qreg[n][ks]);
                }
            }
#pragma unroll
            for (int mt = 0; mt < 2; ++mt) {
                int u = ch * CH + wm * 32 + mt * 16 + gi;
#pragma unroll
                for (int n = 0; n < 2; ++n) {
                    int iw = wn * 8 + n * 4 + ti;
                    bdt[u * EW + iw]       = packh2(c_[mt][n][0], c_[mt][n][1]);
                    bdt[(u + 8) * EW + iw] = packh2(c_[mt][n][2], c_[mt][n][3]);
                }
            }
        }
        sts_A(Tf[(ch + 1) & 1], r, wid, lane);
        __syncthreads();
    }

    // ---- Phase AC: 4 chunks; epilogue folds bd+uk+vr+scale+mask+tau ----
    const float scale = 0.125f;
    const float tauf = expf(tau_ptr[0]);
#pragma unroll
    for (int jc = 0; jc < 4; ++jc) {
        if (jc < 3) ldg_A_k(r, kbase + (size_t)(jc + 1) * CH * 32, wid, gi, ti);
        else        ldg_B_v(r, vTbase, tid);

        float c_[2][2][4] = {};
        const uint32_t* cur = Tf[(jc ^ 1) & 1];
#pragma unroll
        for (int ks = 0; ks < 4; ++ks) {
            uint32_t a[2][4];
#pragma unroll
            for (int mt = 0; mt < 2; ++mt) {
                int mtg = wm * 2 + mt;
                uint4 av = *(const uint4*)&cur[((mtg * 4 + ks) * 32 + lane) * 4];
                a[mt][0] = av.x; a[mt][1] = av.y; a[mt][2] = av.z; a[mt][3] = av.w;
            }
#pragma unroll
            for (int n = 0; n < 2; ++n) {
                mma16(c_[0][n], a[0], qreg[n][ks]);
                mma16(c_[1][n], a[1], qreg[n][ks]);
            }
        }
#pragma unroll
        for (int mt = 0; mt < 2; ++mt) {
            int j = jc * CH + wm * 32 + mt * 16 + gi;
            float uk0 = uks[j], uk1 = uks[j + 8];
#pragma unroll
            for (int n = 0; n < 2; ++n) {
                int ii = wn * 16 + n * 8 + 2 * ti;
                int iw = wn * 8 + n * 4 + ti;
#pragma unroll
                for (int rr = 0; rr < 2; ++rr) {
                    int jj = j + rr * 8;
                    float ukv = rr ? uk1 : uk0;
                    int ur0 = ii - jj + 511;
                    int ur1 = ur0 + 1;
                    float bd0 = __half2float(bdth[ur0 * EH2 + ii]);
                    float bd1 = __half2float(bdth[ur1 * EH2 + ii + 1]);
                    float v0 = (c_[mt][n][rr * 2]     + bd0 + ukv + vrs[ur0]) * scale;
                    float v1 = (c_[mt][n][rr * 2 + 1] + bd1 + ukv + vrs[ur1]) * scale;
                    if (jj == i0 + ii)     v0 = -FLT_MAX;
                    if (jj == i0 + ii + 1) v1 = -FLT_MAX;
                    e_h[jj * EW + iw] = packh2(v0 * tauf, v1 * tauf);
                }
            }
        }
        if (jc < 3) sts_A(Tf[jc & 1], r, wid, lane);
        else        sts_B(Tf[1], r, tid);
        __syncthreads();
    }

    // ---- softmax (vectorized half2 over column pairs) ----
    {
        int cp = tid & 31, seg = tid >> 5;
        float m0 = -FLT_MAX, m1 = -FLT_MAX;
        for (int jj = 0; jj < 32; ++jj) {
            int j = seg * 32 + jj;
            __half2 hv = *(__half2*)&e_h[j * EW + cp];
            float2 f = __half22float2(hv);
            m0 = fmaxf(m0, f.x); m1 = fmaxf(m1, f.y);
        }
        red[seg * 64 + 2 * cp]     = m0;
        red[seg * 64 + 2 * cp + 1] = m1;
        __syncthreads();
        if (tid < 64) {
            float m = red[tid];
#pragma unroll
            for (int s = 1; s < 16; ++s) m = fmaxf(m, red[s * 64 + tid]);
            rowm[tid] = m;
        }
        __syncthreads();
        m0 = rowm[2 * cp]; m1 = rowm[2 * cp + 1];
        float s0 = 0.f, s1 = 0.f;
        for (int jj = 0; jj < 32; ++jj) {
            int j = seg * 32 + jj;
            __half2 hv = *(__half2*)&e_h[j * EW + cp];
            float2 f = __half22float2(hv);
            float p0 = __expf(f.x - m0), p1 = __expf(f.y - m1);
            e_h[j * EW + cp] = packh2(p0, p1);
            s0 += p0; s1 += p1;
        }
        red[seg * 64 + 2 * cp]     = s0;
        red[seg * 64 + 2 * cp + 1] = s1;
        __syncthreads();
        if (tid < 64) {
            float s = 0.f;
#pragma unroll
            for (int ss = 0; ss < 16; ++ss) s += red[ss * 64 + tid];
            rowl[tid] = s;
        }
        __syncthreads();
    }

    // ---- Phase PV: A = P via ldmatrix.x4.trans, B = V staged ----
    float o_[2][4] = {};
    const int pwm = wid >> 2;
    const int pwn = wid & 3;
    const uint32_t ehb = smem_u32(e_h);
    const int grp = lane >> 3, lr = lane & 7;
    const int rsel = (grp & 2) ? 8 : 0;
    const int csel = (grp & 1) ? 8 : 0;
    const int i0w = pwm * 16 + csel;
#pragma unroll
    for (int jc = 0; jc < 4; ++jc) {
        if (jc < 3) ldg_B_v(r, vTbase + (size_t)(jc + 1) * 64, tid);

        const uint32_t* cur = Tf[(jc ^ 1) & 1];
#pragma unroll
        for (int ks = 0; ks < 8; ++ks) {
            int jb = jc * CH + ks * 16;
            uint32_t addr = ehb + (uint32_t)(((jb + rsel + lr) * EH2 + i0w) * 2);
            uint32_t a[4];
            asm volatile(
                "ldmatrix.sync.aligned.m8n8.x4.trans.shared.b16 {%0,%1,%2,%3}, [%4];"
                : "=r"(a[0]), "=r"(a[1]), "=r"(a[2]), "=r"(a[3]) : "r"(addr));
#pragma unroll
            for (int n = 0; n < 2; ++n) {
                int ncol = pwn * 16 + n * 8 + gi;
                uint32_t bb[2];
                bb[0] = cur[ncol * 68 + ks * 8 + ti];
                bb[1] = cur[ncol * 68 + ks * 8 + ti + 4];
                mma16(o_[n], a, bb);
            }
        }
        if (jc < 3) sts_B(Tf[jc & 1], r, tid);
        __syncthreads();
    }

    // ---- epilogue ----
    {
        int i1 = pwm * 16 + gi, i2 = i1 + 8;
        float inv1 = 1.f / rowl[i1];
        float inv2 = 1.f / rowl[i2];
#pragma unroll
        for (int n = 0; n < 2; ++n) {
            int dh = pwn * 16 + n * 8 + 2 * ti;
            size_t o1 = ((size_t)(i0 + i1) * 8 + b) * 512 + h * 64 + dh;
            size_t o2 = ((size_t)(i0 + i2) * 8 + b) * 512 + h * 64 + dh;
            *(uint32_t*)&g_aoh[o1] = packh2(o_[n][0] * inv1, o_[n][1] * inv1);
            *(uint32_t*)&g_aoh[o2] = packh2(o_[n][2] * inv2, o_[n][3] * inv2);
        }
    }
}

// ============================================================================
// Output projection (unchanged)
// ============================================================================
__global__ void __launch_bounds__(256, 3)
out_fp16_kernel(const float* __restrict__ bias, float* __restrict__ out) {
    __shared__ uint32_t As[128 * 36];
    __shared__ uint32_t Bs[64 * 36];
    const int bid = blockIdx.x, tid = threadIdx.x;
    const int m0 = (bid / 8) * 128, n0 = (bid % 8) * 64;
    const int lane = tid & 31, wid = tid >> 5;
    const int gi = lane >> 2, ti = lane & 3;
    const int wm = wid >> 1, wn = wid & 1;

    const uint32_t* aw = (const uint32_t*)g_aoh;
    const uint32_t* bw = (const uint32_t*)g_woh;

    float c_[2][4][4] = {};

    for (int k0 = 0; k0 < 8; ++k0) {
#pragma unroll
        for (int rep = 0; rep < 4; ++rep) {
            int s = rep * 256 + tid;
            int row = s >> 3, seg = s & 7;
            *(uint4*)&As[row * 36 + seg * 4] =
                *(const uint4*)&aw[(size_t)(m0 + row) * 256 + k0 * 32 + seg * 4];
        }
#pragma unroll
        for (int rep = 0; rep < 2; ++rep) {
            int s = rep * 256 + tid;
            int row = s >> 3, seg = s & 7;
            *(uint4*)&Bs[row * 36 + seg * 4] =
                *(const uint4*)&bw[(size_t)(n0 + row) * 256 + k0 * 32 + seg * 4];
        }
        __syncthreads();
#pragma unroll
        for (int kb = 0; kb < 4; ++kb) {
            uint32_t a[2][4], bb[4][2];
#pragma unroll
            for (int mt = 0; mt < 2; ++mt) {
                int r = wm * 32 + mt * 16 + gi;
                a[mt][0] = As[r * 36 + kb * 8 + ti];
                a[mt][1] = As[(r + 8) * 36 + kb * 8 + ti];
                a[mt][2] = As[r * 36 + kb * 8 + ti + 4];
                a[mt][3] = As[(r + 8) * 36 + kb * 8 + ti + 4];
            }
#pragma unroll
            for (int nt = 0; nt < 4; ++nt) {
                int ncol = wn * 32 + nt * 8 + gi;
                bb[nt][0] = Bs[ncol * 36 + kb * 8 + ti];
                bb[nt][1] = Bs[ncol * 36 + kb * 8 + ti + 4];
            }
#pragma unroll
            for (int mt = 0; mt < 2; ++mt)
#pragma unroll
                for (int nt = 0; nt < 4; ++nt)
                    mma16(c_[mt][nt], a[mt], bb[nt]);
        }
        __syncthreads();
    }

#pragma unroll
    for (int mt = 0; mt < 2; ++mt) {
        int m = m0 + wm * 32 + mt * 16 + gi;
#pragma unroll
        for (int nt = 0; nt < 4; ++nt) {
            int n = n0 + wn * 32 + nt * 8 + 2 * ti;
            float b0 = bias[n], b1 = bias[n + 1];
            *(float2*)&out[(size_t)m * 512 + n] =
                make_float2(c_[mt][nt][0] + b0, c_[mt][nt][1] + b1);
            *(float2*)&out[(size_t)(m + 8) * 512 + n] =
                make_float2(c_[mt][nt][2] + b0, c_[mt][nt][3] + b1);
        }
    }
}

// ============================================================================
extern "C" void kernel_launch(void* const* d_in, const int* in_sizes, int n_in,
                              void* d_out, int out_size) {
    const float* x     = (const float*)d_in[0];
    const float* Wqkv  = (const float*)d_in[1];
    const float* Wpos  = (const float*)d_in[2];
    const float* pos_u = (const float*)d_in[3];
    const float* pos_v = (const float*)d_in[4];
    const float* Wout  = (const float*)d_in[5];
    const float* bout  = (const float*)d_in[6];
    const float* ltau  = (const float*)d_in[7];
    float* out = (float*)d_out;

    prep_kernel<<<3328, 256>>>(x, Wqkv, Wpos, Wout);
    gemm_fused_kernel<<<832, 256>>>();
    bias_kernel<<<640, 256>>>(pos_u, pos_v);

    const size_t smem = (size_t)(512 * EW + 576 * EW + 2 * TFW
                                 + 512 + 576 + 1024 + 64 + 64) * sizeof(uint32_t);
    cudaFuncSetAttribute(attn_fp16_kernel, cudaFuncAttributeMaxDynamicSharedMemorySize, (int)smem);
    attn_fp16_kernel<<<dim3(8, 64), 512, smem>>>(ltau);

    out_fp16_kernel<<<256, 256>>>(bout, out);
}

// round 13
// speedup vs baseline: 1.6701x; 1.0131x over previous
#include <cuda_runtime.h>
#include <cuda_fp16.h>
#include <math.h>
#include <float.h>
#include <stdint.h>

#define TT   512
#define BB   8
#define DD   512
#define HH   8
#define DHH  64
#define RR   1023
#define BHN  64
#define MROWS 4096

// ---------------- scratch (fp16 payloads) ----------------
__device__ __half g_q[BHN * TT * DHH];      // [b*8+h][t][dh]
__device__ __half g_k[BHN * TT * DHH];
__device__ __half g_vT[BHN * DHH * TT];     // [b*8+h][dh][t]
__device__ __half g_rpe[RR * DD];           // [r][h*64+dh]
__device__ __half g_xh[MROWS * DD];
__device__ __half g_wqh[1536 * 512];        // W_qkv^T [n][k]
__device__ __half g_wph[512 * 512];         // W_pos^T [n][k]
__device__ __half g_woh[512 * 512];         // W_out^T [n][k]
__device__ __half g_aoh[MROWS * DD];        // attention out (t,b,d), half
__device__ float  g_uk[BHN * TT];
__device__ float  g_vr[RR * HH];

__device__ __forceinline__ void mma16(float* c, const uint32_t* a, const uint32_t* b) {
    asm volatile(
        "mma.sync.aligned.m16n8k16.row.col.f32.f16.f16.f32 "
        "{%0,%1,%2,%3},{%4,%5,%6,%7},{%8,%9},{%0,%1,%2,%3};"
        : "+f"(c[0]), "+f"(c[1]), "+f"(c[2]), "+f"(c[3])
        : "r"(a[0]), "r"(a[1]), "r"(a[2]), "r"(a[3]), "r"(b[0]), "r"(b[1]));
}

__device__ __forceinline__ uint32_t packh2(float lo, float hi) {
    __half2 h = __floats2half2_rn(lo, hi);
    return *(uint32_t*)&h;
}

__device__ __forceinline__ uint32_t smem_u32(const void* p) {
    uint32_t a;
    asm("{ .reg .u64 t; cvta.to.shared.u64 t, %1; cvt.u32.u64 %0, t; }" : "=r"(a) : "l"(p));
    return a;
}

__device__ __forceinline__ void ldm_x4(uint32_t* d, uint32_t addr) {
    asm volatile(
        "ldmatrix.sync.aligned.m8n8.x4.shared.b16 {%0,%1,%2,%3}, [%4];"
        : "=r"(d[0]), "=r"(d[1]), "=r"(d[2]), "=r"(d[3]) : "r"(addr));
}

// ============================================================================
// PREP (fused)
// ============================================================================
__global__ void __launch_bounds__(256)
prep_kernel(const float* __restrict__ x, const float* __restrict__ Wqkv,
            const float* __restrict__ Wpos, const float* __restrict__ Wout) {
    __shared__ float t[32][33];
    int bid = blockIdx.x, tid = threadIdx.x;

    if (bid < 2048) {
        int i = bid * 256 + tid;
        float4 v = *(const float4*)&x[(size_t)i * 4];
        *(uint32_t*)&g_xh[(size_t)i * 4]     = packh2(v.x, v.y);
        *(uint32_t*)&g_xh[(size_t)i * 4 + 2] = packh2(v.z, v.w);
        return;
    }

    const float* src; __half* dst; int N, bx, by;
    if (bid < 2816)      { int b = bid - 2048; src = Wqkv; dst = g_wqh; N = 1536; bx = b % 48, by = b / 48; }
    else if (bid < 3072) { int b = bid - 2816; src = Wpos; dst = g_wph; N = 512;  bx = b % 16, by = b / 16; }
    else                 { int b = bid - 3072; src = Wout; dst = g_woh; N = 512;  bx = b % 16, by = b / 16; }

    int n0 = bx * 32, k0 = by * 32;
    int tx = tid & 31, ty = tid >> 5;
    for (int r = ty; r < 32; r += 8)
        t[r][tx] = src[(size_t)(k0 + r) * N + n0 + tx];
    __syncthreads();
    for (int r = ty; r < 32; r += 8)
        dst[(size_t)(n0 + r) * 512 + k0 + tx] = __float2half(t[tx][r]);
}

// ============================================================================
// FUSED GEMM: QKV + rpe. 128x64 tile, occ 3. ldmatrix fragment loads.
// ============================================================================
__global__ void __launch_bounds__(256, 3)
gemm_fused_kernel() {
    __shared__ uint32_t As[128 * 36];
    __shared__ uint32_t Bs[64 * 36];
    __shared__ float freqs[512];
    const int bid = blockIdx.x, tid = threadIdx.x;
    const int lane = tid & 31, wid = tid >> 5;
    const int wm = wid >> 1, wn = wid & 1;
    const int gi = lane >> 2, ti = lane & 3;

    // ldmatrix lane decomposition
    const int lr = lane & 7;
    const int arow = lr + ((lane >> 3) & 1) * 8;   // A: rows lo/hi by bit3
    const int acol = (lane >> 4) * 4;              // A: k lo/hi by bit4
    const int brow = lr + ((lane >> 4) & 1) * 8;   // B: n lo/hi by bit4
    const int bcol = ((lane >> 3) & 1) * 4;        // B: k lo/hi by bit3

    const uint32_t asb = smem_u32(As);
    const uint32_t bsb = smem_u32(Bs);

    const bool is_rpe = (bid >= 768);
    int m0, n0;
    const uint32_t *aw = 0, *bw;
    if (!is_rpe) {
        m0 = (bid / 24) * 128; n0 = (bid % 24) * 64;
        aw = (const uint32_t*)g_xh; bw = (const uint32_t*)g_wqh;
    } else {
        int b = bid - 768;
        m0 = (b / 8) * 128; n0 = (b % 8) * 64;
        bw = (const uint32_t*)g_wph;
        for (int s = tid; s < 512; s += 256) {
            int cc = s & 255;
            freqs[s] = __expf(-9.210340371976184f * (float)cc * (1.0f / 256.0f));
        }
        __syncthreads();
    }

    float c_[2][4][4] = {};

    for (int k0 = 0; k0 < 8; ++k0) {
        if (!is_rpe) {
#pragma unroll
            for (int rep = 0; rep < 4; ++rep) {
                int s = rep * 256 + tid;
                int row = s >> 3, seg = s & 7;
                *(uint4*)&As[row * 36 + seg * 4] =
                    *(const uint4*)&aw[(size_t)(m0 + row) * 256 + k0 * 32 + seg * 4];
            }
        } else {
#pragma unroll
            for (int rep = 0; rep < 16; ++rep) {
                int s = rep * 256 + tid;
                int row = s >> 5, w = s & 31;
                int kg = k0 * 64 + 2 * w;
                float rel = (float)(m0 + row - 511);
                float a0 = rel * freqs[kg], a1 = rel * freqs[kg + 1];
                float f0 = (kg < 256) ? sinf(a0) : cosf(a0);
                float f1 = (kg + 1 < 256) ? sinf(a1) : cosf(a1);
                As[row * 36 + w] = packh2(f0, f1);
            }
        }
#pragma unroll
        for (int rep = 0; rep < 2; ++rep) {
            int s = rep * 256 + tid;
            int row = s >> 3, seg = s & 7;
            *(uint4*)&Bs[row * 36 + seg * 4] =
                *(const uint4*)&bw[(size_t)(n0 + row) * 256 + k0 * 32 + seg * 4];
        }
        __syncthreads();
#pragma unroll
        for (int kb = 0; kb < 4; ++kb) {
            uint32_t a[2][4], bq[2][4];
#pragma unroll
            for (int mt = 0; mt < 2; ++mt)
                ldm_x4(a[mt], asb + (uint32_t)(((wm * 32 + mt * 16 + arow) * 36
                                                + kb * 8 + acol) * 4));
#pragma unroll
            for (int p = 0; p < 2; ++p)
                ldm_x4(bq[p], bsb + (uint32_t)(((wn * 32 + p * 16 + brow) * 36
                                                + kb * 8 + bcol) * 4));
#pragma unroll
            for (int mt = 0; mt < 2; ++mt)
#pragma unroll
                for (int p = 0; p < 2; ++p) {
                    mma16(c_[mt][p * 2],     a[mt], &bq[p][0]);
                    mma16(c_[mt][p * 2 + 1], a[mt], &bq[p][2]);
                }
        }
        __syncthreads();
    }

    if (!is_rpe) {
#pragma unroll
        for (int mt = 0; mt < 2; ++mt) {
            int m = m0 + wm * 32 + mt * 16 + gi;
#pragma unroll
            for (int nt = 0; nt < 4; ++nt) {
                int n = n0 + wn * 32 + nt * 8 + 2 * ti;
                int part = n >> 9, hh = (n >> 6) & 7, dh = n & 63;
#pragma unroll
                for (int half = 0; half < 2; ++half) {
                    int mm = m + half * 8;
                    float v0 = c_[mt][nt][half * 2], v1 = c_[mt][nt][half * 2 + 1];
                    int tr = mm >> 3, bi = mm & 7;
                    int bh = bi * 8 + hh;
                    if (part == 2) {
                        g_vT[((size_t)bh * 64 + dh) * 512 + tr]     = __float2half(v0);
                        g_vT[((size_t)bh * 64 + dh + 1) * 512 + tr] = __float2half(v1);
                    } else {
                        __half* dst = (part == 0) ? g_q : g_k;
                        *(uint32_t*)&dst[((size_t)bh * 512 + tr) * 64 + dh] = packh2(v0, v1);
                    }
                }
            }
        }
    } else {
#pragma unroll
        for (int mt = 0; mt < 2; ++mt) {
            int m = m0 + wm * 32 + mt * 16 + gi;
#pragma unroll
            for (int nt = 0; nt < 4; ++nt) {
                int n = n0 + wn * 32 + nt * 8 + 2 * ti;
                if (m < RR)
                    *(uint32_t*)&g_rpe[(size_t)m * 512 + n] = packh2(c_[mt][nt][0], c_[mt][nt][1]);
                if (m + 8 < RR)
                    *(uint32_t*)&g_rpe[(size_t)(m + 8) * 512 + n] = packh2(c_[mt][nt][2], c_[mt][nt][3]);
            }
        }
    }
}

// ============================================================================
// BIAS (fused)
// ============================================================================
__global__ void __launch_bounds__(256)
bias_kernel(const float* __restrict__ pos_u, const float* __restrict__ pos_v) {
    int bid = blockIdx.x, tid = threadIdx.x;
    if (bid < 512) {
        int gid = bid * 256 + tid;
        int id = gid >> 2, part = gid & 3;
        int h = (id >> 9) & 7;
        const __half2* kp = (const __half2*)(g_k + (size_t)id * 64) + part * 8;
        const float* up = pos_u + h * 64 + part * 16;
        float acc = 0.f;
#pragma unroll
        for (int s = 0; s < 8; ++s) {
            float2 kf = __half22float2(kp[s]);
            acc += kf.x * up[2 * s] + kf.y * up[2 * s + 1];
        }
        acc += __shfl_xor_sync(0xffffffffu, acc, 1);
        acc += __shfl_xor_sync(0xffffffffu, acc, 2);
        if (part == 0) g_uk[id] = acc;
    } else {
        int gid = (bid - 512) * 256 + tid;
        int id = gid >> 2, part = gid & 3;
        if (id >= RR * HH) return;
        int r = id >> 3, h = id & 7;
        const __half2* rp = (const __half2*)(g_rpe + (size_t)r * 512 + h * 64) + part * 8;
        const float* vp = pos_v + h * 64 + part * 16;
        float acc = 0.f;
#pragma unroll
        for (int s = 0; s < 8; ++s) {
            float2 rf = __half22float2(rp[s]);
            acc += rf.x * vp[2 * s] + rf.y * vp[2 * s + 1];
        }
        acc += __shfl_xor_sync(0xffffffffu, acc, 1);
        acc += __shfl_xor_sync(0xffffffffu, acc, 2);
        if (part == 0) g_vr[id] = acc;
    }
}

// ============================================================================
// Fused attention (as R12) + ldmatrix for PV B fragments.
// ============================================================================
#define EW  36
#define EH2 72
#define CH  128
#define TFW 4608

__device__ __forceinline__ void ldg_A_k(uint32_t* r, const uint32_t* src,
                                        int wid, int gg, int tt) {
#pragma unroll
    for (int k = 0; k < 2; ++k) {
        int c = wid + (k << 4);
        int mt = c >> 2, ks = c & 3;
#pragma unroll
        for (int aidx = 0; aidx < 4; ++aidx) {
            int row = mt * 16 + (aidx & 1) * 8 + gg;
            int col = ks * 8 + (aidx >> 1) * 4 + tt;
            r[k * 4 + aidx] = src[(size_t)row * 32 + col];
        }
    }
}

__device__ __forceinline__ void ldg_A_rpe(uint32_t* r, const uint32_t* rc,
                                          int ubase, int wid, int gg, int tt) {
#pragma unroll
    for (int k = 0; k < 2; ++k) {
        int c = wid + (k << 4);
        int mt = c >> 2, ks = c & 3;
#pragma unroll
        for (int aidx = 0; aidx < 4; ++aidx) {
            int row = mt * 16 + (aidx & 1) * 8 + gg;
            int col = ks * 8 + (aidx >> 1) * 4 + tt;
            int u = ubase + row;
            r[k * 4 + aidx] = (u < RR) ? rc[(size_t)u * 256 + col] : 0u;
        }
    }
}

__device__ __forceinline__ void sts_A(uint32_t* buf, const uint32_t* r,
                                      int wid, int lane) {
#pragma unroll
    for (int k = 0; k < 2; ++k) {
        int c = wid + (k << 4);
        *(uint4*)&buf[(c * 32 + lane) * 4] =
            make_uint4(r[k * 4], r[k * 4 + 1], r[k * 4 + 2], r[k * 4 + 3]);
    }
}

__device__ __forceinline__ void ldg_B_v(uint32_t* r, const uint32_t* src, int tid) {
#pragma unroll
    for (int k = 0; k < 8; ++k) {
        int idx = k * 512 + tid;
        int dh = idx >> 6, w = idx & 63;
        r[k] = src[(size_t)dh * 256 + w];
    }
}

__device__ __forceinline__ void sts_B(uint32_t* buf, const uint32_t* r, int tid) {
#pragma unroll
    for (int k = 0; k < 8; ++k) {
        int idx = k * 512 + tid;
        int dh = idx >> 6, w = idx & 63;
        buf[dh * 68 + w] = r[k];
    }
}

__global__ void __launch_bounds__(512, 1)
attn_fp16_kernel(const float* __restrict__ tau_ptr) {
    extern __shared__ uint32_t smw[];
    uint32_t* e_h = smw;                     // 18432
    uint32_t* bdt = e_h + 512 * EW;          // 20736
    uint32_t* Tf0 = bdt + 576 * EW;          // 4608
    uint32_t* Tf1 = Tf0 + TFW;               // 4608
    float* uks  = (float*)(Tf1 + TFW);       // 512
    float* vrs  = uks + 512;                 // 576
    float* red  = vrs + 576;                 // 1024
    float* rowm = red + 1024;                // 64
    float* rowl = rowm + 64;                 // 64
    uint32_t* Tf[2] = {Tf0, Tf1};
    __half* bdth = (__half*)bdt;

    const int bh = blockIdx.y, h = bh & 7, b = bh >> 3;
    const int i0 = blockIdx.x * 64;
    const int tid = threadIdx.x, lane = tid & 31, wid = tid >> 5;
    const int gi = lane >> 2, ti = lane & 3;
    const int wm = wid >> 2, wn = wid & 3;     // 4x4 warp grid (BD/AC)

    const uint32_t* kbase = (const uint32_t*)g_k + (size_t)bh * TT * 32;
    const uint32_t* vTbase = (const uint32_t*)g_vT + (size_t)bh * 64 * 256;
    const uint32_t* rc = (const uint32_t*)g_rpe + h * 32;
    const uint32_t* qg = (const uint32_t*)g_q + ((size_t)bh * TT + i0) * 32;

    uint32_t r[8];
    uint32_t qreg[2][4][2];                    // Q B-fragments, loop-invariant

    // ---- prefetch BD chunk 0; load Q fragments from gmem; uk/vr ----
    ldg_A_rpe(r, rc, i0, wid, gi, ti);
#pragma unroll
    for (int n = 0; n < 2; ++n) {
        int irow = (wn * 2 + n) * 8 + gi;
#pragma unroll
        for (int ks = 0; ks < 4; ++ks) {
            qreg[n][ks][0] = qg[irow * 32 + ks * 8 + ti];
            qreg[n][ks][1] = qg[irow * 32 + ks * 8 + 4 + ti];
        }
    }
    uks[tid] = g_uk[bh * 512 + tid];
    for (int s = tid; s < 576; s += 512) {
        int u = i0 + s;
        vrs[s] = (u < RR) ? g_vr[u * 8 + h] : 0.f;
    }
    sts_A(Tf[0], r, wid, lane);
    __syncthreads();

    // ---- Phase BD: 5 chunks -> bdt fp16 direct store ----
#pragma unroll
    for (int ch = 0; ch < 5; ++ch) {
        if (ch < 4) ldg_A_rpe(r, rc, i0 + (ch + 1) * CH, wid, gi, ti);
        else        ldg_A_k(r, kbase, wid, gi, ti);

        if (!(ch == 4 && wm >= 2)) {
            float c_[2][2][4] = {};
            const uint32_t* cur = Tf[ch & 1];
#pragma unroll
            for (int ks = 0; ks < 4; ++ks) {
                uint32_t a[2][4];
#pragma unroll
                for (int mt = 0; mt < 2; ++mt) {
                    int mtg = wm * 2 + mt;
                    uint4 av = *(const uint4*)&cur[((mtg * 4 + ks) * 32 + lane) * 4];
                    a[mt][0] = av.x; a[mt][1] = av.y; a[mt][2] = av.z; a[mt][3] = av.w;
                }
#pragma unroll
                for (int n = 0; n < 2; ++n) {
                    mma16(c_[0][n], a[0], qreg[n][ks]);
                    mma16(c_[1][n], a[1], qreg[n][ks]);
                }
            }
#pragma unroll
            for (int mt = 0; mt < 2; ++mt) {
                int u = ch * CH + wm * 32 + mt * 16 + gi;
#pragma unroll
                for (int n = 0; n < 2; ++n) {
                    int iw = wn * 8 + n * 4 + ti;
                    bdt[u * EW + iw]       = packh2(c_[mt][n][0], c_[mt][n][1]);
                    bdt[(u + 8) * EW + iw] = packh2(c_[mt][n][2], c_[mt][n][3]);
                }
            }
        }
        sts_A(Tf[(ch + 1) & 1], r, wid, lane);
        __syncthreads();
    }

    // ---- Phase AC: 4 chunks; epilogue folds bd+uk+vr+scale+mask+tau ----
    const float scale = 0.125f;
    const float tauf = expf(tau_ptr[0]);
#pragma unroll
    for (int jc = 0; jc < 4; ++jc) {
        if (jc < 3) ldg_A_k(r, kbase + (size_t)(jc + 1) * CH * 32, wid, gi, ti);
        else        ldg_B_v(r, vTbase, tid);

        float c_[2][2][4] = {};
        const uint32_t* cur = Tf[(jc ^ 1) & 1];
#pragma unroll
        for (int ks = 0; ks < 4; ++ks) {
            uint32_t a[2][4];
#pragma unroll
            for (int mt = 0; mt < 2; ++mt) {
                int mtg = wm * 2 + mt;
                uint4 av = *(const uint4*)&cur[((mtg * 4 + ks) * 32 + lane) * 4];
                a[mt][0] = av.x; a[mt][1] = av.y; a[mt][2] = av.z; a[mt][3] = av.w;
            }
#pragma unroll
            for (int n = 0; n < 2; ++n) {
                mma16(c_[0][n], a[0], qreg[n][ks]);
                mma16(c_[1][n], a[1], qreg[n][ks]);
            }
        }
#pragma unroll
        for (int mt = 0; mt < 2; ++mt) {
            int j = jc * CH + wm * 32 + mt * 16 + gi;
            float uk0 = uks[j], uk1 = uks[j + 8];
#pragma unroll
            for (int n = 0; n < 2; ++n) {
                int ii = wn * 16 + n * 8 + 2 * ti;
                int iw = wn * 8 + n * 4 + ti;
#pragma unroll
                for (int rr = 0; rr < 2; ++rr) {
                    int jj = j + rr * 8;
                    float ukv = rr ? uk1 : uk0;
                    int ur0 = ii - jj + 511;
                    int ur1 = ur0 + 1;
                    float bd0 = __half2float(bdth[ur0 * EH2 + ii]);
                    float bd1 = __half2float(bdth[ur1 * EH2 + ii + 1]);
                    float v0 = (c_[mt][n][rr * 2]     + bd0 + ukv + vrs[ur0]) * scale;
                    float v1 = (c_[mt][n][rr * 2 + 1] + bd1 + ukv + vrs[ur1]) * scale;
                    if (jj == i0 + ii)     v0 = -FLT_MAX;
                    if (jj == i0 + ii + 1) v1 = -FLT_MAX;
                    e_h[jj * EW + iw] = packh2(v0 * tauf, v1 * tauf);
                }
            }
        }
        if (jc < 3) sts_A(Tf[jc & 1], r, wid, lane);
        else        sts_B(Tf[1], r, tid);
        __syncthreads();
    }

    // ---- softmax (vectorized half2 over column pairs) ----
    {
        int cp = tid & 31, seg = tid >> 5;
        float m0 = -FLT_MAX, m1 = -FLT_MAX;
        for (int jj = 0; jj < 32; ++jj) {
            int j = seg * 32 + jj;
            __half2 hv = *(__half2*)&e_h[j * EW + cp];
            float2 f = __half22float2(hv);
            m0 = fmaxf(m0, f.x); m1 = fmaxf(m1, f.y);
        }
        red[seg * 64 + 2 * cp]     = m0;
        red[seg * 64 + 2 * cp + 1] = m1;
        __syncthreads();
        if (tid < 64) {
            float m = red[tid];
#pragma unroll
            for (int s = 1; s < 16; ++s) m = fmaxf(m, red[s * 64 + tid]);
            rowm[tid] = m;
        }
        __syncthreads();
        m0 = rowm[2 * cp]; m1 = rowm[2 * cp + 1];
        float s0 = 0.f, s1 = 0.f;
        for (int jj = 0; jj < 32; ++jj) {
            int j = seg * 32 + jj;
            __half2 hv = *(__half2*)&e_h[j * EW + cp];
            float2 f = __half22float2(hv);
            float p0 = __expf(f.x - m0), p1 = __expf(f.y - m1);
            e_h[j * EW + cp] = packh2(p0, p1);
            s0 += p0; s1 += p1;
        }
        red[seg * 64 + 2 * cp]     = s0;
        red[seg * 64 + 2 * cp + 1] = s1;
        __syncthreads();
        if (tid < 64) {
            float s = 0.f;
#pragma unroll
            for (int ss = 0; ss < 16; ++ss) s += red[ss * 64 + tid];
            rowl[tid] = s;
        }
        __syncthreads();
    }

    // ---- Phase PV: A = P via ldmatrix.x4.trans, B = V via ldmatrix.x4 ----
    float o_[2][4] = {};
    const int pwm = wid >> 2;
    const int pwn = wid & 3;
    const uint32_t ehb = smem_u32(e_h);
    const int grp = lane >> 3, lr = lane & 7;
    const int rsel = (grp & 2) ? 8 : 0;
    const int csel = (grp & 1) ? 8 : 0;
    const int i0w = pwm * 16 + csel;
    // B (V) ldmatrix lane mapping: n lo/hi by bit4, k lo/hi by bit3
    const int vbrow = lr + ((lane >> 4) & 1) * 8;
    const int vbcol = ((lane >> 3) & 1) * 4;
#pragma unroll
    for (int jc = 0; jc < 4; ++jc) {
        if (jc < 3) ldg_B_v(r, vTbase + (size_t)(jc + 1) * 64, tid);

        const uint32_t* cur = Tf[(jc ^ 1) & 1];
        const uint32_t curb = smem_u32(cur);
#pragma unroll
        for (int ks = 0; ks < 8; ++ks) {
            int jb = jc * CH + ks * 16;
            uint32_t addr = ehb + (uint32_t)(((jb + rsel + lr) * EH2 + i0w) * 2);
            uint32_t a[4];
            asm volatile(
                "ldmatrix.sync.aligned.m8n8.x4.trans.shared.b16 {%0,%1,%2,%3}, [%4];"
                : "=r"(a[0]), "=r"(a[1]), "=r"(a[2]), "=r"(a[3]) : "r"(addr));
            uint32_t bq[4];
            ldm_x4(bq, curb + (uint32_t)(((pwn * 16 + vbrow) * 68 + ks * 8 + vbcol) * 4));
            mma16(o_[0], a, &bq[0]);
            mma16(o_[1], a, &bq[2]);
        }
        if (jc < 3) sts_B(Tf[jc & 1], r, tid);
        __syncthreads();
    }

    // ---- epilogue ----
    {
        int i1 = pwm * 16 + gi, i2 = i1 + 8;
        float inv1 = 1.f / rowl[i1];
        float inv2 = 1.f / rowl[i2];
#pragma unroll
        for (int n = 0; n < 2; ++n) {
            int dh = pwn * 16 + n * 8 + 2 * ti;
            size_t o1 = ((size_t)(i0 + i1) * 8 + b) * 512 + h * 64 + dh;
            size_t o2 = ((size_t)(i0 + i2) * 8 + b) * 512 + h * 64 + dh;
            *(uint32_t*)&g_aoh[o1] = packh2(o_[n][0] * inv1, o_[n][1] * inv1);
            *(uint32_t*)&g_aoh[o2] = packh2(o_[n][2] * inv2, o_[n][3] * inv2);
        }
    }
}

// ============================================================================
// Output projection: ldmatrix fragment loads.
// ============================================================================
__global__ void __launch_bounds__(256, 3)
out_fp16_kernel(const float* __restrict__ bias, float* __restrict__ out) {
    __shared__ uint32_t As[128 * 36];
    __shared__ uint32_t Bs[64 * 36];
    const int bid = blockIdx.x, tid = threadIdx.x;
    const int m0 = (bid / 8) * 128, n0 = (bid % 8) * 64;
    const int lane = tid & 31, wid = tid >> 5;
    const int gi = lane >> 2, ti = lane & 3;
    const int wm = wid >> 1, wn = wid & 1;

    const int lr = lane & 7;
    const int arow = lr + ((lane >> 3) & 1) * 8;
    const int acol = (lane >> 4) * 4;
    const int brow = lr + ((lane >> 4) & 1) * 8;
    const int bcol = ((lane >> 3) & 1) * 4;
    const uint32_t asb = smem_u32(As);
    const uint32_t bsb = smem_u32(Bs);

    const uint32_t* aw = (const uint32_t*)g_aoh;
    const uint32_t* bw = (const uint32_t*)g_woh;

    float c_[2][4][4] = {};

    for (int k0 = 0; k0 < 8; ++k0) {
#pragma unroll
        for (int rep = 0; rep < 4; ++rep) {
            int s = rep * 256 + tid;
            int row = s >> 3, seg = s & 7;
            *(uint4*)&As[row * 36 + seg * 4] =
                *(const uint4*)&aw[(size_t)(m0 + row) * 256 + k0 * 32 + seg * 4];
        }
#pragma unroll
        for (int rep = 0; rep < 2; ++rep) {
            int s = rep * 256 + tid;
            int row = s >> 3, seg = s & 7;
            *(uint4*)&Bs[row * 36 + seg * 4] =
                *(const uint4*)&bw[(size_t)(n0 + row) * 256 + k0 * 32 + seg * 4];
        }
        __syncthreads();
#pragma unroll
        for (int kb = 0; kb < 4; ++kb) {
            uint32_t a[2][4], bq[2][4];
#pragma unroll
            for (int mt = 0; mt < 2; ++mt)
                ldm_x4(a[mt], asb + (uint32_t)(((wm * 32 + mt * 16 + arow) * 36
                                                + kb * 8 + acol) * 4));
#pragma unroll
            for (int p = 0; p < 2; ++p)
                ldm_x4(bq[p], bsb + (uint32_t)(((wn * 32 + p * 16 + brow) * 36
                                                + kb * 8 + bcol) * 4));
#pragma unroll
            for (int mt = 0; mt < 2; ++mt)
#pragma unroll
                for (int p = 0; p < 2; ++p) {
                    mma16(c_[mt][p * 2],     a[mt], &bq[p][0]);
                    mma16(c_[mt][p * 2 + 1], a[mt], &bq[p][2]);
                }
        }
        __syncthreads();
    }

#pragma unroll
    for (int mt = 0; mt < 2; ++mt) {
        int m = m0 + wm * 32 + mt * 16 + gi;
#pragma unroll
        for (int nt = 0; nt < 4; ++nt) {
            int n = n0 + wn * 32 + nt * 8 + 2 * ti;
            float b0 = bias[n], b1 = bias[n + 1];
            *(float2*)&out[(size_t)m * 512 + n] =
                make_float2(c_[mt][nt][0] + b0, c_[mt][nt][1] + b1);
            *(float2*)&out[(size_t)(m + 8) * 512 + n] =
                make_float2(c_[mt][nt][2] + b0, c_[mt][nt][3] + b1);
        }
    }
}

// ============================================================================
extern "C" void kernel_launch(void* const* d_in, const int* in_sizes, int n_in,
                              void* d_out, int out_size) {
    const float* x     = (const float*)d_in[0];
    const float* Wqkv  = (const float*)d_in[1];
    const float* Wpos  = (const float*)d_in[2];
    const float* pos_u = (const float*)d_in[3];
    const float* pos_v = (const float*)d_in[4];
    const float* Wout  = (const float*)d_in[5];
    const float* bout  = (const float*)d_in[6];
    const float* ltau  = (const float*)d_in[7];
    float* out = (float*)d_out;

    prep_kernel<<<3328, 256>>>(x, Wqkv, Wpos, Wout);
    gemm_fused_kernel<<<832, 256>>>();
    bias_kernel<<<640, 256>>>(pos_u, pos_v);

    const size_t smem = (size_t)(512 * EW + 576 * EW + 2 * TFW
                                 + 512 + 576 + 1024 + 64 + 64) * sizeof(uint32_t);
    cudaFuncSetAttribute(attn_fp16_kernel, cudaFuncAttributeMaxDynamicSharedMemorySize, (int)smem);
    attn_fp16_kernel<<<dim3(8, 64), 512, smem>>>(ltau);

    out_fp16_kernel<<<256, 256>>>(bout, out);
}